// round 4
// baseline (speedup 1.0000x reference)
#include <cuda_runtime.h>
#include <math.h>

#define NROWS  4096
#define EDIM   512
#define QKVLD  1536
#define SPLITS 4

// scratch (device globals: no allocations allowed)
__device__ float g_qkv [NROWS * QKVLD];
__device__ float g_ctx [NROWS * EDIM];
__device__ float g_comb[NROWS * 896];
__device__ float g_h   [NROWS * EDIM];
__device__ float g_te  [100 * 256];
__device__ float g_part[(size_t)SPLITS * NROWS * EDIM];   // unnormalized partial ctx
__device__ float g_psum[SPLITS * 8 * NROWS];              // partial row sums
__device__ int   g_perm  [NROWS];
__device__ int   g_ssteps[NROWS];
__device__ int   g_kstart[64];

// ---------------------------------------------------------------------------
// sinusoidal time table (double precision for fidelity)
// ---------------------------------------------------------------------------
__global__ void build_te_kernel() {
    int t = blockIdx.x * blockDim.x + threadIdx.x;
    if (t >= 100 * 128) return;
    int p = t >> 7;
    int k = t & 127;
    double div = exp(-((double)(2 * k)) * log(10000.0) / 256.0);
    double ang = (double)p * div;
    g_te[p * 256 + 2 * k]     = (float)sin(ang);
    g_te[p * 256 + 2 * k + 1] = (float)cos(ang);
}

// ---------------------------------------------------------------------------
// deterministic counting sort of rows by step + per-qtile kstart (round-2 ver)
// ---------------------------------------------------------------------------
__global__ void sort_kernel(const int* __restrict__ steps) {
    __shared__ int s_steps[NROWS];
    __shared__ int hist[100];
    __shared__ int base[100];
    const int t = threadIdx.x;

    for (int i = t; i < 100; i += 128) hist[i] = 0;
    __syncthreads();
    for (int i = t; i < NROWS; i += 128) {
        int s = steps[i];
        s = s < 0 ? 0 : (s > 99 ? 99 : s);
        s_steps[i] = s;
        atomicAdd(&hist[s], 1);
    }
    __syncthreads();
    if (t == 0) {
        int acc = 0;
        for (int b = 0; b < 100; b++) { base[b] = acc; acc += hist[b]; }
    }
    __syncthreads();
    if (t < 100) {                       // stable per-bucket scan (deterministic)
        int r = base[t];
        for (int i = 0; i < NROWS; i++) {
            if (s_steps[i] == t) {
                g_perm[r] = i;
                g_ssteps[r] = t;
                r++;
            }
        }
    }
    __syncthreads();
    if (t < 64) {
        int qmin = g_ssteps[t * 64];
        int ks = 0;
        while (ks < 64 && g_ssteps[ks * 64 + 63] < qmin) ks++;
        g_kstart[t] = ks;
    }
}

// ---------------------------------------------------------------------------
// SGEMM  C[M,N] = A[M,K] @ W[N,K]^T + bias
// 64x64 tile, BK=64, 64 threads, 8x8 micro-tile, XOR-swizzled smem rows.
// ---------------------------------------------------------------------------
__global__ __launch_bounds__(64)
void sgemm_bias_kernel(const float* __restrict__ A, int lda,
                       const float* __restrict__ W,
                       const float* __restrict__ bias,
                       float* __restrict__ C, int ldc, int K) {
    __shared__ float As[4096];
    __shared__ float Ws[4096];
    const int t  = threadIdx.x;
    const int tx = t & 7, ty = t >> 3;
    const int rt = (tx << 3) | ty;        // fill row (rt>>3 == tx)
    const int bm = blockIdx.y * 64, bn = blockIdx.x * 64;

    float acc[8][8] = {};                 // [m j][n i]

    for (int k0 = 0; k0 < K; k0 += 64) {
        __syncthreads();
        const float* ap = A + (size_t)(bm + rt) * lda + k0;
        const float* wp = W + (size_t)(bn + rt) * K   + k0;
        float* ad = As + rt * 64;
        float* wd = Ws + rt * 64;
        #pragma unroll
        for (int g = 0; g < 16; g++) {
            int pg = ((g ^ tx) << 2);
            *(float4*)(ad + pg) = *(const float4*)(ap + g * 4);
            *(float4*)(wd + pg) = *(const float4*)(wp + g * 4);
        }
        __syncthreads();

        #pragma unroll
        for (int kg = 0; kg < 16; kg++) {
            const int apg = (kg ^ tx) << 2;
            const int wpg = (kg ^ ty) << 2;
            float4 av[8];
            #pragma unroll
            for (int j = 0; j < 8; j++)
                av[j] = *(const float4*)(As + (tx * 8 + j) * 64 + apg);
            #pragma unroll
            for (int ih = 0; ih < 2; ih++) {
                float4 wv[4];
                #pragma unroll
                for (int i = 0; i < 4; i++)
                    wv[i] = *(const float4*)(Ws + (ty * 8 + ih * 4 + i) * 64 + wpg);
                #pragma unroll
                for (int j = 0; j < 8; j++)
                    #pragma unroll
                    for (int i = 0; i < 4; i++) {
                        acc[j][ih * 4 + i] += av[j].x * wv[i].x;
                        acc[j][ih * 4 + i] += av[j].y * wv[i].y;
                        acc[j][ih * 4 + i] += av[j].z * wv[i].z;
                        acc[j][ih * 4 + i] += av[j].w * wv[i].w;
                    }
            }
        }
    }

    float4 b0 = *(const float4*)(bias + bn + ty * 8);
    float4 b1 = *(const float4*)(bias + bn + ty * 8 + 4);
    #pragma unroll
    for (int j = 0; j < 8; j++) {
        float4 o0, o1;
        o0.x = acc[j][0] + b0.x; o0.y = acc[j][1] + b0.y;
        o0.z = acc[j][2] + b0.z; o0.w = acc[j][3] + b0.w;
        o1.x = acc[j][4] + b1.x; o1.y = acc[j][5] + b1.y;
        o1.z = acc[j][6] + b1.z; o1.w = acc[j][7] + b1.w;
        float* cp = C + (size_t)(bm + tx * 8 + j) * ldc + bn + ty * 8;
        *(float4*)cp       = o0;
        *(float4*)(cp + 4) = o1;
    }
}

// ---------------------------------------------------------------------------
// flash attention, sorted space, fixed-shift softmax, KV-split=4.
// grid (64 qtiles, 8 heads, 4 splits), 64 threads, 8x8 micro-tiles.
// Unnormalized partial O and row-sums go to g_part / g_psum (combined later).
// ---------------------------------------------------------------------------
__global__ __launch_bounds__(64, 4)
void attn_kernel() {
    extern __shared__ float sm[];
    float* Qs = sm;              // [q][d]   XOR row swizzle
    float* Ks = sm + 4096;       // [key][d] -> reused as Ss [key][q]
    float* Vs = sm + 8192;       // [key][d]
    float* Ss = Ks;
    __shared__ float red[64][9];
    __shared__ int sqs[64], sks[64];

    const int qt = blockIdx.x;
    const int h  = blockIdx.y;
    const int sp = blockIdx.z;
    const int qb = qt * 64;
    const int t  = threadIdx.x;
    const int tx = t & 7, ty = t >> 3;
    const int rt = (tx << 3) | ty;

    if (t < 64) sqs[t] = g_ssteps[qb + t];

    // Q tile fill (once per block)
    {
        const float* qp = g_qkv + (size_t)g_perm[qb + rt] * QKVLD + h * 64;
        float* dst = Qs + rt * 64;
        #pragma unroll
        for (int g = 0; g < 16; g++)
            *(float4*)(dst + ((g ^ tx) << 2)) = *(const float4*)(qp + g * 4);
    }
    __syncthreads();

    int sq8[8];
    #pragma unroll
    for (int j = 0; j < 8; j++) sq8[j] = sqs[tx * 8 + j];

    const int ks0 = g_kstart[qt];
    const int len = (64 - ks0 + SPLITS - 1) / SPLITS;
    const int k0  = ks0 + sp * len;
    const int k1  = (k0 + len < 64) ? (k0 + len) : 64;

    float acc [8][8] = {};
    float psum[8]    = {};

    for (int kt = k0; kt < k1; kt++) {
        const int kb = kt * 64;
        __syncthreads();                       // prior PV done with Ss/Vs
        {
            const float* kp = g_qkv + (size_t)g_perm[kb + rt] * QKVLD + 512 + h * 64;
            float* kd = Ks + rt * 64;
            float* vd = Vs + rt * 64;
            #pragma unroll
            for (int g = 0; g < 16; g++) {
                int pg = (g ^ tx) << 2;
                *(float4*)(kd + pg) = *(const float4*)(kp + g * 4);
                *(float4*)(vd + pg) = *(const float4*)(kp + 512 + g * 4);
            }
        }
        if (t < 64) sks[t] = g_ssteps[kb + t];
        __syncthreads();

        // S^T[key=ty*8+i][q=tx*8+j] = K . Q
        float sT[8][8] = {};
        #pragma unroll
        for (int kg = 0; kg < 16; kg++) {
            const int qpg = (kg ^ tx) << 2;
            const int kpg = (kg ^ ty) << 2;
            float4 qv[8];
            #pragma unroll
            for (int j = 0; j < 8; j++)
                qv[j] = *(const float4*)(Qs + (tx * 8 + j) * 64 + qpg);
            #pragma unroll
            for (int ih = 0; ih < 2; ih++) {
                float4 kv[4];
                #pragma unroll
                for (int i = 0; i < 4; i++)
                    kv[i] = *(const float4*)(Ks + (ty * 8 + ih * 4 + i) * 64 + kpg);
                #pragma unroll
                for (int i = 0; i < 4; i++)
                    #pragma unroll
                    for (int j = 0; j < 8; j++) {
                        sT[ih * 4 + i][j] += kv[i].x * qv[j].x;
                        sT[ih * 4 + i][j] += kv[i].y * qv[j].y;
                        sT[ih * 4 + i][j] += kv[i].z * qv[j].z;
                        sT[ih * 4 + i][j] += kv[i].w * qv[j].w;
                    }
            }
        }
        int sk8[8];
        #pragma unroll
        for (int i = 0; i < 8; i++) sk8[i] = sks[ty * 8 + i];
        __syncthreads();                       // everyone done reading Ks

        // p = exp(s/8) * (step_k >= step_q); stage P^T; accumulate row sums
        #pragma unroll
        for (int i = 0; i < 8; i++) {
            int ki = sk8[i];
            float4 w0, w1;
            w0.x = __expf(sT[i][0] * 0.125f) * ((ki >= sq8[0]) ? 1.f : 0.f);
            w0.y = __expf(sT[i][1] * 0.125f) * ((ki >= sq8[1]) ? 1.f : 0.f);
            w0.z = __expf(sT[i][2] * 0.125f) * ((ki >= sq8[2]) ? 1.f : 0.f);
            w0.w = __expf(sT[i][3] * 0.125f) * ((ki >= sq8[3]) ? 1.f : 0.f);
            w1.x = __expf(sT[i][4] * 0.125f) * ((ki >= sq8[4]) ? 1.f : 0.f);
            w1.y = __expf(sT[i][5] * 0.125f) * ((ki >= sq8[5]) ? 1.f : 0.f);
            w1.z = __expf(sT[i][6] * 0.125f) * ((ki >= sq8[6]) ? 1.f : 0.f);
            w1.w = __expf(sT[i][7] * 0.125f) * ((ki >= sq8[7]) ? 1.f : 0.f);
            psum[0] += w0.x; psum[1] += w0.y; psum[2] += w0.z; psum[3] += w0.w;
            psum[4] += w1.x; psum[5] += w1.y; psum[6] += w1.z; psum[7] += w1.w;
            float* sb = Ss + (ty * 8 + i) * 64 + ((tx ^ ty) << 2);
            *(float4*)sb        = w0;      // slot tx  ^ (key>>3)
            *(float4*)(sb + 32) = w1;      // slot tx+8 (bit3), +8 groups = +32 floats
        }
        __syncthreads();                       // Ss published

        // O[q=tx*8+j][d=ty*8..] += P @ V
        #pragma unroll 2
        for (int kk = 0; kk < 64; kk++) {
            const int c    = kk >> 3;
            const int base = kk * 64;
            float4 s0 = *(const float4*)(Ss + base + ((tx ^ c) << 2));
            float4 s1 = *(const float4*)(Ss + base + (((tx ^ c) + 8) << 2));
            float4 v0 = *(const float4*)(Vs + base + (((2 * ty)     ^ c) << 2));
            float4 v1 = *(const float4*)(Vs + base + (((2 * ty + 1) ^ c) << 2));
            acc[0][0] += s0.x * v0.x; acc[0][1] += s0.x * v0.y; acc[0][2] += s0.x * v0.z; acc[0][3] += s0.x * v0.w;
            acc[0][4] += s0.x * v1.x; acc[0][5] += s0.x * v1.y; acc[0][6] += s0.x * v1.z; acc[0][7] += s0.x * v1.w;
            acc[1][0] += s0.y * v0.x; acc[1][1] += s0.y * v0.y; acc[1][2] += s0.y * v0.z; acc[1][3] += s0.y * v0.w;
            acc[1][4] += s0.y * v1.x; acc[1][5] += s0.y * v1.y; acc[1][6] += s0.y * v1.z; acc[1][7] += s0.y * v1.w;
            acc[2][0] += s0.z * v0.x; acc[2][1] += s0.z * v0.y; acc[2][2] += s0.z * v0.z; acc[2][3] += s0.z * v0.w;
            acc[2][4] += s0.z * v1.x; acc[2][5] += s0.z * v1.y; acc[2][6] += s0.z * v1.z; acc[2][7] += s0.z * v1.w;
            acc[3][0] += s0.w * v0.x; acc[3][1] += s0.w * v0.y; acc[3][2] += s0.w * v0.z; acc[3][3] += s0.w * v0.w;
            acc[3][4] += s0.w * v1.x; acc[3][5] += s0.w * v1.y; acc[3][6] += s0.w * v1.z; acc[3][7] += s0.w * v1.w;
            acc[4][0] += s1.x * v0.x; acc[4][1] += s1.x * v0.y; acc[4][2] += s1.x * v0.z; acc[4][3] += s1.x * v0.w;
            acc[4][4] += s1.x * v1.x; acc[4][5] += s1.x * v1.y; acc[4][6] += s1.x * v1.z; acc[4][7] += s1.x * v1.w;
            acc[5][0] += s1.y * v0.x; acc[5][1] += s1.y * v0.y; acc[5][2] += s1.y * v0.z; acc[5][3] += s1.y * v0.w;
            acc[5][4] += s1.y * v1.x; acc[5][5] += s1.y * v1.y; acc[5][6] += s1.y * v1.z; acc[5][7] += s1.y * v1.w;
            acc[6][0] += s1.z * v0.x; acc[6][1] += s1.z * v0.y; acc[6][2] += s1.z * v0.z; acc[6][3] += s1.z * v0.w;
            acc[6][4] += s1.z * v1.x; acc[6][5] += s1.z * v1.y; acc[6][6] += s1.z * v1.z; acc[6][7] += s1.z * v1.w;
            acc[7][0] += s1.w * v0.x; acc[7][1] += s1.w * v0.y; acc[7][2] += s1.w * v0.z; acc[7][3] += s1.w * v0.w;
            acc[7][4] += s1.w * v1.x; acc[7][5] += s1.w * v1.y; acc[7][6] += s1.w * v1.z; acc[7][7] += s1.w * v1.w;
        }
    }

    // partial row-sum reduction (over key-octants ty) and output
    __syncthreads();
    #pragma unroll
    for (int j = 0; j < 8; j++) red[tx * 8 + j][ty] = psum[j];
    __syncthreads();
    if (t < 64) {
        float s = 0.f;
        #pragma unroll
        for (int c = 0; c < 8; c++) s += red[t][c];
        g_psum[(sp * 8 + h) * NROWS + qb + t] = s;
    }
    #pragma unroll
    for (int j = 0; j < 8; j++) {
        float* op = g_part + ((size_t)sp * NROWS + qb + tx * 8 + j) * EDIM + h * 64 + ty * 8;
        float4 o0, o1;
        o0.x = acc[j][0]; o0.y = acc[j][1]; o0.z = acc[j][2]; o0.w = acc[j][3];
        o1.x = acc[j][4]; o1.y = acc[j][5]; o1.z = acc[j][6]; o1.w = acc[j][7];
        *(float4*)op       = o0;
        *(float4*)(op + 4) = o1;
    }
}

// ---------------------------------------------------------------------------
// combine KV-splits: ctx[perm[r]] = sum_s part[s][r] / sum_s psum[s][h][r]
// ---------------------------------------------------------------------------
__global__ void combine_kernel() {
    const int r = blockIdx.x;
    const int t = threadIdx.x;
    __shared__ float inv[8];
    __shared__ int orow;
    if (t == 0) orow = g_perm[r];
    if (t < 8) {
        float tot = 0.f;
        #pragma unroll
        for (int s = 0; s < SPLITS; s++) tot += g_psum[(s * 8 + t) * NROWS + r];
        inv[t] = 1.f / tot;
    }
    __syncthreads();
    const int c = t * 4;
    float4 a = *(const float4*)&g_part[(size_t)r * EDIM + c];
    #pragma unroll
    for (int s = 1; s < SPLITS; s++) {
        float4 b = *(const float4*)&g_part[((size_t)s * NROWS + r) * EDIM + c];
        a.x += b.x; a.y += b.y; a.z += b.z; a.w += b.w;
    }
    float iv = inv[c >> 6];
    a.x *= iv; a.y *= iv; a.z *= iv; a.w *= iv;
    *(float4*)&g_ctx[(size_t)orow * EDIM + c] = a;
}

// ---------------------------------------------------------------------------
__global__ void fill_comb_kernel(const int* __restrict__ dmask,
                                 const int* __restrict__ steps,
                                 const float* __restrict__ status) {
    int row = blockIdx.x;
    int t = threadIdx.x;   // 0..383
    float v;
    if (t < 128) {
        v = status[dmask[row] * 128 + t];
    } else {
        int sc = steps[row];
        sc = sc < 0 ? 0 : (sc > 99 ? 99 : sc);
        v = g_te[sc * 256 + (t - 128)];
    }
    g_comb[row * 896 + 512 + t] = v;
}

// ---------------------------------------------------------------------------
__global__ void ln_relu_res_kernel(const float* __restrict__ x,
                                   const float* __restrict__ gamma,
                                   const float* __restrict__ beta,
                                   float* __restrict__ out) {
    int row = blockIdx.x;
    int t = threadIdx.x;
    const float* hr = g_h + row * EDIM;
    float v0 = hr[t], v1 = hr[t + 256];

    __shared__ float sh[8];
    __shared__ float stat[2];

    float s = v0 + v1;
    #pragma unroll
    for (int o = 16; o; o >>= 1) s += __shfl_xor_sync(0xffffffffu, s, o);
    if ((t & 31) == 0) sh[t >> 5] = s;
    __syncthreads();
    if (t == 0) {
        float tot = 0.f;
        #pragma unroll
        for (int i = 0; i < 8; i++) tot += sh[i];
        stat[0] = tot * (1.f / 512.f);
    }
    __syncthreads();
    float mu = stat[0];
    float d0 = v0 - mu, d1 = v1 - mu;
    float vv = d0 * d0 + d1 * d1;
    #pragma unroll
    for (int o = 16; o; o >>= 1) vv += __shfl_xor_sync(0xffffffffu, vv, o);
    if ((t & 31) == 0) sh[t >> 5] = vv;
    __syncthreads();
    if (t == 0) {
        float tot = 0.f;
        #pragma unroll
        for (int i = 0; i < 8; i++) tot += sh[i];
        stat[1] = 1.f / sqrtf(tot * (1.f / 512.f) + 1e-5f);
    }
    __syncthreads();
    float inv = stat[1];

    float y0 = fmaxf(d0 * inv * gamma[t]       + beta[t],       0.f);
    float y1 = fmaxf(d1 * inv * gamma[t + 256] + beta[t + 256], 0.f);
    out[row * EDIM + t]       = x[row * EDIM + t]       + y0;
    out[row * EDIM + t + 256] = x[row * EDIM + t + 256] + y1;
}

// ---------------------------------------------------------------------------
extern "C" void kernel_launch(void* const* d_in, const int* in_sizes, int n_in,
                              void* d_out, int out_size) {
    const float* x      = (const float*)d_in[0];
    const int*   dmask  = (const int*)  d_in[1];
    const int*   steps  = (const int*)  d_in[2];
    const float* status = (const float*)d_in[3];
    const float* wqkv   = (const float*)d_in[4];
    const float* bqkv   = (const float*)d_in[5];
    const float* wout   = (const float*)d_in[6];
    const float* bout   = (const float*)d_in[7];
    const float* wmlp   = (const float*)d_in[8];
    const float* bmlp   = (const float*)d_in[9];
    const float* gamma  = (const float*)d_in[10];
    const float* beta   = (const float*)d_in[11];
    float* out = (float*)d_out;

    float *qkv, *ctx, *comb, *hbuf;
    cudaGetSymbolAddress((void**)&qkv,  g_qkv);
    cudaGetSymbolAddress((void**)&ctx,  g_ctx);
    cudaGetSymbolAddress((void**)&comb, g_comb);
    cudaGetSymbolAddress((void**)&hbuf, g_h);

    const int attn_smem = 3 * 4096 * sizeof(float);   // 49152
    cudaFuncSetAttribute(attn_kernel, cudaFuncAttributeMaxDynamicSharedMemorySize,
                         attn_smem);

    sort_kernel<<<1, 128>>>(steps);
    build_te_kernel<<<50, 256>>>();

    // qkv = x @ Wqkv^T + b
    sgemm_bias_kernel<<<dim3(24, 64), 64>>>(x, 512, wqkv, bqkv, qkv, QKVLD, 512);

    // attention partials (sorted space, tile skipping, KV-split)
    attn_kernel<<<dim3(64, 8, SPLITS), 64, attn_smem>>>();

    // combine splits -> ctx (original row order)
    combine_kernel<<<4096, 128>>>();

    // x_att = ctx @ Wout^T + b  -> combined[:, 0:512]
    sgemm_bias_kernel<<<dim3(8, 64), 64>>>(ctx, 512, wout, bout, comb, 896, 512);

    // combined[:, 512:896] = [status | time]
    fill_comb_kernel<<<4096, 384>>>(dmask, steps, status);

    // h = combined @ Wmlp^T + b
    sgemm_bias_kernel<<<dim3(8, 64), 64>>>(comb, 896, wmlp, bmlp, hbuf, 512, 896);

    // out = x + relu(LN(h))
    ln_relu_res_kernel<<<4096, 256>>>(x, gamma, beta, out);
}

// round 5
// speedup vs baseline: 1.0092x; 1.0092x over previous
#include <cuda_runtime.h>
#include <math.h>

#define NROWS  4096
#define EDIM   512
#define QKVLD  1536
#define SPLITS 4

// scratch (device globals: no allocations allowed)
__device__ float g_qkv [NROWS * QKVLD];
__device__ float g_ctx [NROWS * EDIM];
__device__ float g_comb[NROWS * 896];
__device__ float g_h   [NROWS * EDIM];
__device__ float g_te  [100 * 256];
__device__ float g_part[(size_t)SPLITS * NROWS * EDIM];   // unnormalized partial ctx
__device__ float g_psum[SPLITS * 8 * NROWS];              // partial row sums
__device__ int   g_perm  [NROWS];
__device__ int   g_ssteps[NROWS];
__device__ int   g_kstart[64];

// ---------------------------------------------------------------------------
// sinusoidal time table (double precision for fidelity)
// ---------------------------------------------------------------------------
__global__ void build_te_kernel() {
    int t = blockIdx.x * blockDim.x + threadIdx.x;
    if (t >= 100 * 128) return;
    int p = t >> 7;
    int k = t & 127;
    double div = exp(-((double)(2 * k)) * log(10000.0) / 256.0);
    double ang = (double)p * div;
    g_te[p * 256 + 2 * k]     = (float)sin(ang);
    g_te[p * 256 + 2 * k + 1] = (float)cos(ang);
}

// ---------------------------------------------------------------------------
// deterministic counting sort of rows by step + per-qtile kstart (round-2 ver)
// ---------------------------------------------------------------------------
__global__ void sort_kernel(const int* __restrict__ steps) {
    __shared__ int s_steps[NROWS];
    __shared__ int hist[100];
    __shared__ int base[100];
    const int t = threadIdx.x;

    for (int i = t; i < 100; i += 128) hist[i] = 0;
    __syncthreads();
    for (int i = t; i < NROWS; i += 128) {
        int s = steps[i];
        s = s < 0 ? 0 : (s > 99 ? 99 : s);
        s_steps[i] = s;
        atomicAdd(&hist[s], 1);
    }
    __syncthreads();
    if (t == 0) {
        int acc = 0;
        for (int b = 0; b < 100; b++) { base[b] = acc; acc += hist[b]; }
    }
    __syncthreads();
    if (t < 100) {                       // stable per-bucket scan (deterministic)
        int r = base[t];
        for (int i = 0; i < NROWS; i++) {
            if (s_steps[i] == t) {
                g_perm[r] = i;
                g_ssteps[r] = t;
                r++;
            }
        }
    }
    __syncthreads();
    if (t < 64) {
        int qmin = g_ssteps[t * 64];
        int ks = 0;
        while (ks < 64 && g_ssteps[ks * 64 + 63] < qmin) ks++;
        g_kstart[t] = ks;
    }
}

// ---------------------------------------------------------------------------
// SGEMM  C[M,N] = A[M,K] @ W[N,K]^T + bias
// 64x64 tile, BK=64, 64 threads, 8x8 micro-tile, XOR-swizzled smem rows.
// ---------------------------------------------------------------------------
__global__ __launch_bounds__(64)
void sgemm_bias_kernel(const float* __restrict__ A, int lda,
                       const float* __restrict__ W,
                       const float* __restrict__ bias,
                       float* __restrict__ C, int ldc, int K) {
    __shared__ float As[4096];
    __shared__ float Ws[4096];
    const int t  = threadIdx.x;
    const int tx = t & 7, ty = t >> 3;
    const int rt = (tx << 3) | ty;        // fill row (rt>>3 == tx)
    const int bm = blockIdx.y * 64, bn = blockIdx.x * 64;

    float acc[8][8] = {};                 // [m j][n i]

    for (int k0 = 0; k0 < K; k0 += 64) {
        __syncthreads();
        const float* ap = A + (size_t)(bm + rt) * lda + k0;
        const float* wp = W + (size_t)(bn + rt) * K   + k0;
        float* ad = As + rt * 64;
        float* wd = Ws + rt * 64;
        #pragma unroll
        for (int g = 0; g < 16; g++) {
            int pg = ((g ^ tx) << 2);
            *(float4*)(ad + pg) = *(const float4*)(ap + g * 4);
            *(float4*)(wd + pg) = *(const float4*)(wp + g * 4);
        }
        __syncthreads();

        #pragma unroll
        for (int kg = 0; kg < 16; kg++) {
            const int apg = (kg ^ tx) << 2;
            const int wpg = (kg ^ ty) << 2;
            float4 av[8];
            #pragma unroll
            for (int j = 0; j < 8; j++)
                av[j] = *(const float4*)(As + (tx * 8 + j) * 64 + apg);
            #pragma unroll
            for (int ih = 0; ih < 2; ih++) {
                float4 wv[4];
                #pragma unroll
                for (int i = 0; i < 4; i++)
                    wv[i] = *(const float4*)(Ws + (ty * 8 + ih * 4 + i) * 64 + wpg);
                #pragma unroll
                for (int j = 0; j < 8; j++)
                    #pragma unroll
                    for (int i = 0; i < 4; i++) {
                        acc[j][ih * 4 + i] += av[j].x * wv[i].x;
                        acc[j][ih * 4 + i] += av[j].y * wv[i].y;
                        acc[j][ih * 4 + i] += av[j].z * wv[i].z;
                        acc[j][ih * 4 + i] += av[j].w * wv[i].w;
                    }
            }
        }
    }

    float4 b0 = *(const float4*)(bias + bn + ty * 8);
    float4 b1 = *(const float4*)(bias + bn + ty * 8 + 4);
    #pragma unroll
    for (int j = 0; j < 8; j++) {
        float4 o0, o1;
        o0.x = acc[j][0] + b0.x; o0.y = acc[j][1] + b0.y;
        o0.z = acc[j][2] + b0.z; o0.w = acc[j][3] + b0.w;
        o1.x = acc[j][4] + b1.x; o1.y = acc[j][5] + b1.y;
        o1.z = acc[j][6] + b1.z; o1.w = acc[j][7] + b1.w;
        float* cp = C + (size_t)(bm + tx * 8 + j) * ldc + bn + ty * 8;
        *(float4*)cp       = o0;
        *(float4*)(cp + 4) = o1;
    }
}

// ---------------------------------------------------------------------------
// flash attention, sorted space, fixed-shift softmax, KV-split=4.
// grid (64 qtiles, 8 heads, 4 splits), 64 threads, 8x8 micro-tiles.
// Unnormalized partial O and row-sums go to g_part / g_psum (combined later).
// ---------------------------------------------------------------------------
__global__ __launch_bounds__(64, 4)
void attn_kernel() {
    extern __shared__ float sm[];
    float* Qs = sm;              // [q][d]   XOR row swizzle
    float* Ks = sm + 4096;       // [key][d] -> reused as Ss [key][q]
    float* Vs = sm + 8192;       // [key][d]
    float* Ss = Ks;
    __shared__ float red[64][9];
    __shared__ int sqs[64], sks[64];

    const int qt = blockIdx.x;
    const int h  = blockIdx.y;
    const int sp = blockIdx.z;
    const int qb = qt * 64;
    const int t  = threadIdx.x;
    const int tx = t & 7, ty = t >> 3;
    const int rt = (tx << 3) | ty;

    if (t < 64) sqs[t] = g_ssteps[qb + t];

    // Q tile fill (once per block)
    {
        const float* qp = g_qkv + (size_t)g_perm[qb + rt] * QKVLD + h * 64;
        float* dst = Qs + rt * 64;
        #pragma unroll
        for (int g = 0; g < 16; g++)
            *(float4*)(dst + ((g ^ tx) << 2)) = *(const float4*)(qp + g * 4);
    }
    __syncthreads();

    int sq8[8];
    #pragma unroll
    for (int j = 0; j < 8; j++) sq8[j] = sqs[tx * 8 + j];

    const int ks0 = g_kstart[qt];
    const int len = (64 - ks0 + SPLITS - 1) / SPLITS;
    const int k0  = ks0 + sp * len;
    const int k1  = (k0 + len < 64) ? (k0 + len) : 64;

    float acc [8][8] = {};
    float psum[8]    = {};

    for (int kt = k0; kt < k1; kt++) {
        const int kb = kt * 64;
        __syncthreads();                       // prior PV done with Ss/Vs
        {
            const float* kp = g_qkv + (size_t)g_perm[kb + rt] * QKVLD + 512 + h * 64;
            float* kd = Ks + rt * 64;
            float* vd = Vs + rt * 64;
            #pragma unroll
            for (int g = 0; g < 16; g++) {
                int pg = (g ^ tx) << 2;
                *(float4*)(kd + pg) = *(const float4*)(kp + g * 4);
                *(float4*)(vd + pg) = *(const float4*)(kp + 512 + g * 4);
            }
        }
        if (t < 64) sks[t] = g_ssteps[kb + t];
        __syncthreads();

        // S^T[key=ty*8+i][q=tx*8+j] = K . Q
        float sT[8][8] = {};
        #pragma unroll
        for (int kg = 0; kg < 16; kg++) {
            const int qpg = (kg ^ tx) << 2;
            const int kpg = (kg ^ ty) << 2;
            float4 qv[8];
            #pragma unroll
            for (int j = 0; j < 8; j++)
                qv[j] = *(const float4*)(Qs + (tx * 8 + j) * 64 + qpg);
            #pragma unroll
            for (int ih = 0; ih < 2; ih++) {
                float4 kv[4];
                #pragma unroll
                for (int i = 0; i < 4; i++)
                    kv[i] = *(const float4*)(Ks + (ty * 8 + ih * 4 + i) * 64 + kpg);
                #pragma unroll
                for (int i = 0; i < 4; i++)
                    #pragma unroll
                    for (int j = 0; j < 8; j++) {
                        sT[ih * 4 + i][j] += kv[i].x * qv[j].x;
                        sT[ih * 4 + i][j] += kv[i].y * qv[j].y;
                        sT[ih * 4 + i][j] += kv[i].z * qv[j].z;
                        sT[ih * 4 + i][j] += kv[i].w * qv[j].w;
                    }
            }
        }
        int sk8[8];
        #pragma unroll
        for (int i = 0; i < 8; i++) sk8[i] = sks[ty * 8 + i];
        __syncthreads();                       // everyone done reading Ks

        // p = exp(s/8) * (step_k >= step_q); stage P^T; accumulate row sums
        #pragma unroll
        for (int i = 0; i < 8; i++) {
            int ki = sk8[i];
            float4 w0, w1;
            w0.x = __expf(sT[i][0] * 0.125f) * ((ki >= sq8[0]) ? 1.f : 0.f);
            w0.y = __expf(sT[i][1] * 0.125f) * ((ki >= sq8[1]) ? 1.f : 0.f);
            w0.z = __expf(sT[i][2] * 0.125f) * ((ki >= sq8[2]) ? 1.f : 0.f);
            w0.w = __expf(sT[i][3] * 0.125f) * ((ki >= sq8[3]) ? 1.f : 0.f);
            w1.x = __expf(sT[i][4] * 0.125f) * ((ki >= sq8[4]) ? 1.f : 0.f);
            w1.y = __expf(sT[i][5] * 0.125f) * ((ki >= sq8[5]) ? 1.f : 0.f);
            w1.z = __expf(sT[i][6] * 0.125f) * ((ki >= sq8[6]) ? 1.f : 0.f);
            w1.w = __expf(sT[i][7] * 0.125f) * ((ki >= sq8[7]) ? 1.f : 0.f);
            psum[0] += w0.x; psum[1] += w0.y; psum[2] += w0.z; psum[3] += w0.w;
            psum[4] += w1.x; psum[5] += w1.y; psum[6] += w1.z; psum[7] += w1.w;
            float* sb = Ss + (ty * 8 + i) * 64 + ((tx ^ ty) << 2);
            *(float4*)sb        = w0;      // slot tx  ^ (key>>3)
            *(float4*)(sb + 32) = w1;      // slot tx+8 (bit3), +8 groups = +32 floats
        }
        __syncthreads();                       // Ss published

        // O[q=tx*8+j][d=ty*8..] += P @ V
        #pragma unroll 2
        for (int kk = 0; kk < 64; kk++) {
            const int c    = kk >> 3;
            const int base = kk * 64;
            float4 s0 = *(const float4*)(Ss + base + ((tx ^ c) << 2));
            float4 s1 = *(const float4*)(Ss + base + (((tx ^ c) + 8) << 2));
            float4 v0 = *(const float4*)(Vs + base + (((2 * ty)     ^ c) << 2));
            float4 v1 = *(const float4*)(Vs + base + (((2 * ty + 1) ^ c) << 2));
            acc[0][0] += s0.x * v0.x; acc[0][1] += s0.x * v0.y; acc[0][2] += s0.x * v0.z; acc[0][3] += s0.x * v0.w;
            acc[0][4] += s0.x * v1.x; acc[0][5] += s0.x * v1.y; acc[0][6] += s0.x * v1.z; acc[0][7] += s0.x * v1.w;
            acc[1][0] += s0.y * v0.x; acc[1][1] += s0.y * v0.y; acc[1][2] += s0.y * v0.z; acc[1][3] += s0.y * v0.w;
            acc[1][4] += s0.y * v1.x; acc[1][5] += s0.y * v1.y; acc[1][6] += s0.y * v1.z; acc[1][7] += s0.y * v1.w;
            acc[2][0] += s0.z * v0.x; acc[2][1] += s0.z * v0.y; acc[2][2] += s0.z * v0.z; acc[2][3] += s0.z * v0.w;
            acc[2][4] += s0.z * v1.x; acc[2][5] += s0.z * v1.y; acc[2][6] += s0.z * v1.z; acc[2][7] += s0.z * v1.w;
            acc[3][0] += s0.w * v0.x; acc[3][1] += s0.w * v0.y; acc[3][2] += s0.w * v0.z; acc[3][3] += s0.w * v0.w;
            acc[3][4] += s0.w * v1.x; acc[3][5] += s0.w * v1.y; acc[3][6] += s0.w * v1.z; acc[3][7] += s0.w * v1.w;
            acc[4][0] += s1.x * v0.x; acc[4][1] += s1.x * v0.y; acc[4][2] += s1.x * v0.z; acc[4][3] += s1.x * v0.w;
            acc[4][4] += s1.x * v1.x; acc[4][5] += s1.x * v1.y; acc[4][6] += s1.x * v1.z; acc[4][7] += s1.x * v1.w;
            acc[5][0] += s1.y * v0.x; acc[5][1] += s1.y * v0.y; acc[5][2] += s1.y * v0.z; acc[5][3] += s1.y * v0.w;
            acc[5][4] += s1.y * v1.x; acc[5][5] += s1.y * v1.y; acc[5][6] += s1.y * v1.z; acc[5][7] += s1.y * v1.w;
            acc[6][0] += s1.z * v0.x; acc[6][1] += s1.z * v0.y; acc[6][2] += s1.z * v0.z; acc[6][3] += s1.z * v0.w;
            acc[6][4] += s1.z * v1.x; acc[6][5] += s1.z * v1.y; acc[6][6] += s1.z * v1.z; acc[6][7] += s1.z * v1.w;
            acc[7][0] += s1.w * v0.x; acc[7][1] += s1.w * v0.y; acc[7][2] += s1.w * v0.z; acc[7][3] += s1.w * v0.w;
            acc[7][4] += s1.w * v1.x; acc[7][5] += s1.w * v1.y; acc[7][6] += s1.w * v1.z; acc[7][7] += s1.w * v1.w;
        }
    }

    // partial row-sum reduction (over key-octants ty) and output
    __syncthreads();
    #pragma unroll
    for (int j = 0; j < 8; j++) red[tx * 8 + j][ty] = psum[j];
    __syncthreads();
    if (t < 64) {
        float s = 0.f;
        #pragma unroll
        for (int c = 0; c < 8; c++) s += red[t][c];
        g_psum[(sp * 8 + h) * NROWS + qb + t] = s;
    }
    #pragma unroll
    for (int j = 0; j < 8; j++) {
        float* op = g_part + ((size_t)sp * NROWS + qb + tx * 8 + j) * EDIM + h * 64 + ty * 8;
        float4 o0, o1;
        o0.x = acc[j][0]; o0.y = acc[j][1]; o0.z = acc[j][2]; o0.w = acc[j][3];
        o1.x = acc[j][4]; o1.y = acc[j][5]; o1.z = acc[j][6]; o1.w = acc[j][7];
        *(float4*)op       = o0;
        *(float4*)(op + 4) = o1;
    }
}

// ---------------------------------------------------------------------------
// combine KV-splits: ctx[perm[r]] = sum_s part[s][r] / sum_s psum[s][h][r]
// ---------------------------------------------------------------------------
__global__ void combine_kernel() {
    const int r = blockIdx.x;
    const int t = threadIdx.x;
    __shared__ float inv[8];
    __shared__ int orow;
    if (t == 0) orow = g_perm[r];
    if (t < 8) {
        float tot = 0.f;
        #pragma unroll
        for (int s = 0; s < SPLITS; s++) tot += g_psum[(s * 8 + t) * NROWS + r];
        inv[t] = 1.f / tot;
    }
    __syncthreads();
    const int c = t * 4;
    float4 a = *(const float4*)&g_part[(size_t)r * EDIM + c];
    #pragma unroll
    for (int s = 1; s < SPLITS; s++) {
        float4 b = *(const float4*)&g_part[((size_t)s * NROWS + r) * EDIM + c];
        a.x += b.x; a.y += b.y; a.z += b.z; a.w += b.w;
    }
    float iv = inv[c >> 6];
    a.x *= iv; a.y *= iv; a.z *= iv; a.w *= iv;
    *(float4*)&g_ctx[(size_t)orow * EDIM + c] = a;
}

// ---------------------------------------------------------------------------
__global__ void fill_comb_kernel(const int* __restrict__ dmask,
                                 const int* __restrict__ steps,
                                 const float* __restrict__ status) {
    int row = blockIdx.x;
    int t = threadIdx.x;   // 0..383
    float v;
    if (t < 128) {
        v = status[dmask[row] * 128 + t];
    } else {
        int sc = steps[row];
        sc = sc < 0 ? 0 : (sc > 99 ? 99 : sc);
        v = g_te[sc * 256 + (t - 128)];
    }
    g_comb[row * 896 + 512 + t] = v;
}

// ---------------------------------------------------------------------------
__global__ void ln_relu_res_kernel(const float* __restrict__ x,
                                   const float* __restrict__ gamma,
                                   const float* __restrict__ beta,
                                   float* __restrict__ out) {
    int row = blockIdx.x;
    int t = threadIdx.x;
    const float* hr = g_h + row * EDIM;
    float v0 = hr[t], v1 = hr[t + 256];

    __shared__ float sh[8];
    __shared__ float stat[2];

    float s = v0 + v1;
    #pragma unroll
    for (int o = 16; o; o >>= 1) s += __shfl_xor_sync(0xffffffffu, s, o);
    if ((t & 31) == 0) sh[t >> 5] = s;
    __syncthreads();
    if (t == 0) {
        float tot = 0.f;
        #pragma unroll
        for (int i = 0; i < 8; i++) tot += sh[i];
        stat[0] = tot * (1.f / 512.f);
    }
    __syncthreads();
    float mu = stat[0];
    float d0 = v0 - mu, d1 = v1 - mu;
    float vv = d0 * d0 + d1 * d1;
    #pragma unroll
    for (int o = 16; o; o >>= 1) vv += __shfl_xor_sync(0xffffffffu, vv, o);
    if ((t & 31) == 0) sh[t >> 5] = vv;
    __syncthreads();
    if (t == 0) {
        float tot = 0.f;
        #pragma unroll
        for (int i = 0; i < 8; i++) tot += sh[i];
        stat[1] = 1.f / sqrtf(tot * (1.f / 512.f) + 1e-5f);
    }
    __syncthreads();
    float inv = stat[1];

    float y0 = fmaxf(d0 * inv * gamma[t]       + beta[t],       0.f);
    float y1 = fmaxf(d1 * inv * gamma[t + 256] + beta[t + 256], 0.f);
    out[row * EDIM + t]       = x[row * EDIM + t]       + y0;
    out[row * EDIM + t + 256] = x[row * EDIM + t + 256] + y1;
}

// ---------------------------------------------------------------------------
extern "C" void kernel_launch(void* const* d_in, const int* in_sizes, int n_in,
                              void* d_out, int out_size) {
    const float* x      = (const float*)d_in[0];
    const int*   dmask  = (const int*)  d_in[1];
    const int*   steps  = (const int*)  d_in[2];
    const float* status = (const float*)d_in[3];
    const float* wqkv   = (const float*)d_in[4];
    const float* bqkv   = (const float*)d_in[5];
    const float* wout   = (const float*)d_in[6];
    const float* bout   = (const float*)d_in[7];
    const float* wmlp   = (const float*)d_in[8];
    const float* bmlp   = (const float*)d_in[9];
    const float* gamma  = (const float*)d_in[10];
    const float* beta   = (const float*)d_in[11];
    float* out = (float*)d_out;

    float *qkv, *ctx, *comb, *hbuf;
    cudaGetSymbolAddress((void**)&qkv,  g_qkv);
    cudaGetSymbolAddress((void**)&ctx,  g_ctx);
    cudaGetSymbolAddress((void**)&comb, g_comb);
    cudaGetSymbolAddress((void**)&hbuf, g_h);

    const int attn_smem = 3 * 4096 * sizeof(float);   // 49152
    cudaFuncSetAttribute(attn_kernel, cudaFuncAttributeMaxDynamicSharedMemorySize,
                         attn_smem);

    sort_kernel<<<1, 128>>>(steps);
    build_te_kernel<<<50, 256>>>();

    // qkv = x @ Wqkv^T + b
    sgemm_bias_kernel<<<dim3(24, 64), 64>>>(x, 512, wqkv, bqkv, qkv, QKVLD, 512);

    // attention partials (sorted space, tile skipping, KV-split)
    attn_kernel<<<dim3(64, 8, SPLITS), 64, attn_smem>>>();

    // combine splits -> ctx (original row order)
    combine_kernel<<<4096, 128>>>();

    // x_att = ctx @ Wout^T + b  -> combined[:, 0:512]
    sgemm_bias_kernel<<<dim3(8, 64), 64>>>(ctx, 512, wout, bout, comb, 896, 512);

    // combined[:, 512:896] = [status | time]
    fill_comb_kernel<<<4096, 384>>>(dmask, steps, status);

    // h = combined @ Wmlp^T + b
    sgemm_bias_kernel<<<dim3(8, 64), 64>>>(comb, 896, wmlp, bmlp, hbuf, 512, 896);

    // out = x + relu(LN(h))
    ln_relu_res_kernel<<<4096, 256>>>(x, gamma, beta, out);
}

// round 6
// speedup vs baseline: 1.8957x; 1.8785x over previous
#include <cuda_runtime.h>
#include <cuda_bf16.h>
#include <math.h>
#include <stdint.h>

#define NROWS 4096
#define EDIM  512
#define QKVLD 1536

// ---------------- device scratch (no allocations allowed) -------------------
__device__ float g_te[100 * 256];
__device__ int   g_perm[NROWS], g_sortpos[NROWS], g_ssteps[NROWS], g_kstart[64];

__device__ __align__(16) __nv_bfloat16 g_xh   [NROWS * EDIM],  g_xl   [NROWS * EDIM];
__device__ __align__(16) __nv_bfloat16 g_wqkvh[QKVLD * EDIM],  g_wqkvl[QKVLD * EDIM];
__device__ __align__(16) __nv_bfloat16 g_wouth[EDIM * EDIM],   g_woutl[EDIM * EDIM];
__device__ __align__(16) __nv_bfloat16 g_wmlph[EDIM * 896],    g_wmlpl[EDIM * 896];
__device__ __align__(16) __nv_bfloat16 g_qkvh [NROWS * QKVLD], g_qkvl [NROWS * QKVLD];
__device__ __align__(16) __nv_bfloat16 g_vth  [EDIM * NROWS],  g_vtl  [EDIM * NROWS];
__device__ __align__(16) __nv_bfloat16 g_ctxh [NROWS * EDIM],  g_ctxl [NROWS * EDIM];
__device__ __align__(16) __nv_bfloat16 g_combh[NROWS * 896],   g_combl[NROWS * 896];
__device__ float g_h[NROWS * EDIM];

// ---------------- helpers ----------------------------------------------------
__device__ __forceinline__ void mma16816(float* c,
    uint32_t a0, uint32_t a1, uint32_t a2, uint32_t a3,
    uint32_t b0, uint32_t b1) {
    asm volatile(
        "mma.sync.aligned.m16n8k16.row.col.f32.bf16.bf16.f32 "
        "{%0,%1,%2,%3},{%4,%5,%6,%7},{%8,%9},{%0,%1,%2,%3};"
        : "+f"(c[0]), "+f"(c[1]), "+f"(c[2]), "+f"(c[3])
        : "r"(a0), "r"(a1), "r"(a2), "r"(a3), "r"(b0), "r"(b1));
}

__device__ __forceinline__ void split2(float v0, float v1, uint32_t& hi, uint32_t& lo) {
    __nv_bfloat162 h = __floats2bfloat162_rn(v0, v1);
    float r0 = v0 - __bfloat162float(h.x);
    float r1 = v1 - __bfloat162float(h.y);
    __nv_bfloat162 l = __floats2bfloat162_rn(r0, r1);
    hi = *reinterpret_cast<uint32_t*>(&h);
    lo = *reinterpret_cast<uint32_t*>(&l);
}

// ---------------- time table ---------------------------------------------------
__global__ void build_te_kernel() {
    int t = blockIdx.x * blockDim.x + threadIdx.x;
    if (t >= 100 * 128) return;
    int p = t >> 7;
    int k = t & 127;
    double div = exp(-((double)(2 * k)) * log(10000.0) / 256.0);
    double ang = (double)p * div;
    g_te[p * 256 + 2 * k]     = (float)sin(ang);
    g_te[p * 256 + 2 * k + 1] = (float)cos(ang);
}

// ---------------- deterministic stable sort by step ----------------------------
__global__ void sort_kernel(const int* __restrict__ steps) {
    __shared__ int s_steps[NROWS];
    __shared__ int hist[100];
    __shared__ int base[100];
    const int t = threadIdx.x;

    for (int i = t; i < 100; i += 128) hist[i] = 0;
    __syncthreads();
    for (int i = t; i < NROWS; i += 128) {
        int s = steps[i];
        s = s < 0 ? 0 : (s > 99 ? 99 : s);
        s_steps[i] = s;
        atomicAdd(&hist[s], 1);
    }
    __syncthreads();
    if (t == 0) {
        int acc = 0;
        for (int b = 0; b < 100; b++) { base[b] = acc; acc += hist[b]; }
    }
    __syncthreads();
    if (t < 100) {
        int r = base[t];
        for (int i = 0; i < NROWS; i++) {
            if (s_steps[i] == t) {
                g_perm[r] = i;
                g_sortpos[i] = r;
                g_ssteps[r] = t;
                r++;
            }
        }
    }
    __syncthreads();
    if (t < 64) {
        int qmin = g_ssteps[t * 64];
        int ks = 0;
        while (ks < 64 && g_ssteps[ks * 64 + 63] < qmin) ks++;
        g_kstart[t] = ks;
    }
}

// ---------------- fp32 -> bf16 hi/lo split -------------------------------------
__global__ void cvt_split_kernel(const float* __restrict__ src,
                                 __nv_bfloat16* __restrict__ h,
                                 __nv_bfloat16* __restrict__ l, int n) {
    int i = (blockIdx.x * blockDim.x + threadIdx.x) * 2;
    if (i >= n) return;
    float2 v = *(const float2*)(src + i);
    uint32_t hw, lw;
    split2(v.x, v.y, hw, lw);
    *(uint32_t*)(h + i) = hw;
    *(uint32_t*)(l + i) = lw;
}

// ---------------- split-bf16 tensor GEMM ----------------------------------------
// C[M,N] = A[M,K] @ W[N,K]^T + bias, 64x64 tile, 128 thr (4 warps), k-chunk 64.
// MODE 0: bf16 hi/lo out, rows scattered via g_sortpos (qkv)
// MODE 1: bf16 hi/lo out, rows direct (out_proj -> comb)
// MODE 2: fp32 out, rows direct (mlp -> h)
template<int MODE>
__global__ __launch_bounds__(128)
void mma_gemm(const __nv_bfloat16* __restrict__ Ah, const __nv_bfloat16* __restrict__ Al,
              int lda,
              const __nv_bfloat16* __restrict__ Wh, const __nv_bfloat16* __restrict__ Wl,
              const float* __restrict__ bias, int K,
              float* __restrict__ Cf,
              __nv_bfloat16* __restrict__ Ch, __nv_bfloat16* __restrict__ Cl, int ldc) {
    __shared__ __align__(16) __nv_bfloat16 sA[2][64 * 72];
    __shared__ __align__(16) __nv_bfloat16 sW[2][64 * 72];
    const int t = threadIdx.x;
    const int w = t >> 5, lane = t & 31, g = lane >> 2, tq = lane & 3;
    const int bm = blockIdx.y * 64, bn = blockIdx.x * 64;
    const int lrow = t >> 1, lhalf = (t & 1) * 32;

    float c[8][4];
    #pragma unroll
    for (int i = 0; i < 8; i++)
        #pragma unroll
        for (int j = 0; j < 4; j++) c[i][j] = 0.f;

    for (int k0 = 0; k0 < K; k0 += 64) {
        __syncthreads();
        const size_t aoff = (size_t)(bm + lrow) * lda + k0 + lhalf;
        const size_t woff = (size_t)(bn + lrow) * K   + k0 + lhalf;
        #pragma unroll
        for (int j = 0; j < 4; j++) {
            *(uint4*)&sA[0][lrow * 72 + lhalf + j * 8] = *(const uint4*)(Ah + aoff + j * 8);
            *(uint4*)&sA[1][lrow * 72 + lhalf + j * 8] = *(const uint4*)(Al + aoff + j * 8);
            *(uint4*)&sW[0][lrow * 72 + lhalf + j * 8] = *(const uint4*)(Wh + woff + j * 8);
            *(uint4*)&sW[1][lrow * 72 + lhalf + j * 8] = *(const uint4*)(Wl + woff + j * 8);
        }
        __syncthreads();
        #pragma unroll
        for (int kb = 0; kb < 4; kb++) {
            const int ca = 16 * kb + 2 * tq;
            const int ra = 16 * w + g;
            uint32_t ah0 = *(const uint32_t*)&sA[0][ra * 72 + ca];
            uint32_t ah1 = *(const uint32_t*)&sA[0][(ra + 8) * 72 + ca];
            uint32_t ah2 = *(const uint32_t*)&sA[0][ra * 72 + ca + 8];
            uint32_t ah3 = *(const uint32_t*)&sA[0][(ra + 8) * 72 + ca + 8];
            uint32_t al0 = *(const uint32_t*)&sA[1][ra * 72 + ca];
            uint32_t al1 = *(const uint32_t*)&sA[1][(ra + 8) * 72 + ca];
            uint32_t al2 = *(const uint32_t*)&sA[1][ra * 72 + ca + 8];
            uint32_t al3 = *(const uint32_t*)&sA[1][(ra + 8) * 72 + ca + 8];
            #pragma unroll
            for (int nb = 0; nb < 8; nb++) {
                const int rb = 8 * nb + g;
                uint32_t bh0 = *(const uint32_t*)&sW[0][rb * 72 + ca];
                uint32_t bh1 = *(const uint32_t*)&sW[0][rb * 72 + ca + 8];
                uint32_t bl0 = *(const uint32_t*)&sW[1][rb * 72 + ca];
                uint32_t bl1 = *(const uint32_t*)&sW[1][rb * 72 + ca + 8];
                mma16816(c[nb], ah0, ah1, ah2, ah3, bh0, bh1);
                mma16816(c[nb], ah0, ah1, ah2, ah3, bl0, bl1);
                mma16816(c[nb], al0, al1, al2, al3, bh0, bh1);
            }
        }
    }

    const int r0 = bm + 16 * w + g, r1 = r0 + 8;
    size_t gr0, gr1;
    if (MODE == 0) { gr0 = g_sortpos[r0]; gr1 = g_sortpos[r1]; }
    else           { gr0 = r0;            gr1 = r1; }
    #pragma unroll
    for (int nb = 0; nb < 8; nb++) {
        const int col = bn + 8 * nb + 2 * tq;
        float b0 = __ldg(bias + col), b1 = __ldg(bias + col + 1);
        float v0 = c[nb][0] + b0, v1 = c[nb][1] + b1;
        float v2 = c[nb][2] + b0, v3 = c[nb][3] + b1;
        if (MODE == 2) {
            *(float2*)&Cf[gr0 * ldc + col] = make_float2(v0, v1);
            *(float2*)&Cf[gr1 * ldc + col] = make_float2(v2, v3);
        } else {
            uint32_t h0, l0, h1, l1;
            split2(v0, v1, h0, l0);
            split2(v2, v3, h1, l1);
            *(uint32_t*)&Ch[gr0 * ldc + col] = h0;
            *(uint32_t*)&Cl[gr0 * ldc + col] = l0;
            *(uint32_t*)&Ch[gr1 * ldc + col] = h1;
            *(uint32_t*)&Cl[gr1 * ldc + col] = l1;
        }
    }
}

// ---------------- V transpose: sorted qkv v-part -> [head][d][key] --------------
__global__ __launch_bounds__(128)
void vt_transpose_kernel() {
    __shared__ __align__(16) __nv_bfloat16 th[64 * 72], tl[64 * 72];
    const int t = threadIdx.x;
    const int rb = blockIdx.x * 64, h = blockIdx.y;
    const int lrow = t >> 1, lhalf = (t & 1) * 32;
    const size_t src = (size_t)(rb + lrow) * QKVLD + 1024 + h * 64 + lhalf;
    #pragma unroll
    for (int j = 0; j < 4; j++) {
        *(uint4*)&th[lrow * 72 + lhalf + j * 8] = *(const uint4*)(g_qkvh + src + j * 8);
        *(uint4*)&tl[lrow * 72 + lhalf + j * 8] = *(const uint4*)(g_qkvl + src + j * 8);
    }
    __syncthreads();
    const int d = t >> 1, kh = (t & 1) * 32;
    __nv_bfloat16* dh = g_vth + (size_t)(h * 64 + d) * NROWS + rb;
    __nv_bfloat16* dl = g_vtl + (size_t)(h * 64 + d) * NROWS + rb;
    #pragma unroll
    for (int j = 0; j < 16; j++) {
        int sr = kh + 2 * j;
        __nv_bfloat162 a, b;
        a.x = th[sr * 72 + d]; a.y = th[(sr + 1) * 72 + d];
        b.x = tl[sr * 72 + d]; b.y = tl[(sr + 1) * 72 + d];
        *(__nv_bfloat162*)(dh + sr) = a;
        *(__nv_bfloat162*)(dl + sr) = b;
    }
}

// ---------------- tensor-core flash attention (sorted space) --------------------
__global__ __launch_bounds__(128)
void attn_kernel() {
    extern __shared__ __align__(16) unsigned char smraw[];
    __nv_bfloat16* Qh = (__nv_bfloat16*)smraw;
    __nv_bfloat16* Ql = Qh + 1 * 4608;
    __nv_bfloat16* Kh = Qh + 2 * 4608;
    __nv_bfloat16* Kl = Qh + 3 * 4608;
    __nv_bfloat16* Th = Qh + 4 * 4608;
    __nv_bfloat16* Tl = Qh + 5 * 4608;
    int* sks = (int*)(smraw + 6 * 4608 * 2);

    const int qt = blockIdx.x, h = blockIdx.y;
    const int qb = qt * 64;
    const int t = threadIdx.x, w = t >> 5, lane = t & 31, g = lane >> 2, tq = lane & 3;
    const int lrow = t >> 1, lhalf = (t & 1) * 32;

    {
        const size_t src = (size_t)(qb + lrow) * QKVLD + h * 64 + lhalf;
        #pragma unroll
        for (int j = 0; j < 4; j++) {
            *(uint4*)&Qh[lrow * 72 + lhalf + j * 8] = *(const uint4*)(g_qkvh + src + j * 8);
            *(uint4*)&Ql[lrow * 72 + lhalf + j * 8] = *(const uint4*)(g_qkvl + src + j * 8);
        }
    }
    const int sq_a = g_ssteps[qb + 16 * w + g];
    const int sq_b = g_ssteps[qb + 16 * w + g + 8];

    float o[8][4];
    #pragma unroll
    for (int i = 0; i < 8; i++)
        #pragma unroll
        for (int j = 0; j < 4; j++) o[i][j] = 0.f;
    float ps_a = 0.f, ps_b = 0.f;

    for (int kt = g_kstart[qt]; kt < 64; kt++) {
        const int kb64 = kt * 64;
        __syncthreads();
        {
            const size_t ks = (size_t)(kb64 + lrow) * QKVLD + 512 + h * 64 + lhalf;
            const size_t vs = (size_t)(h * 64 + lrow) * NROWS + kb64 + lhalf;
            #pragma unroll
            for (int j = 0; j < 4; j++) {
                *(uint4*)&Kh[lrow * 72 + lhalf + j * 8] = *(const uint4*)(g_qkvh + ks + j * 8);
                *(uint4*)&Kl[lrow * 72 + lhalf + j * 8] = *(const uint4*)(g_qkvl + ks + j * 8);
                *(uint4*)&Th[lrow * 72 + lhalf + j * 8] = *(const uint4*)(g_vth  + vs + j * 8);
                *(uint4*)&Tl[lrow * 72 + lhalf + j * 8] = *(const uint4*)(g_vtl  + vs + j * 8);
            }
            if (t < 64) sks[t] = g_ssteps[kb64 + t];
        }
        __syncthreads();

        // S = Q K^T
        float s[8][4];
        #pragma unroll
        for (int i = 0; i < 8; i++)
            #pragma unroll
            for (int j = 0; j < 4; j++) s[i][j] = 0.f;
        #pragma unroll
        for (int kb = 0; kb < 4; kb++) {
            const int ca = 16 * kb + 2 * tq;
            const int ra = 16 * w + g;
            uint32_t qh0 = *(const uint32_t*)&Qh[ra * 72 + ca];
            uint32_t qh1 = *(const uint32_t*)&Qh[(ra + 8) * 72 + ca];
            uint32_t qh2 = *(const uint32_t*)&Qh[ra * 72 + ca + 8];
            uint32_t qh3 = *(const uint32_t*)&Qh[(ra + 8) * 72 + ca + 8];
            uint32_t ql0 = *(const uint32_t*)&Ql[ra * 72 + ca];
            uint32_t ql1 = *(const uint32_t*)&Ql[(ra + 8) * 72 + ca];
            uint32_t ql2 = *(const uint32_t*)&Ql[ra * 72 + ca + 8];
            uint32_t ql3 = *(const uint32_t*)&Ql[(ra + 8) * 72 + ca + 8];
            #pragma unroll
            for (int nb = 0; nb < 8; nb++) {
                const int rk = 8 * nb + g;
                uint32_t bh0 = *(const uint32_t*)&Kh[rk * 72 + ca];
                uint32_t bh1 = *(const uint32_t*)&Kh[rk * 72 + ca + 8];
                uint32_t bl0 = *(const uint32_t*)&Kl[rk * 72 + ca];
                uint32_t bl1 = *(const uint32_t*)&Kl[rk * 72 + ca + 8];
                mma16816(s[nb], qh0, qh1, qh2, qh3, bh0, bh1);
                mma16816(s[nb], qh0, qh1, qh2, qh3, bl0, bl1);
                mma16816(s[nb], ql0, ql1, ql2, ql3, bh0, bh1);
            }
        }

        // softmax (fixed shift) + mask; P A-frags built in registers
        uint32_t pah[16], pal[16];
        #pragma unroll
        for (int nb = 0; nb < 8; nb++) {
            int2 kk = *(const int2*)&sks[8 * nb + 2 * tq];
            float p0 = __expf(s[nb][0] * 0.125f); if (kk.x < sq_a) p0 = 0.f;
            float p1 = __expf(s[nb][1] * 0.125f); if (kk.y < sq_a) p1 = 0.f;
            float p2 = __expf(s[nb][2] * 0.125f); if (kk.x < sq_b) p2 = 0.f;
            float p3 = __expf(s[nb][3] * 0.125f); if (kk.y < sq_b) p3 = 0.f;
            ps_a += p0 + p1;
            ps_b += p2 + p3;
            split2(p0, p1, pah[2 * nb],     pal[2 * nb]);
            split2(p2, p3, pah[2 * nb + 1], pal[2 * nb + 1]);
        }

        // O += P @ V  (V^T tiles as col-major B)
        #pragma unroll
        for (int kb = 0; kb < 4; kb++) {
            uint32_t a0h = pah[4 * kb],     a1h = pah[4 * kb + 1];
            uint32_t a2h = pah[4 * kb + 2], a3h = pah[4 * kb + 3];
            uint32_t a0l = pal[4 * kb],     a1l = pal[4 * kb + 1];
            uint32_t a2l = pal[4 * kb + 2], a3l = pal[4 * kb + 3];
            const int cv = 16 * kb + 2 * tq;
            #pragma unroll
            for (int nb = 0; nb < 8; nb++) {
                const int rv = 8 * nb + g;
                uint32_t bh0 = *(const uint32_t*)&Th[rv * 72 + cv];
                uint32_t bh1 = *(const uint32_t*)&Th[rv * 72 + cv + 8];
                uint32_t bl0 = *(const uint32_t*)&Tl[rv * 72 + cv];
                uint32_t bl1 = *(const uint32_t*)&Tl[rv * 72 + cv + 8];
                mma16816(o[nb], a0h, a1h, a2h, a3h, bh0, bh1);
                mma16816(o[nb], a0h, a1h, a2h, a3h, bl0, bl1);
                mma16816(o[nb], a0l, a1l, a2l, a3l, bh0, bh1);
            }
        }
    }

    ps_a += __shfl_xor_sync(0xffffffffu, ps_a, 1);
    ps_a += __shfl_xor_sync(0xffffffffu, ps_a, 2);
    ps_b += __shfl_xor_sync(0xffffffffu, ps_b, 1);
    ps_b += __shfl_xor_sync(0xffffffffu, ps_b, 2);
    const float inv_a = 1.f / ps_a, inv_b = 1.f / ps_b;
    const size_t r0 = qb + 16 * w + g, r1 = r0 + 8;
    #pragma unroll
    for (int nb = 0; nb < 8; nb++) {
        const int col = h * 64 + 8 * nb + 2 * tq;
        uint32_t h0, l0, h1, l1;
        split2(o[nb][0] * inv_a, o[nb][1] * inv_a, h0, l0);
        split2(o[nb][2] * inv_b, o[nb][3] * inv_b, h1, l1);
        *(uint32_t*)&g_ctxh[r0 * EDIM + col] = h0;
        *(uint32_t*)&g_ctxl[r0 * EDIM + col] = l0;
        *(uint32_t*)&g_ctxh[r1 * EDIM + col] = h1;
        *(uint32_t*)&g_ctxl[r1 * EDIM + col] = l1;
    }
}

// ---------------- fill comb cols 512..895 (sorted rows, hi/lo) ------------------
__global__ void fill_comb_kernel(const int* __restrict__ dmask,
                                 const int* __restrict__ steps,
                                 const float* __restrict__ status) {
    const int r = blockIdx.x;
    __shared__ int so;
    if (threadIdx.x == 0) so = g_perm[r];
    __syncthreads();
    const int col = 2 * threadIdx.x;           // 0..382
    float v0, v1;
    if (col < 128) {
        int dm = dmask[so];
        v0 = status[dm * 128 + col];
        v1 = status[dm * 128 + col + 1];
    } else {
        int sc = steps[so];
        sc = sc < 0 ? 0 : (sc > 99 ? 99 : sc);
        v0 = g_te[sc * 256 + col - 128];
        v1 = g_te[sc * 256 + col - 127];
    }
    uint32_t hw, lw;
    split2(v0, v1, hw, lw);
    *(uint32_t*)&g_combh[(size_t)r * 896 + 512 + col] = hw;
    *(uint32_t*)&g_combl[(size_t)r * 896 + 512 + col] = lw;
}

// ---------------- LayerNorm -> ReLU -> residual (un-permute) --------------------
__global__ void ln_relu_res_kernel(const float* __restrict__ x,
                                   const float* __restrict__ gamma,
                                   const float* __restrict__ beta,
                                   float* __restrict__ out) {
    const int r = blockIdx.x;
    const int t = threadIdx.x;
    __shared__ float sh[8];
    __shared__ float stat[2];
    __shared__ int so;
    if (t == 0) so = g_perm[r];

    const float* hr = g_h + (size_t)r * EDIM;
    float v0 = hr[t], v1 = hr[t + 256];

    float s = v0 + v1;
    #pragma unroll
    for (int o2 = 16; o2; o2 >>= 1) s += __shfl_xor_sync(0xffffffffu, s, o2);
    if ((t & 31) == 0) sh[t >> 5] = s;
    __syncthreads();
    if (t == 0) {
        float tot = 0.f;
        #pragma unroll
        for (int i = 0; i < 8; i++) tot += sh[i];
        stat[0] = tot * (1.f / 512.f);
    }
    __syncthreads();
    float mu = stat[0];
    float d0 = v0 - mu, d1 = v1 - mu;
    float vv = d0 * d0 + d1 * d1;
    #pragma unroll
    for (int o2 = 16; o2; o2 >>= 1) vv += __shfl_xor_sync(0xffffffffu, vv, o2);
    if ((t & 31) == 0) sh[t >> 5] = vv;
    __syncthreads();
    if (t == 0) {
        float tot = 0.f;
        #pragma unroll
        for (int i = 0; i < 8; i++) tot += sh[i];
        stat[1] = 1.f / sqrtf(tot * (1.f / 512.f) + 1e-5f);
    }
    __syncthreads();
    float inv = stat[1];

    float y0 = fmaxf(d0 * inv * gamma[t]       + beta[t],       0.f);
    float y1 = fmaxf(d1 * inv * gamma[t + 256] + beta[t + 256], 0.f);
    const size_t orow = so;
    out[orow * EDIM + t]       = x[orow * EDIM + t]       + y0;
    out[orow * EDIM + t + 256] = x[orow * EDIM + t + 256] + y1;
}

// ---------------- launch ---------------------------------------------------------
extern "C" void kernel_launch(void* const* d_in, const int* in_sizes, int n_in,
                              void* d_out, int out_size) {
    const float* x      = (const float*)d_in[0];
    const int*   dmask  = (const int*)  d_in[1];
    const int*   steps  = (const int*)  d_in[2];
    const float* status = (const float*)d_in[3];
    const float* wqkv   = (const float*)d_in[4];
    const float* bqkv   = (const float*)d_in[5];
    const float* wout   = (const float*)d_in[6];
    const float* bout   = (const float*)d_in[7];
    const float* wmlp   = (const float*)d_in[8];
    const float* bmlp   = (const float*)d_in[9];
    const float* gamma  = (const float*)d_in[10];
    const float* beta   = (const float*)d_in[11];
    float* out = (float*)d_out;

    __nv_bfloat16 *xh, *xl, *wqh, *wql, *woh, *wol, *wmh, *wml;
    __nv_bfloat16 *qkvh, *qkvl, *ctxh, *ctxl, *combh, *combl;
    float* hbuf;
    cudaGetSymbolAddress((void**)&xh,    g_xh);
    cudaGetSymbolAddress((void**)&xl,    g_xl);
    cudaGetSymbolAddress((void**)&wqh,   g_wqkvh);
    cudaGetSymbolAddress((void**)&wql,   g_wqkvl);
    cudaGetSymbolAddress((void**)&woh,   g_wouth);
    cudaGetSymbolAddress((void**)&wol,   g_woutl);
    cudaGetSymbolAddress((void**)&wmh,   g_wmlph);
    cudaGetSymbolAddress((void**)&wml,   g_wmlpl);
    cudaGetSymbolAddress((void**)&qkvh,  g_qkvh);
    cudaGetSymbolAddress((void**)&qkvl,  g_qkvl);
    cudaGetSymbolAddress((void**)&ctxh,  g_ctxh);
    cudaGetSymbolAddress((void**)&ctxl,  g_ctxl);
    cudaGetSymbolAddress((void**)&combh, g_combh);
    cudaGetSymbolAddress((void**)&combl, g_combl);
    cudaGetSymbolAddress((void**)&hbuf,  g_h);

    const int attn_smem = 6 * 4608 * 2 + 64 * 4;   // 55552
    cudaFuncSetAttribute(attn_kernel, cudaFuncAttributeMaxDynamicSharedMemorySize,
                         attn_smem);

    sort_kernel<<<1, 128>>>(steps);
    build_te_kernel<<<50, 256>>>();

    // input/weight splits
    cvt_split_kernel<<<(NROWS * EDIM / 2 + 255) / 256, 256>>>(x,    xh,  xl,  NROWS * EDIM);
    cvt_split_kernel<<<(QKVLD * EDIM / 2 + 255) / 256, 256>>>(wqkv, wqh, wql, QKVLD * EDIM);
    cvt_split_kernel<<<(EDIM * EDIM / 2 + 255) / 256, 256>>>(wout, woh, wol, EDIM * EDIM);
    cvt_split_kernel<<<(EDIM * 896 / 2 + 255) / 256, 256>>>(wmlp, wmh, wml, EDIM * 896);

    // qkv = x @ Wqkv^T + b  (rows scattered into sorted order)
    mma_gemm<0><<<dim3(24, 64), 128>>>(xh, xl, EDIM, wqh, wql, bqkv, EDIM,
                                       nullptr, qkvh, qkvl, QKVLD);

    // V -> [head][d][key]
    vt_transpose_kernel<<<dim3(64, 8), 128>>>();

    // attention -> ctx (sorted, hi/lo)
    attn_kernel<<<dim3(64, 8), 128, attn_smem>>>();

    // x_att = ctx @ Wout^T + b -> comb cols 0..511
    mma_gemm<1><<<dim3(8, 64), 128>>>(ctxh, ctxl, EDIM, woh, wol, bout, EDIM,
                                      nullptr, combh, combl, 896);

    // comb cols 512..895
    fill_comb_kernel<<<4096, 192>>>(dmask, steps, status);

    // h = comb @ Wmlp^T + b (fp32)
    mma_gemm<2><<<dim3(8, 64), 128>>>(combh, combl, 896, wmh, wml, bmlp, 896,
                                      hbuf, nullptr, nullptr, EDIM);

    // out = x + relu(LN(h)) (un-permuted)
    ln_relu_res_kernel<<<4096, 256>>>(x, gamma, beta, out);
}

// round 7
// speedup vs baseline: 2.2622x; 1.1933x over previous
#include <cuda_runtime.h>
#include <cuda_bf16.h>
#include <math.h>
#include <stdint.h>

#define NROWS 4096
#define EDIM  512
#define QKVLD 1536

// ---------------- device scratch (no allocations allowed) -------------------
__device__ float g_te[100 * 256];
__device__ int   g_perm[NROWS], g_sortpos[NROWS], g_ssteps[NROWS], g_kstart[64];

__device__ __align__(16) __nv_bfloat16 g_xh   [NROWS * EDIM],  g_xl   [NROWS * EDIM];
__device__ __align__(16) __nv_bfloat16 g_wqkvh[QKVLD * EDIM],  g_wqkvl[QKVLD * EDIM];
__device__ __align__(16) __nv_bfloat16 g_wouth[EDIM * EDIM],   g_woutl[EDIM * EDIM];
__device__ __align__(16) __nv_bfloat16 g_wmlph[EDIM * 896],    g_wmlpl[EDIM * 896];
__device__ __align__(16) __nv_bfloat16 g_qkvh [NROWS * QKVLD], g_qkvl [NROWS * QKVLD];
__device__ __align__(16) __nv_bfloat16 g_vth  [EDIM * NROWS],  g_vtl  [EDIM * NROWS];
__device__ __align__(16) __nv_bfloat16 g_ctxh [NROWS * EDIM],  g_ctxl [NROWS * EDIM];
__device__ __align__(16) __nv_bfloat16 g_combh[NROWS * 896],   g_combl[NROWS * 896];
__device__ float g_h[NROWS * EDIM];

// ---------------- helpers ----------------------------------------------------
__device__ __forceinline__ void mma16816(float* c,
    uint32_t a0, uint32_t a1, uint32_t a2, uint32_t a3,
    uint32_t b0, uint32_t b1) {
    asm volatile(
        "mma.sync.aligned.m16n8k16.row.col.f32.bf16.bf16.f32 "
        "{%0,%1,%2,%3},{%4,%5,%6,%7},{%8,%9},{%0,%1,%2,%3};"
        : "+f"(c[0]), "+f"(c[1]), "+f"(c[2]), "+f"(c[3])
        : "r"(a0), "r"(a1), "r"(a2), "r"(a3), "r"(b0), "r"(b1));
}

__device__ __forceinline__ void ldsm4(uint32_t* r, uint32_t addr) {
    asm volatile("ldmatrix.sync.aligned.m8n8.x4.shared.b16 {%0,%1,%2,%3}, [%4];"
        : "=r"(r[0]), "=r"(r[1]), "=r"(r[2]), "=r"(r[3]) : "r"(addr));
}

__device__ __forceinline__ void split2(float v0, float v1, uint32_t& hi, uint32_t& lo) {
    __nv_bfloat162 h = __floats2bfloat162_rn(v0, v1);
    float r0 = v0 - __bfloat162float(h.x);
    float r1 = v1 - __bfloat162float(h.y);
    __nv_bfloat162 l = __floats2bfloat162_rn(r0, r1);
    hi = *reinterpret_cast<uint32_t*>(&h);
    lo = *reinterpret_cast<uint32_t*>(&l);
}

// ---------------- time table ---------------------------------------------------
__global__ void build_te_kernel() {
    int t = blockIdx.x * blockDim.x + threadIdx.x;
    if (t >= 100 * 128) return;
    int p = t >> 7;
    int k = t & 127;
    double div = exp(-((double)(2 * k)) * log(10000.0) / 256.0);
    double ang = (double)p * div;
    g_te[p * 256 + 2 * k]     = (float)sin(ang);
    g_te[p * 256 + 2 * k + 1] = (float)cos(ang);
}

// ---------------- deterministic stable sort by step ----------------------------
__global__ void sort_kernel(const int* __restrict__ steps) {
    __shared__ int s_steps[NROWS];
    __shared__ int hist[100];
    __shared__ int base[100];
    const int t = threadIdx.x;

    for (int i = t; i < 100; i += 128) hist[i] = 0;
    __syncthreads();
    for (int i = t; i < NROWS; i += 128) {
        int s = steps[i];
        s = s < 0 ? 0 : (s > 99 ? 99 : s);
        s_steps[i] = s;
        atomicAdd(&hist[s], 1);
    }
    __syncthreads();
    if (t == 0) {
        int acc = 0;
        for (int b = 0; b < 100; b++) { base[b] = acc; acc += hist[b]; }
    }
    __syncthreads();
    if (t < 100) {
        int r = base[t];
        for (int i = 0; i < NROWS; i++) {
            if (s_steps[i] == t) {
                g_perm[r] = i;
                g_sortpos[i] = r;
                g_ssteps[r] = t;
                r++;
            }
        }
    }
    __syncthreads();
    if (t < 64) {
        int qmin = g_ssteps[t * 64];
        int ks = 0;
        while (ks < 64 && g_ssteps[ks * 64 + 63] < qmin) ks++;
        g_kstart[t] = ks;
    }
}

// ---------------- fp32 -> bf16 hi/lo split -------------------------------------
__global__ void cvt_split_kernel(const float* __restrict__ src,
                                 __nv_bfloat16* __restrict__ h,
                                 __nv_bfloat16* __restrict__ l, int n) {
    int i = (blockIdx.x * blockDim.x + threadIdx.x) * 2;
    if (i >= n) return;
    float2 v = *(const float2*)(src + i);
    uint32_t hw, lw;
    split2(v.x, v.y, hw, lw);
    *(uint32_t*)(h + i) = hw;
    *(uint32_t*)(l + i) = lw;
}

// ---------------- split-bf16 tensor GEMM (ldmatrix fragments) -------------------
// C[M,N] = A[M,K] @ W[N,K]^T + bias, 64x64 tile, 128 thr (4 warps), k-chunk 64.
// MODE 0: bf16 hi/lo out, rows scattered via g_sortpos; 1: bf16 direct; 2: fp32.
template<int MODE>
__global__ __launch_bounds__(128)
void mma_gemm(const __nv_bfloat16* __restrict__ Ah, const __nv_bfloat16* __restrict__ Al,
              int lda,
              const __nv_bfloat16* __restrict__ Wh, const __nv_bfloat16* __restrict__ Wl,
              const float* __restrict__ bias, int K,
              float* __restrict__ Cf,
              __nv_bfloat16* __restrict__ Ch, __nv_bfloat16* __restrict__ Cl, int ldc) {
    __shared__ __align__(16) __nv_bfloat16 sA[2][64 * 72];
    __shared__ __align__(16) __nv_bfloat16 sW[2][64 * 72];
    const int t = threadIdx.x;
    const int w = t >> 5, lane = t & 31, g = lane >> 2, tq = lane & 3;
    const int bm = blockIdx.y * 64, bn = blockIdx.x * 64;
    const int lrow = t >> 1, lhalf = (t & 1) * 32;

    const uint32_t shAh = (uint32_t)__cvta_generic_to_shared(&sA[0][0]);
    const uint32_t shAl = (uint32_t)__cvta_generic_to_shared(&sA[1][0]);
    const uint32_t shWh = (uint32_t)__cvta_generic_to_shared(&sW[0][0]);
    const uint32_t shWl = (uint32_t)__cvta_generic_to_shared(&sW[1][0]);

    const int lr  = lane & 7;
    const int sel = lane >> 3;
    const uint32_t aoff = (uint32_t)(((16 * w + (sel & 1) * 8 + lr) * 72 + (sel >> 1) * 8) * 2);
    const uint32_t boff = (uint32_t)((((sel >> 1) * 8 + lr) * 72 + (sel & 1) * 8) * 2);

    float c[8][4];
    #pragma unroll
    for (int i = 0; i < 8; i++)
        #pragma unroll
        for (int j = 0; j < 4; j++) c[i][j] = 0.f;

    for (int k0 = 0; k0 < K; k0 += 64) {
        __syncthreads();
        const size_t ao = (size_t)(bm + lrow) * lda + k0 + lhalf;
        const size_t wo = (size_t)(bn + lrow) * K   + k0 + lhalf;
        #pragma unroll
        for (int j = 0; j < 4; j++) {
            *(uint4*)&sA[0][lrow * 72 + lhalf + j * 8] = *(const uint4*)(Ah + ao + j * 8);
            *(uint4*)&sA[1][lrow * 72 + lhalf + j * 8] = *(const uint4*)(Al + ao + j * 8);
            *(uint4*)&sW[0][lrow * 72 + lhalf + j * 8] = *(const uint4*)(Wh + wo + j * 8);
            *(uint4*)&sW[1][lrow * 72 + lhalf + j * 8] = *(const uint4*)(Wl + wo + j * 8);
        }
        __syncthreads();
        #pragma unroll
        for (int kb = 0; kb < 4; kb++) {
            uint32_t ah[4], al[4];
            ldsm4(ah, shAh + aoff + kb * 32);
            ldsm4(al, shAl + aoff + kb * 32);
            #pragma unroll
            for (int p = 0; p < 4; p++) {
                uint32_t bh[4], bl[4];
                ldsm4(bh, shWh + boff + p * 2304 + kb * 32);
                ldsm4(bl, shWl + boff + p * 2304 + kb * 32);
                mma16816(c[2 * p],     ah[0], ah[1], ah[2], ah[3], bh[0], bh[1]);
                mma16816(c[2 * p],     ah[0], ah[1], ah[2], ah[3], bl[0], bl[1]);
                mma16816(c[2 * p],     al[0], al[1], al[2], al[3], bh[0], bh[1]);
                mma16816(c[2 * p + 1], ah[0], ah[1], ah[2], ah[3], bh[2], bh[3]);
                mma16816(c[2 * p + 1], ah[0], ah[1], ah[2], ah[3], bl[2], bl[3]);
                mma16816(c[2 * p + 1], al[0], al[1], al[2], al[3], bh[2], bh[3]);
            }
        }
    }

    const int r0 = bm + 16 * w + g, r1 = r0 + 8;
    size_t gr0, gr1;
    if (MODE == 0) { gr0 = g_sortpos[r0]; gr1 = g_sortpos[r1]; }
    else           { gr0 = r0;            gr1 = r1; }
    #pragma unroll
    for (int nb = 0; nb < 8; nb++) {
        const int col = bn + 8 * nb + 2 * tq;
        float b0 = __ldg(bias + col), b1 = __ldg(bias + col + 1);
        float v0 = c[nb][0] + b0, v1 = c[nb][1] + b1;
        float v2 = c[nb][2] + b0, v3 = c[nb][3] + b1;
        if (MODE == 2) {
            *(float2*)&Cf[gr0 * ldc + col] = make_float2(v0, v1);
            *(float2*)&Cf[gr1 * ldc + col] = make_float2(v2, v3);
        } else {
            uint32_t h0, l0, h1, l1;
            split2(v0, v1, h0, l0);
            split2(v2, v3, h1, l1);
            *(uint32_t*)&Ch[gr0 * ldc + col] = h0;
            *(uint32_t*)&Cl[gr0 * ldc + col] = l0;
            *(uint32_t*)&Ch[gr1 * ldc + col] = h1;
            *(uint32_t*)&Cl[gr1 * ldc + col] = l1;
        }
    }
}

// ---------------- V transpose: sorted qkv v-part -> [head][d][key] --------------
__global__ __launch_bounds__(128)
void vt_transpose_kernel() {
    __shared__ __align__(16) __nv_bfloat16 th[64 * 72], tl[64 * 72];
    const int t = threadIdx.x;
    const int rb = blockIdx.x * 64, h = blockIdx.y;
    const int lrow = t >> 1, lhalf = (t & 1) * 32;
    const size_t src = (size_t)(rb + lrow) * QKVLD + 1024 + h * 64 + lhalf;
    #pragma unroll
    for (int j = 0; j < 4; j++) {
        *(uint4*)&th[lrow * 72 + lhalf + j * 8] = *(const uint4*)(g_qkvh + src + j * 8);
        *(uint4*)&tl[lrow * 72 + lhalf + j * 8] = *(const uint4*)(g_qkvl + src + j * 8);
    }
    __syncthreads();
    const int d = t >> 1, kh = (t & 1) * 32;
    __nv_bfloat16* dh = g_vth + (size_t)(h * 64 + d) * NROWS + rb;
    __nv_bfloat16* dl = g_vtl + (size_t)(h * 64 + d) * NROWS + rb;
    #pragma unroll
    for (int j = 0; j < 16; j++) {
        int sr = kh + 2 * j;
        __nv_bfloat162 a, b;
        a.x = th[sr * 72 + d]; a.y = th[(sr + 1) * 72 + d];
        b.x = tl[sr * 72 + d]; b.y = tl[(sr + 1) * 72 + d];
        *(__nv_bfloat162*)(dh + sr) = a;
        *(__nv_bfloat162*)(dl + sr) = b;
    }
}

// ---------------- tensor-core flash attention (sorted space, ldmatrix) ----------
__global__ __launch_bounds__(128)
void attn_kernel() {
    extern __shared__ __align__(16) unsigned char smraw[];
    __nv_bfloat16* Qh = (__nv_bfloat16*)smraw;
    __nv_bfloat16* Ql = Qh + 1 * 4608;
    __nv_bfloat16* Kh = Qh + 2 * 4608;
    __nv_bfloat16* Kl = Qh + 3 * 4608;
    __nv_bfloat16* Th = Qh + 4 * 4608;
    __nv_bfloat16* Tl = Qh + 5 * 4608;
    int* sks = (int*)(smraw + 6 * 4608 * 2);

    const int qt = blockIdx.x, h = blockIdx.y;
    const int qb = qt * 64;
    const int t = threadIdx.x, w = t >> 5, lane = t & 31, g = lane >> 2, tq = lane & 3;
    const int lrow = t >> 1, lhalf = (t & 1) * 32;

    const uint32_t shQh = (uint32_t)__cvta_generic_to_shared(Qh);
    const uint32_t shQl = (uint32_t)__cvta_generic_to_shared(Ql);
    const uint32_t shKh = (uint32_t)__cvta_generic_to_shared(Kh);
    const uint32_t shKl = (uint32_t)__cvta_generic_to_shared(Kl);
    const uint32_t shTh = (uint32_t)__cvta_generic_to_shared(Th);
    const uint32_t shTl = (uint32_t)__cvta_generic_to_shared(Tl);

    const int lr  = lane & 7;
    const int sel = lane >> 3;
    const uint32_t aoff = (uint32_t)(((16 * w + (sel & 1) * 8 + lr) * 72 + (sel >> 1) * 8) * 2);
    const uint32_t boff = (uint32_t)((((sel >> 1) * 8 + lr) * 72 + (sel & 1) * 8) * 2);

    // stage Q
    {
        const size_t src = (size_t)(qb + lrow) * QKVLD + h * 64 + lhalf;
        #pragma unroll
        for (int j = 0; j < 4; j++) {
            *(uint4*)&Qh[lrow * 72 + lhalf + j * 8] = *(const uint4*)(g_qkvh + src + j * 8);
            *(uint4*)&Ql[lrow * 72 + lhalf + j * 8] = *(const uint4*)(g_qkvl + src + j * 8);
        }
    }
    const int sq_a = g_ssteps[qb + 16 * w + g];
    const int sq_b = g_ssteps[qb + 16 * w + g + 8];
    __syncthreads();

    // register-resident Q fragments for the whole block
    uint32_t qfh[4][4], qfl[4][4];
    #pragma unroll
    for (int kb = 0; kb < 4; kb++) {
        ldsm4(qfh[kb], shQh + aoff + kb * 32);
        ldsm4(qfl[kb], shQl + aoff + kb * 32);
    }

    float o[8][4];
    #pragma unroll
    for (int i = 0; i < 8; i++)
        #pragma unroll
        for (int j = 0; j < 4; j++) o[i][j] = 0.f;
    float ps_a = 0.f, ps_b = 0.f;

    for (int kt = g_kstart[qt]; kt < 64; kt++) {
        const int kb64 = kt * 64;
        __syncthreads();
        {
            const size_t ks = (size_t)(kb64 + lrow) * QKVLD + 512 + h * 64 + lhalf;
            const size_t vs = (size_t)(h * 64 + lrow) * NROWS + kb64 + lhalf;
            #pragma unroll
            for (int j = 0; j < 4; j++) {
                *(uint4*)&Kh[lrow * 72 + lhalf + j * 8] = *(const uint4*)(g_qkvh + ks + j * 8);
                *(uint4*)&Kl[lrow * 72 + lhalf + j * 8] = *(const uint4*)(g_qkvl + ks + j * 8);
                *(uint4*)&Th[lrow * 72 + lhalf + j * 8] = *(const uint4*)(g_vth  + vs + j * 8);
                *(uint4*)&Tl[lrow * 72 + lhalf + j * 8] = *(const uint4*)(g_vtl  + vs + j * 8);
            }
            if (t < 64) sks[t] = g_ssteps[kb64 + t];
        }
        __syncthreads();

        // S = Q K^T
        float s[8][4];
        #pragma unroll
        for (int i = 0; i < 8; i++)
            #pragma unroll
            for (int j = 0; j < 4; j++) s[i][j] = 0.f;
        #pragma unroll
        for (int kb = 0; kb < 4; kb++) {
            #pragma unroll
            for (int p = 0; p < 4; p++) {
                uint32_t bh[4], bl[4];
                ldsm4(bh, shKh + boff + p * 2304 + kb * 32);
                ldsm4(bl, shKl + boff + p * 2304 + kb * 32);
                mma16816(s[2 * p],     qfh[kb][0], qfh[kb][1], qfh[kb][2], qfh[kb][3], bh[0], bh[1]);
                mma16816(s[2 * p],     qfh[kb][0], qfh[kb][1], qfh[kb][2], qfh[kb][3], bl[0], bl[1]);
                mma16816(s[2 * p],     qfl[kb][0], qfl[kb][1], qfl[kb][2], qfl[kb][3], bh[0], bh[1]);
                mma16816(s[2 * p + 1], qfh[kb][0], qfh[kb][1], qfh[kb][2], qfh[kb][3], bh[2], bh[3]);
                mma16816(s[2 * p + 1], qfh[kb][0], qfh[kb][1], qfh[kb][2], qfh[kb][3], bl[2], bl[3]);
                mma16816(s[2 * p + 1], qfl[kb][0], qfl[kb][1], qfl[kb][2], qfl[kb][3], bh[2], bh[3]);
            }
        }

        // softmax (fixed shift) + mask; P A-frags built in registers
        uint32_t pah[16], pal[16];
        #pragma unroll
        for (int nb = 0; nb < 8; nb++) {
            int2 kk = *(const int2*)&sks[8 * nb + 2 * tq];
            float p0 = __expf(s[nb][0] * 0.125f); if (kk.x < sq_a) p0 = 0.f;
            float p1 = __expf(s[nb][1] * 0.125f); if (kk.y < sq_a) p1 = 0.f;
            float p2 = __expf(s[nb][2] * 0.125f); if (kk.x < sq_b) p2 = 0.f;
            float p3 = __expf(s[nb][3] * 0.125f); if (kk.y < sq_b) p3 = 0.f;
            ps_a += p0 + p1;
            ps_b += p2 + p3;
            split2(p0, p1, pah[2 * nb],     pal[2 * nb]);
            split2(p2, p3, pah[2 * nb + 1], pal[2 * nb + 1]);
        }

        // O += P @ V
        #pragma unroll
        for (int kb = 0; kb < 4; kb++) {
            uint32_t a0h = pah[4 * kb],     a1h = pah[4 * kb + 1];
            uint32_t a2h = pah[4 * kb + 2], a3h = pah[4 * kb + 3];
            uint32_t a0l = pal[4 * kb],     a1l = pal[4 * kb + 1];
            uint32_t a2l = pal[4 * kb + 2], a3l = pal[4 * kb + 3];
            #pragma unroll
            for (int p = 0; p < 4; p++) {
                uint32_t bh[4], bl[4];
                ldsm4(bh, shTh + boff + p * 2304 + kb * 32);
                ldsm4(bl, shTl + boff + p * 2304 + kb * 32);
                mma16816(o[2 * p],     a0h, a1h, a2h, a3h, bh[0], bh[1]);
                mma16816(o[2 * p],     a0h, a1h, a2h, a3h, bl[0], bl[1]);
                mma16816(o[2 * p],     a0l, a1l, a2l, a3l, bh[0], bh[1]);
                mma16816(o[2 * p + 1], a0h, a1h, a2h, a3h, bh[2], bh[3]);
                mma16816(o[2 * p + 1], a0h, a1h, a2h, a3h, bl[2], bl[3]);
                mma16816(o[2 * p + 1], a0l, a1l, a2l, a3l, bh[2], bh[3]);
            }
        }
    }

    ps_a += __shfl_xor_sync(0xffffffffu, ps_a, 1);
    ps_a += __shfl_xor_sync(0xffffffffu, ps_a, 2);
    ps_b += __shfl_xor_sync(0xffffffffu, ps_b, 1);
    ps_b += __shfl_xor_sync(0xffffffffu, ps_b, 2);
    const float inv_a = 1.f / ps_a, inv_b = 1.f / ps_b;
    const size_t r0 = qb + 16 * w + g, r1 = r0 + 8;
    #pragma unroll
    for (int nb = 0; nb < 8; nb++) {
        const int col = h * 64 + 8 * nb + 2 * tq;
        uint32_t h0, l0, h1, l1;
        split2(o[nb][0] * inv_a, o[nb][1] * inv_a, h0, l0);
        split2(o[nb][2] * inv_b, o[nb][3] * inv_b, h1, l1);
        *(uint32_t*)&g_ctxh[r0 * EDIM + col] = h0;
        *(uint32_t*)&g_ctxl[r0 * EDIM + col] = l0;
        *(uint32_t*)&g_ctxh[r1 * EDIM + col] = h1;
        *(uint32_t*)&g_ctxl[r1 * EDIM + col] = l1;
    }
}

// ---------------- fill comb cols 512..895 (sorted rows, hi/lo) ------------------
__global__ void fill_comb_kernel(const int* __restrict__ dmask,
                                 const int* __restrict__ steps,
                                 const float* __restrict__ status) {
    const int r = blockIdx.x;
    __shared__ int so;
    if (threadIdx.x == 0) so = g_perm[r];
    __syncthreads();
    const int col = 2 * threadIdx.x;           // 0..382
    float v0, v1;
    if (col < 128) {
        int dm = dmask[so];
        v0 = status[dm * 128 + col];
        v1 = status[dm * 128 + col + 1];
    } else {
        int sc = steps[so];
        sc = sc < 0 ? 0 : (sc > 99 ? 99 : sc);
        v0 = g_te[sc * 256 + col - 128];
        v1 = g_te[sc * 256 + col - 127];
    }
    uint32_t hw, lw;
    split2(v0, v1, hw, lw);
    *(uint32_t*)&g_combh[(size_t)r * 896 + 512 + col] = hw;
    *(uint32_t*)&g_combl[(size_t)r * 896 + 512 + col] = lw;
}

// ---------------- LayerNorm -> ReLU -> residual (un-permute) --------------------
__global__ void ln_relu_res_kernel(const float* __restrict__ x,
                                   const float* __restrict__ gamma,
                                   const float* __restrict__ beta,
                                   float* __restrict__ out) {
    const int r = blockIdx.x;
    const int t = threadIdx.x;
    __shared__ float sh[8];
    __shared__ float stat[2];
    __shared__ int so;
    if (t == 0) so = g_perm[r];

    const float* hr = g_h + (size_t)r * EDIM;
    float v0 = hr[t], v1 = hr[t + 256];

    float s = v0 + v1;
    #pragma unroll
    for (int o2 = 16; o2; o2 >>= 1) s += __shfl_xor_sync(0xffffffffu, s, o2);
    if ((t & 31) == 0) sh[t >> 5] = s;
    __syncthreads();
    if (t == 0) {
        float tot = 0.f;
        #pragma unroll
        for (int i = 0; i < 8; i++) tot += sh[i];
        stat[0] = tot * (1.f / 512.f);
    }
    __syncthreads();
    float mu = stat[0];
    float d0 = v0 - mu, d1 = v1 - mu;
    float vv = d0 * d0 + d1 * d1;
    #pragma unroll
    for (int o2 = 16; o2; o2 >>= 1) vv += __shfl_xor_sync(0xffffffffu, vv, o2);
    if ((t & 31) == 0) sh[t >> 5] = vv;
    __syncthreads();
    if (t == 0) {
        float tot = 0.f;
        #pragma unroll
        for (int i = 0; i < 8; i++) tot += sh[i];
        stat[1] = 1.f / sqrtf(tot * (1.f / 512.f) + 1e-5f);
    }
    __syncthreads();
    float inv = stat[1];

    float y0 = fmaxf(d0 * inv * gamma[t]       + beta[t],       0.f);
    float y1 = fmaxf(d1 * inv * gamma[t + 256] + beta[t + 256], 0.f);
    const size_t orow = so;
    out[orow * EDIM + t]       = x[orow * EDIM + t]       + y0;
    out[orow * EDIM + t + 256] = x[orow * EDIM + t + 256] + y1;
}

// ---------------- launch ---------------------------------------------------------
extern "C" void kernel_launch(void* const* d_in, const int* in_sizes, int n_in,
                              void* d_out, int out_size) {
    const float* x      = (const float*)d_in[0];
    const int*   dmask  = (const int*)  d_in[1];
    const int*   steps  = (const int*)  d_in[2];
    const float* status = (const float*)d_in[3];
    const float* wqkv   = (const float*)d_in[4];
    const float* bqkv   = (const float*)d_in[5];
    const float* wout   = (const float*)d_in[6];
    const float* bout   = (const float*)d_in[7];
    const float* wmlp   = (const float*)d_in[8];
    const float* bmlp   = (const float*)d_in[9];
    const float* gamma  = (const float*)d_in[10];
    const float* beta   = (const float*)d_in[11];
    float* out = (float*)d_out;

    __nv_bfloat16 *xh, *xl, *wqh, *wql, *woh, *wol, *wmh, *wml;
    __nv_bfloat16 *qkvh, *qkvl, *ctxh, *ctxl, *combh, *combl;
    float* hbuf;
    cudaGetSymbolAddress((void**)&xh,    g_xh);
    cudaGetSymbolAddress((void**)&xl,    g_xl);
    cudaGetSymbolAddress((void**)&wqh,   g_wqkvh);
    cudaGetSymbolAddress((void**)&wql,   g_wqkvl);
    cudaGetSymbolAddress((void**)&woh,   g_wouth);
    cudaGetSymbolAddress((void**)&wol,   g_woutl);
    cudaGetSymbolAddress((void**)&wmh,   g_wmlph);
    cudaGetSymbolAddress((void**)&wml,   g_wmlpl);
    cudaGetSymbolAddress((void**)&qkvh,  g_qkvh);
    cudaGetSymbolAddress((void**)&qkvl,  g_qkvl);
    cudaGetSymbolAddress((void**)&ctxh,  g_ctxh);
    cudaGetSymbolAddress((void**)&ctxl,  g_ctxl);
    cudaGetSymbolAddress((void**)&combh, g_combh);
    cudaGetSymbolAddress((void**)&combl, g_combl);
    cudaGetSymbolAddress((void**)&hbuf,  g_h);

    const int attn_smem = 6 * 4608 * 2 + 64 * 4;   // 55552
    cudaFuncSetAttribute(attn_kernel, cudaFuncAttributeMaxDynamicSharedMemorySize,
                         attn_smem);

    sort_kernel<<<1, 128>>>(steps);
    build_te_kernel<<<50, 256>>>();

    cvt_split_kernel<<<(NROWS * EDIM / 2 + 255) / 256, 256>>>(x,    xh,  xl,  NROWS * EDIM);
    cvt_split_kernel<<<(QKVLD * EDIM / 2 + 255) / 256, 256>>>(wqkv, wqh, wql, QKVLD * EDIM);
    cvt_split_kernel<<<(EDIM * EDIM / 2 + 255) / 256, 256>>>(wout, woh, wol, EDIM * EDIM);
    cvt_split_kernel<<<(EDIM * 896 / 2 + 255) / 256, 256>>>(wmlp, wmh, wml, EDIM * 896);

    mma_gemm<0><<<dim3(24, 64), 128>>>(xh, xl, EDIM, wqh, wql, bqkv, EDIM,
                                       nullptr, qkvh, qkvl, QKVLD);

    vt_transpose_kernel<<<dim3(64, 8), 128>>>();

    attn_kernel<<<dim3(64, 8), 128, attn_smem>>>();

    mma_gemm<1><<<dim3(8, 64), 128>>>(ctxh, ctxl, EDIM, woh, wol, bout, EDIM,
                                      nullptr, combh, combl, 896);

    fill_comb_kernel<<<4096, 192>>>(dmask, steps, status);

    mma_gemm<2><<<dim3(8, 64), 128>>>(combh, combl, 896, wmh, wml, bmlp, 896,
                                      hbuf, nullptr, nullptr, EDIM);

    ln_relu_res_kernel<<<4096, 256>>>(x, gamma, beta, out);
}

// round 8
// speedup vs baseline: 2.4451x; 1.0808x over previous
#include <cuda_runtime.h>
#include <cuda_bf16.h>
#include <math.h>
#include <stdint.h>

#define NROWS  4096
#define EDIM   512
#define QKVLD  1536
#define SPLITS 4

// ---------------- device scratch (no allocations allowed) -------------------
__device__ float g_te[100 * 256];
__device__ int   g_perm[NROWS], g_sortpos[NROWS], g_ssteps[NROWS], g_kstart[64];

__device__ __align__(16) __nv_bfloat16 g_xh   [NROWS * EDIM],  g_xl   [NROWS * EDIM];
__device__ __align__(16) __nv_bfloat16 g_wqkvh[QKVLD * EDIM],  g_wqkvl[QKVLD * EDIM];
__device__ __align__(16) __nv_bfloat16 g_wouth[EDIM * EDIM],   g_woutl[EDIM * EDIM];
__device__ __align__(16) __nv_bfloat16 g_wmlph[EDIM * 896],    g_wmlpl[EDIM * 896];
__device__ __align__(16) __nv_bfloat16 g_qkvh [NROWS * QKVLD], g_qkvl [NROWS * QKVLD];
__device__ __align__(16) __nv_bfloat16 g_vth  [EDIM * NROWS],  g_vtl  [EDIM * NROWS];
__device__ __align__(16) __nv_bfloat16 g_ctxh [NROWS * EDIM],  g_ctxl [NROWS * EDIM];
__device__ __align__(16) __nv_bfloat16 g_combh[NROWS * 896],   g_combl[NROWS * 896];
__device__ float g_h[NROWS * EDIM];
__device__ float g_part[(size_t)SPLITS * NROWS * EDIM];   // unnormalized partial O
__device__ float g_psum[SPLITS * 8 * NROWS];              // partial row sums per head

// ---------------- helpers ----------------------------------------------------
__device__ __forceinline__ void mma16816(float* c,
    uint32_t a0, uint32_t a1, uint32_t a2, uint32_t a3,
    uint32_t b0, uint32_t b1) {
    asm volatile(
        "mma.sync.aligned.m16n8k16.row.col.f32.bf16.bf16.f32 "
        "{%0,%1,%2,%3},{%4,%5,%6,%7},{%8,%9},{%0,%1,%2,%3};"
        : "+f"(c[0]), "+f"(c[1]), "+f"(c[2]), "+f"(c[3])
        : "r"(a0), "r"(a1), "r"(a2), "r"(a3), "r"(b0), "r"(b1));
}

__device__ __forceinline__ void ldsm4(uint32_t* r, uint32_t addr) {
    asm volatile("ldmatrix.sync.aligned.m8n8.x4.shared.b16 {%0,%1,%2,%3}, [%4];"
        : "=r"(r[0]), "=r"(r[1]), "=r"(r[2]), "=r"(r[3]) : "r"(addr));
}

__device__ __forceinline__ void split2(float v0, float v1, uint32_t& hi, uint32_t& lo) {
    __nv_bfloat162 h = __floats2bfloat162_rn(v0, v1);
    float r0 = v0 - __bfloat162float(h.x);
    float r1 = v1 - __bfloat162float(h.y);
    __nv_bfloat162 l = __floats2bfloat162_rn(r0, r1);
    hi = *reinterpret_cast<uint32_t*>(&h);
    lo = *reinterpret_cast<uint32_t*>(&l);
}

__device__ __forceinline__ uint32_t pack_bf162(float v0, float v1) {
    __nv_bfloat162 h = __floats2bfloat162_rn(v0, v1);
    return *reinterpret_cast<uint32_t*>(&h);
}

// ---------------- time table ---------------------------------------------------
__global__ void build_te_kernel() {
    int t = blockIdx.x * blockDim.x + threadIdx.x;
    if (t >= 100 * 128) return;
    int p = t >> 7;
    int k = t & 127;
    double div = exp(-((double)(2 * k)) * log(10000.0) / 256.0);
    double ang = (double)p * div;
    g_te[p * 256 + 2 * k]     = (float)sin(ang);
    g_te[p * 256 + 2 * k + 1] = (float)cos(ang);
}

// ---------------- deterministic stable sort by step ----------------------------
__global__ void sort_kernel(const int* __restrict__ steps) {
    __shared__ int s_steps[NROWS];
    __shared__ int hist[100];
    __shared__ int base[100];
    const int t = threadIdx.x;

    for (int i = t; i < 100; i += 128) hist[i] = 0;
    __syncthreads();
    for (int i = t; i < NROWS; i += 128) {
        int s = steps[i];
        s = s < 0 ? 0 : (s > 99 ? 99 : s);
        s_steps[i] = s;
        atomicAdd(&hist[s], 1);
    }
    __syncthreads();
    if (t == 0) {
        int acc = 0;
        for (int b = 0; b < 100; b++) { base[b] = acc; acc += hist[b]; }
    }
    __syncthreads();
    if (t < 100) {
        int r = base[t];
        for (int i = 0; i < NROWS; i++) {
            if (s_steps[i] == t) {
                g_perm[r] = i;
                g_sortpos[i] = r;
                g_ssteps[r] = t;
                r++;
            }
        }
    }
    __syncthreads();
    if (t < 64) {
        int qmin = g_ssteps[t * 64];
        int ks = 0;
        while (ks < 64 && g_ssteps[ks * 64 + 63] < qmin) ks++;
        g_kstart[t] = ks;
    }
}

// ---------------- fp32 -> bf16 hi/lo split -------------------------------------
__global__ void cvt_split_kernel(const float* __restrict__ src,
                                 __nv_bfloat16* __restrict__ h,
                                 __nv_bfloat16* __restrict__ l, int n) {
    int i = (blockIdx.x * blockDim.x + threadIdx.x) * 2;
    if (i >= n) return;
    float2 v = *(const float2*)(src + i);
    uint32_t hw, lw;
    split2(v.x, v.y, hw, lw);
    *(uint32_t*)(h + i) = hw;
    *(uint32_t*)(l + i) = lw;
}

// ---------------- split-bf16 tensor GEMM (ldmatrix fragments) -------------------
template<int MODE>
__global__ __launch_bounds__(128)
void mma_gemm(const __nv_bfloat16* __restrict__ Ah, const __nv_bfloat16* __restrict__ Al,
              int lda,
              const __nv_bfloat16* __restrict__ Wh, const __nv_bfloat16* __restrict__ Wl,
              const float* __restrict__ bias, int K,
              float* __restrict__ Cf,
              __nv_bfloat16* __restrict__ Ch, __nv_bfloat16* __restrict__ Cl, int ldc) {
    __shared__ __align__(16) __nv_bfloat16 sA[2][64 * 72];
    __shared__ __align__(16) __nv_bfloat16 sW[2][64 * 72];
    const int t = threadIdx.x;
    const int w = t >> 5, lane = t & 31, g = lane >> 2, tq = lane & 3;
    const int bm = blockIdx.y * 64, bn = blockIdx.x * 64;
    const int lrow = t >> 1, lhalf = (t & 1) * 32;

    const uint32_t shAh = (uint32_t)__cvta_generic_to_shared(&sA[0][0]);
    const uint32_t shAl = (uint32_t)__cvta_generic_to_shared(&sA[1][0]);
    const uint32_t shWh = (uint32_t)__cvta_generic_to_shared(&sW[0][0]);
    const uint32_t shWl = (uint32_t)__cvta_generic_to_shared(&sW[1][0]);

    const int lr  = lane & 7;
    const int sel = lane >> 3;
    const uint32_t aoff = (uint32_t)(((16 * w + (sel & 1) * 8 + lr) * 72 + (sel >> 1) * 8) * 2);
    const uint32_t boff = (uint32_t)((((sel >> 1) * 8 + lr) * 72 + (sel & 1) * 8) * 2);

    float c[8][4];
    #pragma unroll
    for (int i = 0; i < 8; i++)
        #pragma unroll
        for (int j = 0; j < 4; j++) c[i][j] = 0.f;

    for (int k0 = 0; k0 < K; k0 += 64) {
        __syncthreads();
        const size_t ao = (size_t)(bm + lrow) * lda + k0 + lhalf;
        const size_t wo = (size_t)(bn + lrow) * K   + k0 + lhalf;
        #pragma unroll
        for (int j = 0; j < 4; j++) {
            *(uint4*)&sA[0][lrow * 72 + lhalf + j * 8] = *(const uint4*)(Ah + ao + j * 8);
            *(uint4*)&sA[1][lrow * 72 + lhalf + j * 8] = *(const uint4*)(Al + ao + j * 8);
            *(uint4*)&sW[0][lrow * 72 + lhalf + j * 8] = *(const uint4*)(Wh + wo + j * 8);
            *(uint4*)&sW[1][lrow * 72 + lhalf + j * 8] = *(const uint4*)(Wl + wo + j * 8);
        }
        __syncthreads();
        #pragma unroll
        for (int kb = 0; kb < 4; kb++) {
            uint32_t ah[4], al[4];
            ldsm4(ah, shAh + aoff + kb * 32);
            ldsm4(al, shAl + aoff + kb * 32);
            #pragma unroll
            for (int p = 0; p < 4; p++) {
                uint32_t bh[4], bl[4];
                ldsm4(bh, shWh + boff + p * 2304 + kb * 32);
                ldsm4(bl, shWl + boff + p * 2304 + kb * 32);
                mma16816(c[2 * p],     ah[0], ah[1], ah[2], ah[3], bh[0], bh[1]);
                mma16816(c[2 * p],     ah[0], ah[1], ah[2], ah[3], bl[0], bl[1]);
                mma16816(c[2 * p],     al[0], al[1], al[2], al[3], bh[0], bh[1]);
                mma16816(c[2 * p + 1], ah[0], ah[1], ah[2], ah[3], bh[2], bh[3]);
                mma16816(c[2 * p + 1], ah[0], ah[1], ah[2], ah[3], bl[2], bl[3]);
                mma16816(c[2 * p + 1], al[0], al[1], al[2], al[3], bh[2], bh[3]);
            }
        }
    }

    const int r0 = bm + 16 * w + g, r1 = r0 + 8;
    size_t gr0, gr1;
    if (MODE == 0) { gr0 = g_sortpos[r0]; gr1 = g_sortpos[r1]; }
    else           { gr0 = r0;            gr1 = r1; }
    #pragma unroll
    for (int nb = 0; nb < 8; nb++) {
        const int col = bn + 8 * nb + 2 * tq;
        float b0 = __ldg(bias + col), b1 = __ldg(bias + col + 1);
        float v0 = c[nb][0] + b0, v1 = c[nb][1] + b1;
        float v2 = c[nb][2] + b0, v3 = c[nb][3] + b1;
        if (MODE == 2) {
            *(float2*)&Cf[gr0 * ldc + col] = make_float2(v0, v1);
            *(float2*)&Cf[gr1 * ldc + col] = make_float2(v2, v3);
        } else {
            uint32_t h0, l0, h1, l1;
            split2(v0, v1, h0, l0);
            split2(v2, v3, h1, l1);
            *(uint32_t*)&Ch[gr0 * ldc + col] = h0;
            *(uint32_t*)&Cl[gr0 * ldc + col] = l0;
            *(uint32_t*)&Ch[gr1 * ldc + col] = h1;
            *(uint32_t*)&Cl[gr1 * ldc + col] = l1;
        }
    }
}

// ---------------- V transpose: sorted qkv v-part -> [head][d][key] --------------
__global__ __launch_bounds__(128)
void vt_transpose_kernel() {
    __shared__ __align__(16) __nv_bfloat16 th[64 * 72], tl[64 * 72];
    const int t = threadIdx.x;
    const int rb = blockIdx.x * 64, h = blockIdx.y;
    const int lrow = t >> 1, lhalf = (t & 1) * 32;
    const size_t src = (size_t)(rb + lrow) * QKVLD + 1024 + h * 64 + lhalf;
    #pragma unroll
    for (int j = 0; j < 4; j++) {
        *(uint4*)&th[lrow * 72 + lhalf + j * 8] = *(const uint4*)(g_qkvh + src + j * 8);
        *(uint4*)&tl[lrow * 72 + lhalf + j * 8] = *(const uint4*)(g_qkvl + src + j * 8);
    }
    __syncthreads();
    const int d = t >> 1, kh = (t & 1) * 32;
    __nv_bfloat16* dh = g_vth + (size_t)(h * 64 + d) * NROWS + rb;
    __nv_bfloat16* dl = g_vtl + (size_t)(h * 64 + d) * NROWS + rb;
    #pragma unroll
    for (int j = 0; j < 16; j++) {
        int sr = kh + 2 * j;
        __nv_bfloat162 a, b;
        a.x = th[sr * 72 + d]; a.y = th[(sr + 1) * 72 + d];
        b.x = tl[sr * 72 + d]; b.y = tl[(sr + 1) * 72 + d];
        *(__nv_bfloat162*)(dh + sr) = a;
        *(__nv_bfloat162*)(dl + sr) = b;
    }
}

// ---------------- tensor-core flash attention, KV-split ------------------------
__global__ __launch_bounds__(128)
void attn_kernel() {
    extern __shared__ __align__(16) unsigned char smraw[];
    __nv_bfloat16* Qh = (__nv_bfloat16*)smraw;
    __nv_bfloat16* Ql = Qh + 1 * 4608;
    __nv_bfloat16* Kh = Qh + 2 * 4608;
    __nv_bfloat16* Kl = Qh + 3 * 4608;
    __nv_bfloat16* Th = Qh + 4 * 4608;
    __nv_bfloat16* Tl = Qh + 5 * 4608;
    int* sks = (int*)(smraw + 6 * 4608 * 2);

    const int qt = blockIdx.x, h = blockIdx.y, sp = blockIdx.z;
    const int qb = qt * 64;
    const int t = threadIdx.x, w = t >> 5, lane = t & 31, g = lane >> 2, tq = lane & 3;
    const int lrow = t >> 1, lhalf = (t & 1) * 32;

    const uint32_t shQh = (uint32_t)__cvta_generic_to_shared(Qh);
    const uint32_t shQl = (uint32_t)__cvta_generic_to_shared(Ql);
    const uint32_t shKh = (uint32_t)__cvta_generic_to_shared(Kh);
    const uint32_t shKl = (uint32_t)__cvta_generic_to_shared(Kl);
    const uint32_t shTh = (uint32_t)__cvta_generic_to_shared(Th);
    const uint32_t shTl = (uint32_t)__cvta_generic_to_shared(Tl);

    const int lr  = lane & 7;
    const int sel = lane >> 3;
    const uint32_t aoff = (uint32_t)(((16 * w + (sel & 1) * 8 + lr) * 72 + (sel >> 1) * 8) * 2);
    const uint32_t boff = (uint32_t)((((sel >> 1) * 8 + lr) * 72 + (sel & 1) * 8) * 2);

    // stage Q
    {
        const size_t src = (size_t)(qb + lrow) * QKVLD + h * 64 + lhalf;
        #pragma unroll
        for (int j = 0; j < 4; j++) {
            *(uint4*)&Qh[lrow * 72 + lhalf + j * 8] = *(const uint4*)(g_qkvh + src + j * 8);
            *(uint4*)&Ql[lrow * 72 + lhalf + j * 8] = *(const uint4*)(g_qkvl + src + j * 8);
        }
    }
    const int sq_a = g_ssteps[qb + 16 * w + g];
    const int sq_b = g_ssteps[qb + 16 * w + g + 8];
    __syncthreads();

    uint32_t qfh[4][4], qfl[4][4];
    #pragma unroll
    for (int kb = 0; kb < 4; kb++) {
        ldsm4(qfh[kb], shQh + aoff + kb * 32);
        ldsm4(qfl[kb], shQl + aoff + kb * 32);
    }

    float o[8][4];
    #pragma unroll
    for (int i = 0; i < 8; i++)
        #pragma unroll
        for (int j = 0; j < 4; j++) o[i][j] = 0.f;
    float ps_a = 0.f, ps_b = 0.f;

    const int ks0 = g_kstart[qt];
    const int len = (64 - ks0 + SPLITS - 1) / SPLITS;
    const int k0  = ks0 + sp * len;
    const int k1  = (k0 + len < 64) ? (k0 + len) : 64;

    for (int kt = k0; kt < k1; kt++) {
        const int kb64 = kt * 64;
        __syncthreads();
        {
            const size_t ks = (size_t)(kb64 + lrow) * QKVLD + 512 + h * 64 + lhalf;
            const size_t vs = (size_t)(h * 64 + lrow) * NROWS + kb64 + lhalf;
            #pragma unroll
            for (int j = 0; j < 4; j++) {
                *(uint4*)&Kh[lrow * 72 + lhalf + j * 8] = *(const uint4*)(g_qkvh + ks + j * 8);
                *(uint4*)&Kl[lrow * 72 + lhalf + j * 8] = *(const uint4*)(g_qkvl + ks + j * 8);
                *(uint4*)&Th[lrow * 72 + lhalf + j * 8] = *(const uint4*)(g_vth  + vs + j * 8);
                *(uint4*)&Tl[lrow * 72 + lhalf + j * 8] = *(const uint4*)(g_vtl  + vs + j * 8);
            }
            if (t < 64) sks[t] = g_ssteps[kb64 + t];
        }
        __syncthreads();

        // S = Q K^T (full 3-term split)
        float s[8][4];
        #pragma unroll
        for (int i = 0; i < 8; i++)
            #pragma unroll
            for (int j = 0; j < 4; j++) s[i][j] = 0.f;
        #pragma unroll
        for (int kb = 0; kb < 4; kb++) {
            #pragma unroll
            for (int p = 0; p < 4; p++) {
                uint32_t bh[4], bl[4];
                ldsm4(bh, shKh + boff + p * 2304 + kb * 32);
                ldsm4(bl, shKl + boff + p * 2304 + kb * 32);
                mma16816(s[2 * p],     qfh[kb][0], qfh[kb][1], qfh[kb][2], qfh[kb][3], bh[0], bh[1]);
                mma16816(s[2 * p],     qfh[kb][0], qfh[kb][1], qfh[kb][2], qfh[kb][3], bl[0], bl[1]);
                mma16816(s[2 * p],     qfl[kb][0], qfl[kb][1], qfl[kb][2], qfl[kb][3], bh[0], bh[1]);
                mma16816(s[2 * p + 1], qfh[kb][0], qfh[kb][1], qfh[kb][2], qfh[kb][3], bh[2], bh[3]);
                mma16816(s[2 * p + 1], qfh[kb][0], qfh[kb][1], qfh[kb][2], qfh[kb][3], bl[2], bl[3]);
                mma16816(s[2 * p + 1], qfl[kb][0], qfl[kb][1], qfl[kb][2], qfl[kb][3], bh[2], bh[3]);
            }
        }

        // softmax (fixed shift) + mask; P hi-only A-frags (exact p in row sums)
        uint32_t pah[16];
        #pragma unroll
        for (int nb = 0; nb < 8; nb++) {
            int2 kk = *(const int2*)&sks[8 * nb + 2 * tq];
            float p0 = __expf(s[nb][0] * 0.125f); if (kk.x < sq_a) p0 = 0.f;
            float p1 = __expf(s[nb][1] * 0.125f); if (kk.y < sq_a) p1 = 0.f;
            float p2 = __expf(s[nb][2] * 0.125f); if (kk.x < sq_b) p2 = 0.f;
            float p3 = __expf(s[nb][3] * 0.125f); if (kk.y < sq_b) p3 = 0.f;
            ps_a += p0 + p1;
            ps_b += p2 + p3;
            pah[2 * nb]     = pack_bf162(p0, p1);
            pah[2 * nb + 1] = pack_bf162(p2, p3);
        }

        // O += P @ V   (P hi-only; V split 2-term)
        #pragma unroll
        for (int kb = 0; kb < 4; kb++) {
            uint32_t a0 = pah[4 * kb],     a1 = pah[4 * kb + 1];
            uint32_t a2 = pah[4 * kb + 2], a3 = pah[4 * kb + 3];
            #pragma unroll
            for (int p = 0; p < 4; p++) {
                uint32_t bh[4], bl[4];
                ldsm4(bh, shTh + boff + p * 2304 + kb * 32);
                ldsm4(bl, shTl + boff + p * 2304 + kb * 32);
                mma16816(o[2 * p],     a0, a1, a2, a3, bh[0], bh[1]);
                mma16816(o[2 * p],     a0, a1, a2, a3, bl[0], bl[1]);
                mma16816(o[2 * p + 1], a0, a1, a2, a3, bh[2], bh[3]);
                mma16816(o[2 * p + 1], a0, a1, a2, a3, bl[2], bl[3]);
            }
        }
    }

    // reduce row sums across quad lanes; emit partials
    ps_a += __shfl_xor_sync(0xffffffffu, ps_a, 1);
    ps_a += __shfl_xor_sync(0xffffffffu, ps_a, 2);
    ps_b += __shfl_xor_sync(0xffffffffu, ps_b, 1);
    ps_b += __shfl_xor_sync(0xffffffffu, ps_b, 2);
    const int rl0 = 16 * w + g, rl1 = rl0 + 8;
    if (tq == 0) {
        g_psum[(sp * 8 + h) * NROWS + qb + rl0] = ps_a;
        g_psum[(sp * 8 + h) * NROWS + qb + rl1] = ps_b;
    }
    #pragma unroll
    for (int nb = 0; nb < 8; nb++) {
        const int col = h * 64 + 8 * nb + 2 * tq;
        *(float2*)&g_part[((size_t)sp * NROWS + qb + rl0) * EDIM + col] = make_float2(o[nb][0], o[nb][1]);
        *(float2*)&g_part[((size_t)sp * NROWS + qb + rl1) * EDIM + col] = make_float2(o[nb][2], o[nb][3]);
    }
}

// ---------------- combine KV-splits -> ctx hi/lo (sorted space) -----------------
__global__ void combine_kernel() {
    const int r = blockIdx.x;
    const int t = threadIdx.x;
    __shared__ float inv[8];
    if (t < 8) {
        float tot = 0.f;
        #pragma unroll
        for (int s = 0; s < SPLITS; s++) tot += g_psum[(s * 8 + t) * NROWS + r];
        inv[t] = 1.f / tot;
    }
    __syncthreads();
    const int c = t * 4;
    float4 a = *(const float4*)&g_part[(size_t)r * EDIM + c];
    #pragma unroll
    for (int s = 1; s < SPLITS; s++) {
        float4 b = *(const float4*)&g_part[((size_t)s * NROWS + r) * EDIM + c];
        a.x += b.x; a.y += b.y; a.z += b.z; a.w += b.w;
    }
    float iv = inv[c >> 6];
    uint32_t h0, l0, h1, l1;
    split2(a.x * iv, a.y * iv, h0, l0);
    split2(a.z * iv, a.w * iv, h1, l1);
    *(uint32_t*)&g_ctxh[(size_t)r * EDIM + c]     = h0;
    *(uint32_t*)&g_ctxl[(size_t)r * EDIM + c]     = l0;
    *(uint32_t*)&g_ctxh[(size_t)r * EDIM + c + 2] = h1;
    *(uint32_t*)&g_ctxl[(size_t)r * EDIM + c + 2] = l1;
}

// ---------------- fill comb cols 512..895 (sorted rows, hi/lo) ------------------
__global__ void fill_comb_kernel(const int* __restrict__ dmask,
                                 const int* __restrict__ steps,
                                 const float* __restrict__ status) {
    const int r = blockIdx.x;
    __shared__ int so;
    if (threadIdx.x == 0) so = g_perm[r];
    __syncthreads();
    const int col = 2 * threadIdx.x;           // 0..382
    float v0, v1;
    if (col < 128) {
        int dm = dmask[so];
        v0 = status[dm * 128 + col];
        v1 = status[dm * 128 + col + 1];
    } else {
        int sc = steps[so];
        sc = sc < 0 ? 0 : (sc > 99 ? 99 : sc);
        v0 = g_te[sc * 256 + col - 128];
        v1 = g_te[sc * 256 + col - 127];
    }
    uint32_t hw, lw;
    split2(v0, v1, hw, lw);
    *(uint32_t*)&g_combh[(size_t)r * 896 + 512 + col] = hw;
    *(uint32_t*)&g_combl[(size_t)r * 896 + 512 + col] = lw;
}

// ---------------- LayerNorm -> ReLU -> residual (un-permute) --------------------
__global__ void ln_relu_res_kernel(const float* __restrict__ x,
                                   const float* __restrict__ gamma,
                                   const float* __restrict__ beta,
                                   float* __restrict__ out) {
    const int r = blockIdx.x;
    const int t = threadIdx.x;
    __shared__ float sh[8];
    __shared__ float stat[2];
    __shared__ int so;
    if (t == 0) so = g_perm[r];

    const float* hr = g_h + (size_t)r * EDIM;
    float v0 = hr[t], v1 = hr[t + 256];

    float s = v0 + v1;
    #pragma unroll
    for (int o2 = 16; o2; o2 >>= 1) s += __shfl_xor_sync(0xffffffffu, s, o2);
    if ((t & 31) == 0) sh[t >> 5] = s;
    __syncthreads();
    if (t == 0) {
        float tot = 0.f;
        #pragma unroll
        for (int i = 0; i < 8; i++) tot += sh[i];
        stat[0] = tot * (1.f / 512.f);
    }
    __syncthreads();
    float mu = stat[0];
    float d0 = v0 - mu, d1 = v1 - mu;
    float vv = d0 * d0 + d1 * d1;
    #pragma unroll
    for (int o2 = 16; o2; o2 >>= 1) vv += __shfl_xor_sync(0xffffffffu, vv, o2);
    if ((t & 31) == 0) sh[t >> 5] = vv;
    __syncthreads();
    if (t == 0) {
        float tot = 0.f;
        #pragma unroll
        for (int i = 0; i < 8; i++) tot += sh[i];
        stat[1] = 1.f / sqrtf(tot * (1.f / 512.f) + 1e-5f);
    }
    __syncthreads();
    float inv = stat[1];

    float y0 = fmaxf(d0 * inv * gamma[t]       + beta[t],       0.f);
    float y1 = fmaxf(d1 * inv * gamma[t + 256] + beta[t + 256], 0.f);
    const size_t orow = so;
    out[orow * EDIM + t]       = x[orow * EDIM + t]       + y0;
    out[orow * EDIM + t + 256] = x[orow * EDIM + t + 256] + y1;
}

// ---------------- launch ---------------------------------------------------------
extern "C" void kernel_launch(void* const* d_in, const int* in_sizes, int n_in,
                              void* d_out, int out_size) {
    const float* x      = (const float*)d_in[0];
    const int*   dmask  = (const int*)  d_in[1];
    const int*   steps  = (const int*)  d_in[2];
    const float* status = (const float*)d_in[3];
    const float* wqkv   = (const float*)d_in[4];
    const float* bqkv   = (const float*)d_in[5];
    const float* wout   = (const float*)d_in[6];
    const float* bout   = (const float*)d_in[7];
    const float* wmlp   = (const float*)d_in[8];
    const float* bmlp   = (const float*)d_in[9];
    const float* gamma  = (const float*)d_in[10];
    const float* beta   = (const float*)d_in[11];
    float* out = (float*)d_out;

    __nv_bfloat16 *xh, *xl, *wqh, *wql, *woh, *wol, *wmh, *wml;
    __nv_bfloat16 *qkvh, *qkvl, *ctxh, *ctxl, *combh, *combl;
    float* hbuf;
    cudaGetSymbolAddress((void**)&xh,    g_xh);
    cudaGetSymbolAddress((void**)&xl,    g_xl);
    cudaGetSymbolAddress((void**)&wqh,   g_wqkvh);
    cudaGetSymbolAddress((void**)&wql,   g_wqkvl);
    cudaGetSymbolAddress((void**)&woh,   g_wouth);
    cudaGetSymbolAddress((void**)&wol,   g_woutl);
    cudaGetSymbolAddress((void**)&wmh,   g_wmlph);
    cudaGetSymbolAddress((void**)&wml,   g_wmlpl);
    cudaGetSymbolAddress((void**)&qkvh,  g_qkvh);
    cudaGetSymbolAddress((void**)&qkvl,  g_qkvl);
    cudaGetSymbolAddress((void**)&ctxh,  g_ctxh);
    cudaGetSymbolAddress((void**)&ctxl,  g_ctxl);
    cudaGetSymbolAddress((void**)&combh, g_combh);
    cudaGetSymbolAddress((void**)&combl, g_combl);
    cudaGetSymbolAddress((void**)&hbuf,  g_h);

    const int attn_smem = 6 * 4608 * 2 + 64 * 4;   // 55552
    cudaFuncSetAttribute(attn_kernel, cudaFuncAttributeMaxDynamicSharedMemorySize,
                         attn_smem);

    sort_kernel<<<1, 128>>>(steps);
    build_te_kernel<<<50, 256>>>();

    cvt_split_kernel<<<(NROWS * EDIM / 2 + 255) / 256, 256>>>(x,    xh,  xl,  NROWS * EDIM);
    cvt_split_kernel<<<(QKVLD * EDIM / 2 + 255) / 256, 256>>>(wqkv, wqh, wql, QKVLD * EDIM);
    cvt_split_kernel<<<(EDIM * EDIM / 2 + 255) / 256, 256>>>(wout, woh, wol, EDIM * EDIM);
    cvt_split_kernel<<<(EDIM * 896 / 2 + 255) / 256, 256>>>(wmlp, wmh, wml, EDIM * 896);

    mma_gemm<0><<<dim3(24, 64), 128>>>(xh, xl, EDIM, wqh, wql, bqkv, EDIM,
                                       nullptr, qkvh, qkvl, QKVLD);

    vt_transpose_kernel<<<dim3(64, 8), 128>>>();

    attn_kernel<<<dim3(64, 8, SPLITS), 128, attn_smem>>>();

    combine_kernel<<<4096, 128>>>();

    mma_gemm<1><<<dim3(8, 64), 128>>>(ctxh, ctxl, EDIM, woh, wol, bout, EDIM,
                                      nullptr, combh, combl, 896);

    fill_comb_kernel<<<4096, 192>>>(dmask, steps, status);

    mma_gemm<2><<<dim3(8, 64), 128>>>(combh, combl, 896, wmh, wml, bmlp, 896,
                                      hbuf, nullptr, nullptr, EDIM);

    ln_relu_res_kernel<<<4096, 256>>>(x, gamma, beta, out);
}

// round 9
// speedup vs baseline: 2.5625x; 1.0480x over previous
#include <cuda_runtime.h>
#include <cuda_bf16.h>
#include <math.h>
#include <stdint.h>

#define NROWS  4096
#define EDIM   512
#define QKVLD  1536
#define SPLITS 4

// ---------------- device scratch (no allocations allowed) -------------------
__device__ float g_te[100 * 256];
__device__ int   g_perm[NROWS], g_sortpos[NROWS], g_ssteps[NROWS], g_kstart[64];

__device__ __align__(16) __nv_bfloat16 g_xh   [NROWS * EDIM],  g_xl   [NROWS * EDIM];
__device__ __align__(16) __nv_bfloat16 g_wqkvh[QKVLD * EDIM],  g_wqkvl[QKVLD * EDIM];
__device__ __align__(16) __nv_bfloat16 g_wouth[EDIM * EDIM],   g_woutl[EDIM * EDIM];
__device__ __align__(16) __nv_bfloat16 g_wmlph[EDIM * 896],    g_wmlpl[EDIM * 896];
__device__ __align__(16) __nv_bfloat16 g_qkvh [NROWS * QKVLD], g_qkvl [NROWS * QKVLD];
__device__ __align__(16) __nv_bfloat16 g_vth  [EDIM * NROWS];
__device__ __align__(16) __nv_bfloat16 g_ctxh [NROWS * EDIM],  g_ctxl [NROWS * EDIM];
__device__ __align__(16) __nv_bfloat16 g_combh[NROWS * 896],   g_combl[NROWS * 896];
__device__ float g_h[NROWS * EDIM];
__device__ float g_part[(size_t)SPLITS * NROWS * EDIM];
__device__ float g_psum[SPLITS * 8 * NROWS];

// ---------------- helpers ----------------------------------------------------
__device__ __forceinline__ void mma16816(float* c,
    uint32_t a0, uint32_t a1, uint32_t a2, uint32_t a3,
    uint32_t b0, uint32_t b1) {
    asm volatile(
        "mma.sync.aligned.m16n8k16.row.col.f32.bf16.bf16.f32 "
        "{%0,%1,%2,%3},{%4,%5,%6,%7},{%8,%9},{%0,%1,%2,%3};"
        : "+f"(c[0]), "+f"(c[1]), "+f"(c[2]), "+f"(c[3])
        : "r"(a0), "r"(a1), "r"(a2), "r"(a3), "r"(b0), "r"(b1));
}

__device__ __forceinline__ void ldsm4(uint32_t* r, uint32_t addr) {
    asm volatile("ldmatrix.sync.aligned.m8n8.x4.shared.b16 {%0,%1,%2,%3}, [%4];"
        : "=r"(r[0]), "=r"(r[1]), "=r"(r[2]), "=r"(r[3]) : "r"(addr));
}

__device__ __forceinline__ void cp16(uint32_t dst, const void* src) {
    asm volatile("cp.async.cg.shared.global [%0], [%1], 16;" :: "r"(dst), "l"(src));
}
__device__ __forceinline__ void cp4(uint32_t dst, const void* src) {
    asm volatile("cp.async.ca.shared.global [%0], [%1], 4;" :: "r"(dst), "l"(src));
}
__device__ __forceinline__ void cp_commit() { asm volatile("cp.async.commit_group;"); }
__device__ __forceinline__ void cp_wait0()  { asm volatile("cp.async.wait_group 0;"); }

__device__ __forceinline__ void split2(float v0, float v1, uint32_t& hi, uint32_t& lo) {
    __nv_bfloat162 h = __floats2bfloat162_rn(v0, v1);
    float r0 = v0 - __bfloat162float(h.x);
    float r1 = v1 - __bfloat162float(h.y);
    __nv_bfloat162 l = __floats2bfloat162_rn(r0, r1);
    hi = *reinterpret_cast<uint32_t*>(&h);
    lo = *reinterpret_cast<uint32_t*>(&l);
}

__device__ __forceinline__ uint32_t pack_bf162(float v0, float v1) {
    __nv_bfloat162 h = __floats2bfloat162_rn(v0, v1);
    return *reinterpret_cast<uint32_t*>(&h);
}

// ---------------- time table ---------------------------------------------------
__global__ void build_te_kernel() {
    int t = blockIdx.x * blockDim.x + threadIdx.x;
    if (t >= 100 * 128) return;
    int p = t >> 7;
    int k = t & 127;
    double div = exp(-((double)(2 * k)) * log(10000.0) / 256.0);
    double ang = (double)p * div;
    g_te[p * 256 + 2 * k]     = (float)sin(ang);
    g_te[p * 256 + 2 * k + 1] = (float)cos(ang);
}

// ---------------- deterministic stable sort by step ----------------------------
__global__ void sort_kernel(const int* __restrict__ steps) {
    __shared__ int s_steps[NROWS];
    __shared__ int hist[100];
    __shared__ int base[100];
    const int t = threadIdx.x;

    for (int i = t; i < 100; i += 128) hist[i] = 0;
    __syncthreads();
    for (int i = t; i < NROWS; i += 128) {
        int s = steps[i];
        s = s < 0 ? 0 : (s > 99 ? 99 : s);
        s_steps[i] = s;
        atomicAdd(&hist[s], 1);
    }
    __syncthreads();
    if (t == 0) {
        int acc = 0;
        for (int b = 0; b < 100; b++) { base[b] = acc; acc += hist[b]; }
    }
    __syncthreads();
    if (t < 100) {
        int r = base[t];
        for (int i = 0; i < NROWS; i++) {
            if (s_steps[i] == t) {
                g_perm[r] = i;
                g_sortpos[i] = r;
                g_ssteps[r] = t;
                r++;
            }
        }
    }
    __syncthreads();
    if (t < 64) {
        int qmin = g_ssteps[t * 64];
        int ks = 0;
        while (ks < 64 && g_ssteps[ks * 64 + 63] < qmin) ks++;
        g_kstart[t] = ks;
    }
}

// ---------------- fp32 -> bf16 hi/lo split -------------------------------------
__global__ void cvt_split_kernel(const float* __restrict__ src,
                                 __nv_bfloat16* __restrict__ h,
                                 __nv_bfloat16* __restrict__ l, int n) {
    int i = (blockIdx.x * blockDim.x + threadIdx.x) * 2;
    if (i >= n) return;
    float2 v = *(const float2*)(src + i);
    uint32_t hw, lw;
    split2(v.x, v.y, hw, lw);
    *(uint32_t*)(h + i) = hw;
    *(uint32_t*)(l + i) = lw;
}

// ---------------- split-bf16 tensor GEMM, cp.async double-buffered --------------
// smem layout (bf16 units): buffer(stage, which) = (stage*4 + which) * 4608
// which: 0=Ah 1=Al 2=Wh 3=Wl.  Total 8*4608*2 = 73728 bytes.
template<int MODE>
__global__ __launch_bounds__(128)
void mma_gemm(const __nv_bfloat16* __restrict__ Ah, const __nv_bfloat16* __restrict__ Al,
              int lda,
              const __nv_bfloat16* __restrict__ Wh, const __nv_bfloat16* __restrict__ Wl,
              const float* __restrict__ bias, int K,
              float* __restrict__ Cf,
              __nv_bfloat16* __restrict__ Ch, __nv_bfloat16* __restrict__ Cl, int ldc) {
    extern __shared__ __align__(16) unsigned char smraw[];
    const uint32_t smb = (uint32_t)__cvta_generic_to_shared(smraw);
    const int t = threadIdx.x;
    const int w = t >> 5, lane = t & 31, g = lane >> 2, tq = lane & 3;
    const int bm = blockIdx.y * 64, bn = blockIdx.x * 64;
    const int lrow = t >> 1, lhalf = (t & 1) * 32;
    const uint32_t ldst = (uint32_t)((lrow * 72 + lhalf) * 2);

    const int lr  = lane & 7;
    const int sel = lane >> 3;
    const uint32_t aoff = (uint32_t)(((16 * w + (sel & 1) * 8 + lr) * 72 + (sel >> 1) * 8) * 2);
    const uint32_t boff = (uint32_t)((((sel >> 1) * 8 + lr) * 72 + (sel & 1) * 8) * 2);

    const int nck = K >> 6;

    auto issue = [&](int c, int stg) {
        const size_t ao = (size_t)(bm + lrow) * lda + c * 64 + lhalf;
        const size_t wo = (size_t)(bn + lrow) * K   + c * 64 + lhalf;
        const uint32_t b0 = smb + (uint32_t)(stg * 4) * 9216;
        #pragma unroll
        for (int j = 0; j < 4; j++) {
            cp16(b0 +            ldst + j * 16, Ah + ao + j * 8);
            cp16(b0 + 1 * 9216 + ldst + j * 16, Al + ao + j * 8);
            cp16(b0 + 2 * 9216 + ldst + j * 16, Wh + wo + j * 8);
            cp16(b0 + 3 * 9216 + ldst + j * 16, Wl + wo + j * 8);
        }
        cp_commit();
    };

    float c[8][4];
    #pragma unroll
    for (int i = 0; i < 8; i++)
        #pragma unroll
        for (int j = 0; j < 4; j++) c[i][j] = 0.f;

    issue(0, 0);
    for (int ck = 0; ck < nck; ck++) {
        cp_wait0();
        __syncthreads();
        if (ck + 1 < nck) issue(ck + 1, (ck + 1) & 1);
        const uint32_t b0 = smb + (uint32_t)((ck & 1) * 4) * 9216;
        #pragma unroll
        for (int kb = 0; kb < 4; kb++) {
            uint32_t ah[4], al[4];
            ldsm4(ah, b0 +        aoff + kb * 32);
            ldsm4(al, b0 + 9216 + aoff + kb * 32);
            #pragma unroll
            for (int p = 0; p < 4; p++) {
                uint32_t bh[4], bl[4];
                ldsm4(bh, b0 + 2 * 9216 + boff + p * 2304 + kb * 32);
                ldsm4(bl, b0 + 3 * 9216 + boff + p * 2304 + kb * 32);
                mma16816(c[2 * p],     ah[0], ah[1], ah[2], ah[3], bh[0], bh[1]);
                mma16816(c[2 * p],     ah[0], ah[1], ah[2], ah[3], bl[0], bl[1]);
                mma16816(c[2 * p],     al[0], al[1], al[2], al[3], bh[0], bh[1]);
                mma16816(c[2 * p + 1], ah[0], ah[1], ah[2], ah[3], bh[2], bh[3]);
                mma16816(c[2 * p + 1], ah[0], ah[1], ah[2], ah[3], bl[2], bl[3]);
                mma16816(c[2 * p + 1], al[0], al[1], al[2], al[3], bh[2], bh[3]);
            }
        }
        __syncthreads();   // all warps done with this stage before it is refilled
    }

    const int r0 = bm + 16 * w + g, r1 = r0 + 8;
    size_t gr0, gr1;
    if (MODE == 0) { gr0 = g_sortpos[r0]; gr1 = g_sortpos[r1]; }
    else           { gr0 = r0;            gr1 = r1; }
    #pragma unroll
    for (int nb = 0; nb < 8; nb++) {
        const int col = bn + 8 * nb + 2 * tq;
        float b0 = __ldg(bias + col), b1 = __ldg(bias + col + 1);
        float v0 = c[nb][0] + b0, v1 = c[nb][1] + b1;
        float v2 = c[nb][2] + b0, v3 = c[nb][3] + b1;
        if (MODE == 2) {
            *(float2*)&Cf[gr0 * ldc + col] = make_float2(v0, v1);
            *(float2*)&Cf[gr1 * ldc + col] = make_float2(v2, v3);
        } else {
            uint32_t h0, l0, h1, l1;
            split2(v0, v1, h0, l0);
            split2(v2, v3, h1, l1);
            *(uint32_t*)&Ch[gr0 * ldc + col] = h0;
            *(uint32_t*)&Cl[gr0 * ldc + col] = l0;
            *(uint32_t*)&Ch[gr1 * ldc + col] = h1;
            *(uint32_t*)&Cl[gr1 * ldc + col] = l1;
        }
    }
}

// ---------------- V transpose (hi only): sorted v -> [head][d][key] -------------
__global__ __launch_bounds__(128)
void vt_transpose_kernel() {
    __shared__ __align__(16) __nv_bfloat16 th[64 * 72];
    const int t = threadIdx.x;
    const int rb = blockIdx.x * 64, h = blockIdx.y;
    const int lrow = t >> 1, lhalf = (t & 1) * 32;
    const size_t src = (size_t)(rb + lrow) * QKVLD + 1024 + h * 64 + lhalf;
    #pragma unroll
    for (int j = 0; j < 4; j++)
        *(uint4*)&th[lrow * 72 + lhalf + j * 8] = *(const uint4*)(g_qkvh + src + j * 8);
    __syncthreads();
    const int d = t >> 1, kh = (t & 1) * 32;
    __nv_bfloat16* dh = g_vth + (size_t)(h * 64 + d) * NROWS + rb;
    #pragma unroll
    for (int j = 0; j < 16; j++) {
        int sr = kh + 2 * j;
        __nv_bfloat162 a;
        a.x = th[sr * 72 + d]; a.y = th[(sr + 1) * 72 + d];
        *(__nv_bfloat162*)(dh + sr) = a;
    }
}

// ---------------- tensor-core flash attention, KV-split, cp.async pipeline ------
// smem bytes: Qh 0, Ql 9216, stage s: Kh 18432+s*27648, Kl +9216, Th +18432,
// sks at 73728 + s*256.  Total 74240.
__global__ __launch_bounds__(128)
void attn_kernel() {
    extern __shared__ __align__(16) unsigned char smraw[];
    const uint32_t smb = (uint32_t)__cvta_generic_to_shared(smraw);
    __nv_bfloat16* Qh = (__nv_bfloat16*)smraw;
    __nv_bfloat16* Ql = Qh + 4608;
    int* sks0 = (int*)(smraw + 73728);

    const int qt = blockIdx.x, h = blockIdx.y, sp = blockIdx.z;
    const int qb = qt * 64;
    const int t = threadIdx.x, w = t >> 5, lane = t & 31, g = lane >> 2, tq = lane & 3;
    const int lrow = t >> 1, lhalf = (t & 1) * 32;
    const uint32_t ldst = (uint32_t)((lrow * 72 + lhalf) * 2);

    const int lr  = lane & 7;
    const int sel = lane >> 3;
    const uint32_t aoff = (uint32_t)(((16 * w + (sel & 1) * 8 + lr) * 72 + (sel >> 1) * 8) * 2);
    const uint32_t boff = (uint32_t)((((sel >> 1) * 8 + lr) * 72 + (sel & 1) * 8) * 2);

    const int ks0 = g_kstart[qt];
    const int len = (64 - ks0 + SPLITS - 1) / SPLITS;
    const int k0  = ks0 + sp * len;
    const int k1  = (k0 + len < 64) ? (k0 + len) : 64;

    auto issue = [&](int kt, int stg) {
        const int kb64 = kt * 64;
        const size_t ks = (size_t)(kb64 + lrow) * QKVLD + 512 + h * 64 + lhalf;
        const size_t vs = (size_t)(h * 64 + lrow) * NROWS + kb64 + lhalf;
        const uint32_t b0 = smb + 18432 + (uint32_t)stg * 27648;
        #pragma unroll
        for (int j = 0; j < 4; j++) {
            cp16(b0 +             ldst + j * 16, g_qkvh + ks + j * 8);
            cp16(b0 + 1 * 9216 +  ldst + j * 16, g_qkvl + ks + j * 8);
            cp16(b0 + 2 * 9216 +  ldst + j * 16, g_vth  + vs + j * 8);
        }
        if (t < 64) cp4(smb + 73728 + (uint32_t)stg * 256 + t * 4, g_ssteps + kb64 + t);
        cp_commit();
    };

    // stage Q (regular loads) + first tile (async)
    if (k0 < k1) issue(k0, k0 & 1);
    {
        const size_t src = (size_t)(qb + lrow) * QKVLD + h * 64 + lhalf;
        #pragma unroll
        for (int j = 0; j < 4; j++) {
            *(uint4*)&Qh[lrow * 72 + lhalf + j * 8] = *(const uint4*)(g_qkvh + src + j * 8);
            *(uint4*)&Ql[lrow * 72 + lhalf + j * 8] = *(const uint4*)(g_qkvl + src + j * 8);
        }
    }
    const int sq_a = g_ssteps[qb + 16 * w + g];
    const int sq_b = g_ssteps[qb + 16 * w + g + 8];
    __syncthreads();

    uint32_t qfh[4][4], qfl[4][4];
    #pragma unroll
    for (int kb = 0; kb < 4; kb++) {
        ldsm4(qfh[kb], smb +        aoff + kb * 32);
        ldsm4(qfl[kb], smb + 9216 + aoff + kb * 32);
    }

    float o[8][4];
    #pragma unroll
    for (int i = 0; i < 8; i++)
        #pragma unroll
        for (int j = 0; j < 4; j++) o[i][j] = 0.f;
    float ps_a = 0.f, ps_b = 0.f;

    for (int kt = k0; kt < k1; kt++) {
        const int stg = kt & 1;
        cp_wait0();
        __syncthreads();          // tile kt resident; all warps past prior compute
        if (kt + 1 < k1) issue(kt + 1, (kt + 1) & 1);

        const uint32_t b0 = smb + 18432 + (uint32_t)stg * 27648;
        const int* sksS = sks0 + stg * 64;

        // S = Q K^T (3-term split)
        float s[8][4];
        #pragma unroll
        for (int i = 0; i < 8; i++)
            #pragma unroll
            for (int j = 0; j < 4; j++) s[i][j] = 0.f;
        #pragma unroll
        for (int kb = 0; kb < 4; kb++) {
            #pragma unroll
            for (int p = 0; p < 4; p++) {
                uint32_t bh[4], bl[4];
                ldsm4(bh, b0 +        boff + p * 2304 + kb * 32);
                ldsm4(bl, b0 + 9216 + boff + p * 2304 + kb * 32);
                mma16816(s[2 * p],     qfh[kb][0], qfh[kb][1], qfh[kb][2], qfh[kb][3], bh[0], bh[1]);
                mma16816(s[2 * p],     qfh[kb][0], qfh[kb][1], qfh[kb][2], qfh[kb][3], bl[0], bl[1]);
                mma16816(s[2 * p],     qfl[kb][0], qfl[kb][1], qfl[kb][2], qfl[kb][3], bh[0], bh[1]);
                mma16816(s[2 * p + 1], qfh[kb][0], qfh[kb][1], qfh[kb][2], qfh[kb][3], bh[2], bh[3]);
                mma16816(s[2 * p + 1], qfh[kb][0], qfh[kb][1], qfh[kb][2], qfh[kb][3], bl[2], bl[3]);
                mma16816(s[2 * p + 1], qfl[kb][0], qfl[kb][1], qfl[kb][2], qfl[kb][3], bh[2], bh[3]);
            }
        }

        // softmax (fixed shift) + mask; P hi-only frags; exact p in row sums
        uint32_t pah[16];
        #pragma unroll
        for (int nb = 0; nb < 8; nb++) {
            int2 kk = *(const int2*)&sksS[8 * nb + 2 * tq];
            float p0 = __expf(s[nb][0] * 0.125f); if (kk.x < sq_a) p0 = 0.f;
            float p1 = __expf(s[nb][1] * 0.125f); if (kk.y < sq_a) p1 = 0.f;
            float p2 = __expf(s[nb][2] * 0.125f); if (kk.x < sq_b) p2 = 0.f;
            float p3 = __expf(s[nb][3] * 0.125f); if (kk.y < sq_b) p3 = 0.f;
            ps_a += p0 + p1;
            ps_b += p2 + p3;
            pah[2 * nb]     = pack_bf162(p0, p1);
            pah[2 * nb + 1] = pack_bf162(p2, p3);
        }

        // O += P_hi @ V_hi
        #pragma unroll
        for (int kb = 0; kb < 4; kb++) {
            uint32_t a0 = pah[4 * kb],     a1 = pah[4 * kb + 1];
            uint32_t a2 = pah[4 * kb + 2], a3 = pah[4 * kb + 3];
            #pragma unroll
            for (int p = 0; p < 4; p++) {
                uint32_t bh[4];
                ldsm4(bh, b0 + 2 * 9216 + boff + p * 2304 + kb * 32);
                mma16816(o[2 * p],     a0, a1, a2, a3, bh[0], bh[1]);
                mma16816(o[2 * p + 1], a0, a1, a2, a3, bh[2], bh[3]);
            }
        }
        __syncthreads();          // stage may be refilled next iteration
    }

    ps_a += __shfl_xor_sync(0xffffffffu, ps_a, 1);
    ps_a += __shfl_xor_sync(0xffffffffu, ps_a, 2);
    ps_b += __shfl_xor_sync(0xffffffffu, ps_b, 1);
    ps_b += __shfl_xor_sync(0xffffffffu, ps_b, 2);
    const int rl0 = 16 * w + g, rl1 = rl0 + 8;
    if (tq == 0) {
        g_psum[(sp * 8 + h) * NROWS + qb + rl0] = ps_a;
        g_psum[(sp * 8 + h) * NROWS + qb + rl1] = ps_b;
    }
    #pragma unroll
    for (int nb = 0; nb < 8; nb++) {
        const int col = h * 64 + 8 * nb + 2 * tq;
        *(float2*)&g_part[((size_t)sp * NROWS + qb + rl0) * EDIM + col] = make_float2(o[nb][0], o[nb][1]);
        *(float2*)&g_part[((size_t)sp * NROWS + qb + rl1) * EDIM + col] = make_float2(o[nb][2], o[nb][3]);
    }
}

// ---------------- combine KV-splits -> ctx hi/lo (sorted space) -----------------
__global__ void combine_kernel() {
    const int r = blockIdx.x;
    const int t = threadIdx.x;
    __shared__ float inv[8];
    if (t < 8) {
        float tot = 0.f;
        #pragma unroll
        for (int s = 0; s < SPLITS; s++) tot += g_psum[(s * 8 + t) * NROWS + r];
        inv[t] = 1.f / tot;
    }
    __syncthreads();
    const int c = t * 4;
    float4 a = *(const float4*)&g_part[(size_t)r * EDIM + c];
    #pragma unroll
    for (int s = 1; s < SPLITS; s++) {
        float4 b = *(const float4*)&g_part[((size_t)s * NROWS + r) * EDIM + c];
        a.x += b.x; a.y += b.y; a.z += b.z; a.w += b.w;
    }
    float iv = inv[c >> 6];
    uint32_t h0, l0, h1, l1;
    split2(a.x * iv, a.y * iv, h0, l0);
    split2(a.z * iv, a.w * iv, h1, l1);
    *(uint32_t*)&g_ctxh[(size_t)r * EDIM + c]     = h0;
    *(uint32_t*)&g_ctxl[(size_t)r * EDIM + c]     = l0;
    *(uint32_t*)&g_ctxh[(size_t)r * EDIM + c + 2] = h1;
    *(uint32_t*)&g_ctxl[(size_t)r * EDIM + c + 2] = l1;
}

// ---------------- fill comb cols 512..895 (sorted rows, hi/lo) ------------------
__global__ void fill_comb_kernel(const int* __restrict__ dmask,
                                 const int* __restrict__ steps,
                                 const float* __restrict__ status) {
    const int r = blockIdx.x;
    __shared__ int so;
    if (threadIdx.x == 0) so = g_perm[r];
    __syncthreads();
    const int col = 2 * threadIdx.x;
    float v0, v1;
    if (col < 128) {
        int dm = dmask[so];
        v0 = status[dm * 128 + col];
        v1 = status[dm * 128 + col + 1];
    } else {
        int sc = steps[so];
        sc = sc < 0 ? 0 : (sc > 99 ? 99 : sc);
        v0 = g_te[sc * 256 + col - 128];
        v1 = g_te[sc * 256 + col - 127];
    }
    uint32_t hw, lw;
    split2(v0, v1, hw, lw);
    *(uint32_t*)&g_combh[(size_t)r * 896 + 512 + col] = hw;
    *(uint32_t*)&g_combl[(size_t)r * 896 + 512 + col] = lw;
}

// ---------------- LayerNorm -> ReLU -> residual (un-permute) --------------------
__global__ void ln_relu_res_kernel(const float* __restrict__ x,
                                   const float* __restrict__ gamma,
                                   const float* __restrict__ beta,
                                   float* __restrict__ out) {
    const int r = blockIdx.x;
    const int t = threadIdx.x;
    __shared__ float sh[8];
    __shared__ float stat[2];
    __shared__ int so;
    if (t == 0) so = g_perm[r];

    const float* hr = g_h + (size_t)r * EDIM;
    float v0 = hr[t], v1 = hr[t + 256];

    float s = v0 + v1;
    #pragma unroll
    for (int o2 = 16; o2; o2 >>= 1) s += __shfl_xor_sync(0xffffffffu, s, o2);
    if ((t & 31) == 0) sh[t >> 5] = s;
    __syncthreads();
    if (t == 0) {
        float tot = 0.f;
        #pragma unroll
        for (int i = 0; i < 8; i++) tot += sh[i];
        stat[0] = tot * (1.f / 512.f);
    }
    __syncthreads();
    float mu = stat[0];
    float d0 = v0 - mu, d1 = v1 - mu;
    float vv = d0 * d0 + d1 * d1;
    #pragma unroll
    for (int o2 = 16; o2; o2 >>= 1) vv += __shfl_xor_sync(0xffffffffu, vv, o2);
    if ((t & 31) == 0) sh[t >> 5] = vv;
    __syncthreads();
    if (t == 0) {
        float tot = 0.f;
        #pragma unroll
        for (int i = 0; i < 8; i++) tot += sh[i];
        stat[1] = 1.f / sqrtf(tot * (1.f / 512.f) + 1e-5f);
    }
    __syncthreads();
    float inv = stat[1];

    float y0 = fmaxf(d0 * inv * gamma[t]       + beta[t],       0.f);
    float y1 = fmaxf(d1 * inv * gamma[t + 256] + beta[t + 256], 0.f);
    const size_t orow = so;
    out[orow * EDIM + t]       = x[orow * EDIM + t]       + y0;
    out[orow * EDIM + t + 256] = x[orow * EDIM + t + 256] + y1;
}

// ---------------- launch ---------------------------------------------------------
extern "C" void kernel_launch(void* const* d_in, const int* in_sizes, int n_in,
                              void* d_out, int out_size) {
    const float* x      = (const float*)d_in[0];
    const int*   dmask  = (const int*)  d_in[1];
    const int*   steps  = (const int*)  d_in[2];
    const float* status = (const float*)d_in[3];
    const float* wqkv   = (const float*)d_in[4];
    const float* bqkv   = (const float*)d_in[5];
    const float* wout   = (const float*)d_in[6];
    const float* bout   = (const float*)d_in[7];
    const float* wmlp   = (const float*)d_in[8];
    const float* bmlp   = (const float*)d_in[9];
    const float* gamma  = (const float*)d_in[10];
    const float* beta   = (const float*)d_in[11];
    float* out = (float*)d_out;

    __nv_bfloat16 *xh, *xl, *wqh, *wql, *woh, *wol, *wmh, *wml;
    __nv_bfloat16 *qkvh, *qkvl, *ctxh, *ctxl, *combh, *combl;
    float* hbuf;
    cudaGetSymbolAddress((void**)&xh,    g_xh);
    cudaGetSymbolAddress((void**)&xl,    g_xl);
    cudaGetSymbolAddress((void**)&wqh,   g_wqkvh);
    cudaGetSymbolAddress((void**)&wql,   g_wqkvl);
    cudaGetSymbolAddress((void**)&woh,   g_wouth);
    cudaGetSymbolAddress((void**)&wol,   g_woutl);
    cudaGetSymbolAddress((void**)&wmh,   g_wmlph);
    cudaGetSymbolAddress((void**)&wml,   g_wmlpl);
    cudaGetSymbolAddress((void**)&qkvh,  g_qkvh);
    cudaGetSymbolAddress((void**)&qkvl,  g_qkvl);
    cudaGetSymbolAddress((void**)&ctxh,  g_ctxh);
    cudaGetSymbolAddress((void**)&ctxl,  g_ctxl);
    cudaGetSymbolAddress((void**)&combh, g_combh);
    cudaGetSymbolAddress((void**)&combl, g_combl);
    cudaGetSymbolAddress((void**)&hbuf,  g_h);

    const int attn_smem = 74240;
    const int gemm_smem = 73728;
    cudaFuncSetAttribute(attn_kernel, cudaFuncAttributeMaxDynamicSharedMemorySize, attn_smem);
    cudaFuncSetAttribute(mma_gemm<0>,  cudaFuncAttributeMaxDynamicSharedMemorySize, gemm_smem);
    cudaFuncSetAttribute(mma_gemm<1>,  cudaFuncAttributeMaxDynamicSharedMemorySize, gemm_smem);
    cudaFuncSetAttribute(mma_gemm<2>,  cudaFuncAttributeMaxDynamicSharedMemorySize, gemm_smem);

    sort_kernel<<<1, 128>>>(steps);
    build_te_kernel<<<50, 256>>>();

    cvt_split_kernel<<<(NROWS * EDIM / 2 + 255) / 256, 256>>>(x,    xh,  xl,  NROWS * EDIM);
    cvt_split_kernel<<<(QKVLD * EDIM / 2 + 255) / 256, 256>>>(wqkv, wqh, wql, QKVLD * EDIM);
    cvt_split_kernel<<<(EDIM * EDIM / 2 + 255) / 256, 256>>>(wout, woh, wol, EDIM * EDIM);
    cvt_split_kernel<<<(EDIM * 896 / 2 + 255) / 256, 256>>>(wmlp, wmh, wml, EDIM * 896);

    mma_gemm<0><<<dim3(24, 64), 128, gemm_smem>>>(xh, xl, EDIM, wqh, wql, bqkv, EDIM,
                                                  nullptr, qkvh, qkvl, QKVLD);

    vt_transpose_kernel<<<dim3(64, 8), 128>>>();

    attn_kernel<<<dim3(64, 8, SPLITS), 128, attn_smem>>>();

    combine_kernel<<<4096, 128>>>();

    mma_gemm<1><<<dim3(8, 64), 128, gemm_smem>>>(ctxh, ctxl, EDIM, woh, wol, bout, EDIM,
                                                 nullptr, combh, combl, 896);

    fill_comb_kernel<<<4096, 192>>>(dmask, steps, status);

    mma_gemm<2><<<dim3(8, 64), 128, gemm_smem>>>(combh, combl, 896, wmh, wml, bmlp, 896,
                                                 hbuf, nullptr, nullptr, EDIM);

    ln_relu_res_kernel<<<4096, 256>>>(x, gamma, beta, out);
}

// round 10
// speedup vs baseline: 3.2971x; 1.2867x over previous
#include <cuda_runtime.h>
#include <cuda_bf16.h>
#include <math.h>
#include <stdint.h>

#define NROWS  4096
#define EDIM   512
#define QKVLD  1536
#define SPLITS 4

// ---------------- device scratch (no allocations allowed) -------------------
__device__ float g_te[100 * 256];
__device__ int   g_perm[NROWS], g_sortpos[NROWS], g_ssteps[NROWS], g_kstart[64];

__device__ __align__(16) __nv_bfloat16 g_xh   [NROWS * EDIM],  g_xl   [NROWS * EDIM];
__device__ __align__(16) __nv_bfloat16 g_wqkvh[QKVLD * EDIM],  g_wqkvl[QKVLD * EDIM];
__device__ __align__(16) __nv_bfloat16 g_wouth[EDIM * EDIM],   g_woutl[EDIM * EDIM];
__device__ __align__(16) __nv_bfloat16 g_wmlph[EDIM * 896],    g_wmlpl[EDIM * 896];
__device__ __align__(16) __nv_bfloat16 g_qkvh [NROWS * QKVLD], g_qkvl [NROWS * QKVLD];
__device__ __align__(16) __nv_bfloat16 g_vth  [EDIM * NROWS];
__device__ __align__(16) __nv_bfloat16 g_ctxh [NROWS * EDIM],  g_ctxl [NROWS * EDIM];
__device__ __align__(16) __nv_bfloat16 g_combh[NROWS * 896],   g_combl[NROWS * 896];
__device__ float g_h[NROWS * EDIM];
__device__ float g_part[(size_t)SPLITS * NROWS * EDIM];
__device__ float g_psum[SPLITS * 8 * NROWS];

// ---------------- helpers ----------------------------------------------------
__device__ __forceinline__ void mma16816(float* c,
    uint32_t a0, uint32_t a1, uint32_t a2, uint32_t a3,
    uint32_t b0, uint32_t b1) {
    asm volatile(
        "mma.sync.aligned.m16n8k16.row.col.f32.bf16.bf16.f32 "
        "{%0,%1,%2,%3},{%4,%5,%6,%7},{%8,%9},{%0,%1,%2,%3};"
        : "+f"(c[0]), "+f"(c[1]), "+f"(c[2]), "+f"(c[3])
        : "r"(a0), "r"(a1), "r"(a2), "r"(a3), "r"(b0), "r"(b1));
}

__device__ __forceinline__ void ldsm4(uint32_t* r, uint32_t addr) {
    asm volatile("ldmatrix.sync.aligned.m8n8.x4.shared.b16 {%0,%1,%2,%3}, [%4];"
        : "=r"(r[0]), "=r"(r[1]), "=r"(r[2]), "=r"(r[3]) : "r"(addr));
}

__device__ __forceinline__ void cp16(uint32_t dst, const void* src) {
    asm volatile("cp.async.cg.shared.global [%0], [%1], 16;" :: "r"(dst), "l"(src));
}
__device__ __forceinline__ void cp4(uint32_t dst, const void* src) {
    asm volatile("cp.async.ca.shared.global [%0], [%1], 4;" :: "r"(dst), "l"(src));
}
__device__ __forceinline__ void cp_commit() { asm volatile("cp.async.commit_group;"); }
__device__ __forceinline__ void cp_wait0()  { asm volatile("cp.async.wait_group 0;"); }

__device__ __forceinline__ void split2(float v0, float v1, uint32_t& hi, uint32_t& lo) {
    __nv_bfloat162 h = __floats2bfloat162_rn(v0, v1);
    float r0 = v0 - __bfloat162float(h.x);
    float r1 = v1 - __bfloat162float(h.y);
    __nv_bfloat162 l = __floats2bfloat162_rn(r0, r1);
    hi = *reinterpret_cast<uint32_t*>(&h);
    lo = *reinterpret_cast<uint32_t*>(&l);
}

__device__ __forceinline__ uint32_t pack_bf162(float v0, float v1) {
    __nv_bfloat162 h = __floats2bfloat162_rn(v0, v1);
    return *reinterpret_cast<uint32_t*>(&h);
}

// ---------------- time table ---------------------------------------------------
__global__ void build_te_kernel() {
    int t = blockIdx.x * blockDim.x + threadIdx.x;
    if (t >= 100 * 128) return;
    int p = t >> 7;
    int k = t & 127;
    double div = exp(-((double)(2 * k)) * log(10000.0) / 256.0);
    double ang = (double)p * div;
    g_te[p * 256 + 2 * k]     = (float)sin(ang);
    g_te[p * 256 + 2 * k + 1] = (float)cos(ang);
}

// ---------------- deterministic stable sort (parallel chunked) ------------------
__global__ void sort_kernel(const int* __restrict__ steps) {
    __shared__ int s_steps[NROWS];
    __shared__ unsigned short hist[128][100];
    __shared__ int base[100];
    const int t = threadIdx.x;   // 128 threads, 32 rows each

    for (int i = t; i < NROWS; i += 128) {
        int s = steps[i];
        s_steps[i] = s < 0 ? 0 : (s > 99 ? 99 : s);
    }
    __syncthreads();

    for (int b = 0; b < 100; b++) hist[t][b] = 0;
    const int r0 = t * 32;
    for (int r = 0; r < 32; r++) hist[t][s_steps[r0 + r]]++;
    __syncthreads();

    if (t < 100) {                           // exclusive scan over chunks per bucket
        int acc = 0;
        for (int c = 0; c < 128; c++) {
            int v = hist[c][t];
            hist[c][t] = (unsigned short)acc;
            acc += v;
        }
        base[t] = acc;
    }
    __syncthreads();
    if (t == 0) {                            // exclusive scan over buckets
        int acc = 0;
        for (int b = 0; b < 100; b++) { int v = base[b]; base[b] = acc; acc += v; }
    }
    __syncthreads();

    for (int r = 0; r < 32; r++) {           // stable placement
        int i = r0 + r;
        int s = s_steps[i];
        int pos = base[s] + hist[t][s];
        hist[t][s]++;
        g_perm[pos] = i;
        g_sortpos[i] = pos;
        g_ssteps[pos] = s;
    }
    __syncthreads();

    if (t < 64) {                            // first non-fully-blocked k-tile
        int qmin = g_ssteps[t * 64];
        int ks = 0;
        while (ks < 64 && g_ssteps[ks * 64 + 63] < qmin) ks++;
        g_kstart[t] = ks;
    }
}

// ---------------- fp32 -> bf16 hi/lo split -------------------------------------
__global__ void cvt_split_kernel(const float* __restrict__ src,
                                 __nv_bfloat16* __restrict__ h,
                                 __nv_bfloat16* __restrict__ l, int n) {
    int i = (blockIdx.x * blockDim.x + threadIdx.x) * 2;
    if (i >= n) return;
    float2 v = *(const float2*)(src + i);
    uint32_t hw, lw;
    split2(v.x, v.y, hw, lw);
    *(uint32_t*)(h + i) = hw;
    *(uint32_t*)(l + i) = lw;
}

// ---------------- split-bf16 tensor GEMM, cp.async double-buffered --------------
template<int MODE>
__global__ __launch_bounds__(128)
void mma_gemm(const __nv_bfloat16* __restrict__ Ah, const __nv_bfloat16* __restrict__ Al,
              int lda,
              const __nv_bfloat16* __restrict__ Wh, const __nv_bfloat16* __restrict__ Wl,
              const float* __restrict__ bias, int K,
              float* __restrict__ Cf,
              __nv_bfloat16* __restrict__ Ch, __nv_bfloat16* __restrict__ Cl, int ldc) {
    extern __shared__ __align__(16) unsigned char smraw[];
    const uint32_t smb = (uint32_t)__cvta_generic_to_shared(smraw);
    const int t = threadIdx.x;
    const int w = t >> 5, lane = t & 31, g = lane >> 2, tq = lane & 3;
    const int bm = blockIdx.y * 64, bn = blockIdx.x * 64;
    const int lrow = t >> 1, lhalf = (t & 1) * 32;
    const uint32_t ldst = (uint32_t)((lrow * 72 + lhalf) * 2);

    const int lr  = lane & 7;
    const int sel = lane >> 3;
    const uint32_t aoff = (uint32_t)(((16 * w + (sel & 1) * 8 + lr) * 72 + (sel >> 1) * 8) * 2);
    const uint32_t boff = (uint32_t)((((sel >> 1) * 8 + lr) * 72 + (sel & 1) * 8) * 2);

    const int nck = K >> 6;

    auto issue = [&](int c, int stg) {
        const size_t ao = (size_t)(bm + lrow) * lda + c * 64 + lhalf;
        const size_t wo = (size_t)(bn + lrow) * K   + c * 64 + lhalf;
        const uint32_t b0 = smb + (uint32_t)(stg * 4) * 9216;
        #pragma unroll
        for (int j = 0; j < 4; j++) {
            cp16(b0 +            ldst + j * 16, Ah + ao + j * 8);
            cp16(b0 + 1 * 9216 + ldst + j * 16, Al + ao + j * 8);
            cp16(b0 + 2 * 9216 + ldst + j * 16, Wh + wo + j * 8);
            cp16(b0 + 3 * 9216 + ldst + j * 16, Wl + wo + j * 8);
        }
        cp_commit();
    };

    float c[8][4];
    #pragma unroll
    for (int i = 0; i < 8; i++)
        #pragma unroll
        for (int j = 0; j < 4; j++) c[i][j] = 0.f;

    issue(0, 0);
    for (int ck = 0; ck < nck; ck++) {
        cp_wait0();
        __syncthreads();
        if (ck + 1 < nck) issue(ck + 1, (ck + 1) & 1);
        const uint32_t b0 = smb + (uint32_t)((ck & 1) * 4) * 9216;
        #pragma unroll
        for (int kb = 0; kb < 4; kb++) {
            uint32_t ah[4], al[4];
            ldsm4(ah, b0 +        aoff + kb * 32);
            ldsm4(al, b0 + 9216 + aoff + kb * 32);
            #pragma unroll
            for (int p = 0; p < 4; p++) {
                uint32_t bh[4], bl[4];
                ldsm4(bh, b0 + 2 * 9216 + boff + p * 2304 + kb * 32);
                ldsm4(bl, b0 + 3 * 9216 + boff + p * 2304 + kb * 32);
                mma16816(c[2 * p],     ah[0], ah[1], ah[2], ah[3], bh[0], bh[1]);
                mma16816(c[2 * p],     ah[0], ah[1], ah[2], ah[3], bl[0], bl[1]);
                mma16816(c[2 * p],     al[0], al[1], al[2], al[3], bh[0], bh[1]);
                mma16816(c[2 * p + 1], ah[0], ah[1], ah[2], ah[3], bh[2], bh[3]);
                mma16816(c[2 * p + 1], ah[0], ah[1], ah[2], ah[3], bl[2], bl[3]);
                mma16816(c[2 * p + 1], al[0], al[1], al[2], al[3], bh[2], bh[3]);
            }
        }
        __syncthreads();
    }

    const int r0 = bm + 16 * w + g, r1 = r0 + 8;
    size_t gr0, gr1;
    if (MODE == 0) { gr0 = g_sortpos[r0]; gr1 = g_sortpos[r1]; }
    else           { gr0 = r0;            gr1 = r1; }
    #pragma unroll
    for (int nb = 0; nb < 8; nb++) {
        const int col = bn + 8 * nb + 2 * tq;
        float b0 = __ldg(bias + col), b1 = __ldg(bias + col + 1);
        float v0 = c[nb][0] + b0, v1 = c[nb][1] + b1;
        float v2 = c[nb][2] + b0, v3 = c[nb][3] + b1;
        if (MODE == 2) {
            *(float2*)&Cf[gr0 * ldc + col] = make_float2(v0, v1);
            *(float2*)&Cf[gr1 * ldc + col] = make_float2(v2, v3);
        } else {
            uint32_t h0, l0, h1, l1;
            split2(v0, v1, h0, l0);
            split2(v2, v3, h1, l1);
            *(uint32_t*)&Ch[gr0 * ldc + col] = h0;
            *(uint32_t*)&Cl[gr0 * ldc + col] = l0;
            *(uint32_t*)&Ch[gr1 * ldc + col] = h1;
            *(uint32_t*)&Cl[gr1 * ldc + col] = l1;
        }
    }
}

// ---------------- V transpose (hi only): sorted v -> [head][d][key] -------------
__global__ __launch_bounds__(128)
void vt_transpose_kernel() {
    __shared__ __align__(16) __nv_bfloat16 th[64 * 72];
    const int t = threadIdx.x;
    const int rb = blockIdx.x * 64, h = blockIdx.y;
    const int lrow = t >> 1, lhalf = (t & 1) * 32;
    const size_t src = (size_t)(rb + lrow) * QKVLD + 1024 + h * 64 + lhalf;
    #pragma unroll
    for (int j = 0; j < 4; j++)
        *(uint4*)&th[lrow * 72 + lhalf + j * 8] = *(const uint4*)(g_qkvh + src + j * 8);
    __syncthreads();
    const int d = t >> 1, kh = (t & 1) * 32;
    __nv_bfloat16* dh = g_vth + (size_t)(h * 64 + d) * NROWS + rb;
    #pragma unroll
    for (int j = 0; j < 16; j++) {
        int sr = kh + 2 * j;
        __nv_bfloat162 a;
        a.x = th[sr * 72 + d]; a.y = th[(sr + 1) * 72 + d];
        *(__nv_bfloat162*)(dh + sr) = a;
    }
}

// ---------------- flash attention: 128-row Q tiles, 8 warps, cp.async -----------
// smem bytes: Qh 0 (18432), Ql 18432; stage s at 36864+s*27648: Kh, +9216 Kl,
// +18432 Th; sks at 92160 + s*256. Total 92672.
__global__ __launch_bounds__(256, 2)
void attn_kernel() {
    extern __shared__ __align__(16) unsigned char smraw[];
    const uint32_t smb = (uint32_t)__cvta_generic_to_shared(smraw);
    __nv_bfloat16* Qh = (__nv_bfloat16*)smraw;
    __nv_bfloat16* Ql = Qh + 9216;
    int* sks0 = (int*)(smraw + 92160);

    const int qt = blockIdx.x, h = blockIdx.y, sp = blockIdx.z;
    const int qb = qt * 128;
    const int t = threadIdx.x, w = t >> 5, lane = t & 31, g = lane >> 2, tq = lane & 3;
    const int lrow = t >> 1, lhalf = (t & 1) * 32;

    const int lr  = lane & 7;
    const int sel = lane >> 3;
    const uint32_t aoff = (uint32_t)(((16 * w + (sel & 1) * 8 + lr) * 72 + (sel >> 1) * 8) * 2);
    const uint32_t boff = (uint32_t)((((sel >> 1) * 8 + lr) * 72 + (sel & 1) * 8) * 2);

    const int ks0 = g_kstart[2 * qt];
    const int len = (64 - ks0 + SPLITS - 1) / SPLITS;
    const int k0  = ks0 + sp * len;
    const int k1  = (k0 + len < 64) ? (k0 + len) : 64;

    const int krow = t >> 2, koff = (t & 3) * 16;
    const uint32_t kdst = (uint32_t)((krow * 72 + koff) * 2);

    auto issue = [&](int kt, int stg) {
        const int kb64 = kt * 64;
        const size_t ks = (size_t)(kb64 + krow) * QKVLD + 512 + h * 64 + koff;
        const size_t vs = (size_t)(h * 64 + krow) * NROWS + kb64 + koff;
        const uint32_t b0 = smb + 36864 + (uint32_t)stg * 27648;
        cp16(b0 +            kdst,      g_qkvh + ks);
        cp16(b0 +            kdst + 16, g_qkvh + ks + 8);
        cp16(b0 + 1 * 9216 + kdst,      g_qkvl + ks);
        cp16(b0 + 1 * 9216 + kdst + 16, g_qkvl + ks + 8);
        cp16(b0 + 2 * 9216 + kdst,      g_vth  + vs);
        cp16(b0 + 2 * 9216 + kdst + 16, g_vth  + vs + 8);
        if (t < 64) cp4(smb + 92160 + (uint32_t)stg * 256 + t * 4, g_ssteps + kb64 + t);
        cp_commit();
    };

    // stage first tile (async) + Q (regular loads; 256 thr cover 128 rows)
    if (k0 < k1) issue(k0, k0 & 1);
    {
        const size_t src = (size_t)(qb + lrow) * QKVLD + h * 64 + lhalf;
        #pragma unroll
        for (int j = 0; j < 4; j++) {
            *(uint4*)&Qh[lrow * 72 + lhalf + j * 8] = *(const uint4*)(g_qkvh + src + j * 8);
            *(uint4*)&Ql[lrow * 72 + lhalf + j * 8] = *(const uint4*)(g_qkvl + src + j * 8);
        }
    }
    const int sq_a = g_ssteps[qb + 16 * w + g];
    const int sq_b = g_ssteps[qb + 16 * w + g + 8];
    __syncthreads();

    uint32_t qfh[4][4], qfl[4][4];
    #pragma unroll
    for (int kb = 0; kb < 4; kb++) {
        ldsm4(qfh[kb], smb +         aoff + kb * 32);
        ldsm4(qfl[kb], smb + 18432 + aoff + kb * 32);
    }

    float o[8][4];
    #pragma unroll
    for (int i = 0; i < 8; i++)
        #pragma unroll
        for (int j = 0; j < 4; j++) o[i][j] = 0.f;
    float ps_a = 0.f, ps_b = 0.f;

    for (int kt = k0; kt < k1; kt++) {
        const int stg = kt & 1;
        cp_wait0();
        __syncthreads();
        if (kt + 1 < k1) issue(kt + 1, (kt + 1) & 1);

        const uint32_t b0 = smb + 36864 + (uint32_t)stg * 27648;
        const int* sksS = sks0 + stg * 64;

        // S = Q K^T (3-term split)
        float s[8][4];
        #pragma unroll
        for (int i = 0; i < 8; i++)
            #pragma unroll
            for (int j = 0; j < 4; j++) s[i][j] = 0.f;
        #pragma unroll
        for (int kb = 0; kb < 4; kb++) {
            #pragma unroll
            for (int p = 0; p < 4; p++) {
                uint32_t bh[4], bl[4];
                ldsm4(bh, b0 +        boff + p * 2304 + kb * 32);
                ldsm4(bl, b0 + 9216 + boff + p * 2304 + kb * 32);
                mma16816(s[2 * p],     qfh[kb][0], qfh[kb][1], qfh[kb][2], qfh[kb][3], bh[0], bh[1]);
                mma16816(s[2 * p],     qfh[kb][0], qfh[kb][1], qfh[kb][2], qfh[kb][3], bl[0], bl[1]);
                mma16816(s[2 * p],     qfl[kb][0], qfl[kb][1], qfl[kb][2], qfl[kb][3], bh[0], bh[1]);
                mma16816(s[2 * p + 1], qfh[kb][0], qfh[kb][1], qfh[kb][2], qfh[kb][3], bh[2], bh[3]);
                mma16816(s[2 * p + 1], qfh[kb][0], qfh[kb][1], qfh[kb][2], qfh[kb][3], bl[2], bl[3]);
                mma16816(s[2 * p + 1], qfl[kb][0], qfl[kb][1], qfl[kb][2], qfl[kb][3], bh[2], bh[3]);
            }
        }

        // softmax (fixed shift) + mask; P hi-only frags; exact p in row sums
        uint32_t pah[16];
        #pragma unroll
        for (int nb = 0; nb < 8; nb++) {
            int2 kk = *(const int2*)&sksS[8 * nb + 2 * tq];
            float p0 = __expf(s[nb][0] * 0.125f); if (kk.x < sq_a) p0 = 0.f;
            float p1 = __expf(s[nb][1] * 0.125f); if (kk.y < sq_a) p1 = 0.f;
            float p2 = __expf(s[nb][2] * 0.125f); if (kk.x < sq_b) p2 = 0.f;
            float p3 = __expf(s[nb][3] * 0.125f); if (kk.y < sq_b) p3 = 0.f;
            ps_a += p0 + p1;
            ps_b += p2 + p3;
            pah[2 * nb]     = pack_bf162(p0, p1);
            pah[2 * nb + 1] = pack_bf162(p2, p3);
        }

        // O += P_hi @ V_hi
        #pragma unroll
        for (int kb = 0; kb < 4; kb++) {
            uint32_t a0 = pah[4 * kb],     a1 = pah[4 * kb + 1];
            uint32_t a2 = pah[4 * kb + 2], a3 = pah[4 * kb + 3];
            #pragma unroll
            for (int p = 0; p < 4; p++) {
                uint32_t bh[4];
                ldsm4(bh, b0 + 2 * 9216 + boff + p * 2304 + kb * 32);
                mma16816(o[2 * p],     a0, a1, a2, a3, bh[0], bh[1]);
                mma16816(o[2 * p + 1], a0, a1, a2, a3, bh[2], bh[3]);
            }
        }
        __syncthreads();
    }

    ps_a += __shfl_xor_sync(0xffffffffu, ps_a, 1);
    ps_a += __shfl_xor_sync(0xffffffffu, ps_a, 2);
    ps_b += __shfl_xor_sync(0xffffffffu, ps_b, 1);
    ps_b += __shfl_xor_sync(0xffffffffu, ps_b, 2);
    const int rl0 = 16 * w + g, rl1 = rl0 + 8;
    if (tq == 0) {
        g_psum[(sp * 8 + h) * NROWS + qb + rl0] = ps_a;
        g_psum[(sp * 8 + h) * NROWS + qb + rl1] = ps_b;
    }
    #pragma unroll
    for (int nb = 0; nb < 8; nb++) {
        const int col = h * 64 + 8 * nb + 2 * tq;
        *(float2*)&g_part[((size_t)sp * NROWS + qb + rl0) * EDIM + col] = make_float2(o[nb][0], o[nb][1]);
        *(float2*)&g_part[((size_t)sp * NROWS + qb + rl1) * EDIM + col] = make_float2(o[nb][2], o[nb][3]);
    }
}

// ---------------- combine KV-splits -> ctx hi/lo (sorted space) -----------------
__global__ void combine_kernel() {
    const int r = blockIdx.x;
    const int t = threadIdx.x;
    __shared__ float inv[8];
    if (t < 8) {
        float tot = 0.f;
        #pragma unroll
        for (int s = 0; s < SPLITS; s++) tot += g_psum[(s * 8 + t) * NROWS + r];
        inv[t] = 1.f / tot;
    }
    __syncthreads();
    const int c = t * 4;
    float4 a = *(const float4*)&g_part[(size_t)r * EDIM + c];
    #pragma unroll
    for (int s = 1; s < SPLITS; s++) {
        float4 b = *(const float4*)&g_part[((size_t)s * NROWS + r) * EDIM + c];
        a.x += b.x; a.y += b.y; a.z += b.z; a.w += b.w;
    }
    float iv = inv[c >> 6];
    uint32_t h0, l0, h1, l1;
    split2(a.x * iv, a.y * iv, h0, l0);
    split2(a.z * iv, a.w * iv, h1, l1);
    *(uint32_t*)&g_ctxh[(size_t)r * EDIM + c]     = h0;
    *(uint32_t*)&g_ctxl[(size_t)r * EDIM + c]     = l0;
    *(uint32_t*)&g_ctxh[(size_t)r * EDIM + c + 2] = h1;
    *(uint32_t*)&g_ctxl[(size_t)r * EDIM + c + 2] = l1;
}

// ---------------- fill comb cols 512..895 (sorted rows, hi/lo) ------------------
__global__ void fill_comb_kernel(const int* __restrict__ dmask,
                                 const int* __restrict__ steps,
                                 const float* __restrict__ status) {
    const int r = blockIdx.x;
    __shared__ int so;
    if (threadIdx.x == 0) so = g_perm[r];
    __syncthreads();
    const int col = 2 * threadIdx.x;
    float v0, v1;
    if (col < 128) {
        int dm = dmask[so];
        v0 = status[dm * 128 + col];
        v1 = status[dm * 128 + col + 1];
    } else {
        int sc = steps[so];
        sc = sc < 0 ? 0 : (sc > 99 ? 99 : sc);
        v0 = g_te[sc * 256 + col - 128];
        v1 = g_te[sc * 256 + col - 127];
    }
    uint32_t hw, lw;
    split2(v0, v1, hw, lw);
    *(uint32_t*)&g_combh[(size_t)r * 896 + 512 + col] = hw;
    *(uint32_t*)&g_combl[(size_t)r * 896 + 512 + col] = lw;
}

// ---------------- LayerNorm -> ReLU -> residual (un-permute) --------------------
__global__ void ln_relu_res_kernel(const float* __restrict__ x,
                                   const float* __restrict__ gamma,
                                   const float* __restrict__ beta,
                                   float* __restrict__ out) {
    const int r = blockIdx.x;
    const int t = threadIdx.x;
    __shared__ float sh[8];
    __shared__ float stat[2];
    __shared__ int so;
    if (t == 0) so = g_perm[r];

    const float* hr = g_h + (size_t)r * EDIM;
    float v0 = hr[t], v1 = hr[t + 256];

    float s = v0 + v1;
    #pragma unroll
    for (int o2 = 16; o2; o2 >>= 1) s += __shfl_xor_sync(0xffffffffu, s, o2);
    if ((t & 31) == 0) sh[t >> 5] = s;
    __syncthreads();
    if (t == 0) {
        float tot = 0.f;
        #pragma unroll
        for (int i = 0; i < 8; i++) tot += sh[i];
        stat[0] = tot * (1.f / 512.f);
    }
    __syncthreads();
    float mu = stat[0];
    float d0 = v0 - mu, d1 = v1 - mu;
    float vv = d0 * d0 + d1 * d1;
    #pragma unroll
    for (int o2 = 16; o2; o2 >>= 1) vv += __shfl_xor_sync(0xffffffffu, vv, o2);
    if ((t & 31) == 0) sh[t >> 5] = vv;
    __syncthreads();
    if (t == 0) {
        float tot = 0.f;
        #pragma unroll
        for (int i = 0; i < 8; i++) tot += sh[i];
        stat[1] = 1.f / sqrtf(tot * (1.f / 512.f) + 1e-5f);
    }
    __syncthreads();
    float inv = stat[1];

    float y0 = fmaxf(d0 * inv * gamma[t]       + beta[t],       0.f);
    float y1 = fmaxf(d1 * inv * gamma[t + 256] + beta[t + 256], 0.f);
    const size_t orow = so;
    out[orow * EDIM + t]       = x[orow * EDIM + t]       + y0;
    out[orow * EDIM + t + 256] = x[orow * EDIM + t + 256] + y1;
}

// ---------------- launch ---------------------------------------------------------
extern "C" void kernel_launch(void* const* d_in, const int* in_sizes, int n_in,
                              void* d_out, int out_size) {
    const float* x      = (const float*)d_in[0];
    const int*   dmask  = (const int*)  d_in[1];
    const int*   steps  = (const int*)  d_in[2];
    const float* status = (const float*)d_in[3];
    const float* wqkv   = (const float*)d_in[4];
    const float* bqkv   = (const float*)d_in[5];
    const float* wout   = (const float*)d_in[6];
    const float* bout   = (const float*)d_in[7];
    const float* wmlp   = (const float*)d_in[8];
    const float* bmlp   = (const float*)d_in[9];
    const float* gamma  = (const float*)d_in[10];
    const float* beta   = (const float*)d_in[11];
    float* out = (float*)d_out;

    __nv_bfloat16 *xh, *xl, *wqh, *wql, *woh, *wol, *wmh, *wml;
    __nv_bfloat16 *qkvh, *qkvl, *ctxh, *ctxl, *combh, *combl;
    float* hbuf;
    cudaGetSymbolAddress((void**)&xh,    g_xh);
    cudaGetSymbolAddress((void**)&xl,    g_xl);
    cudaGetSymbolAddress((void**)&wqh,   g_wqkvh);
    cudaGetSymbolAddress((void**)&wql,   g_wqkvl);
    cudaGetSymbolAddress((void**)&woh,   g_wouth);
    cudaGetSymbolAddress((void**)&wol,   g_woutl);
    cudaGetSymbolAddress((void**)&wmh,   g_wmlph);
    cudaGetSymbolAddress((void**)&wml,   g_wmlpl);
    cudaGetSymbolAddress((void**)&qkvh,  g_qkvh);
    cudaGetSymbolAddress((void**)&qkvl,  g_qkvl);
    cudaGetSymbolAddress((void**)&ctxh,  g_ctxh);
    cudaGetSymbolAddress((void**)&ctxl,  g_ctxl);
    cudaGetSymbolAddress((void**)&combh, g_combh);
    cudaGetSymbolAddress((void**)&combl, g_combl);
    cudaGetSymbolAddress((void**)&hbuf,  g_h);

    const int attn_smem = 92672;
    const int gemm_smem = 73728;
    cudaFuncSetAttribute(attn_kernel, cudaFuncAttributeMaxDynamicSharedMemorySize, attn_smem);
    cudaFuncSetAttribute(mma_gemm<0>,  cudaFuncAttributeMaxDynamicSharedMemorySize, gemm_smem);
    cudaFuncSetAttribute(mma_gemm<1>,  cudaFuncAttributeMaxDynamicSharedMemorySize, gemm_smem);
    cudaFuncSetAttribute(mma_gemm<2>,  cudaFuncAttributeMaxDynamicSharedMemorySize, gemm_smem);

    sort_kernel<<<1, 128>>>(steps);
    build_te_kernel<<<50, 256>>>();

    cvt_split_kernel<<<(NROWS * EDIM / 2 + 255) / 256, 256>>>(x,    xh,  xl,  NROWS * EDIM);
    cvt_split_kernel<<<(QKVLD * EDIM / 2 + 255) / 256, 256>>>(wqkv, wqh, wql, QKVLD * EDIM);
    cvt_split_kernel<<<(EDIM * EDIM / 2 + 255) / 256, 256>>>(wout, woh, wol, EDIM * EDIM);
    cvt_split_kernel<<<(EDIM * 896 / 2 + 255) / 256, 256>>>(wmlp, wmh, wml, EDIM * 896);

    mma_gemm<0><<<dim3(24, 64), 128, gemm_smem>>>(xh, xl, EDIM, wqh, wql, bqkv, EDIM,
                                                  nullptr, qkvh, qkvl, QKVLD);

    vt_transpose_kernel<<<dim3(64, 8), 128>>>();

    attn_kernel<<<dim3(32, 8, SPLITS), 256, attn_smem>>>();

    combine_kernel<<<4096, 128>>>();

    mma_gemm<1><<<dim3(8, 64), 128, gemm_smem>>>(ctxh, ctxl, EDIM, woh, wol, bout, EDIM,
                                                 nullptr, combh, combl, 896);

    fill_comb_kernel<<<4096, 192>>>(dmask, steps, status);

    mma_gemm<2><<<dim3(8, 64), 128, gemm_smem>>>(combh, combl, 896, wmh, wml, bmlp, 896,
                                                 hbuf, nullptr, nullptr, EDIM);

    ln_relu_res_kernel<<<4096, 256>>>(x, gamma, beta, out);
}

// round 11
// speedup vs baseline: 3.5987x; 1.0915x over previous
#include <cuda_runtime.h>
#include <cuda_bf16.h>
#include <math.h>
#include <stdint.h>

#define NROWS  4096
#define EDIM   512
#define QKVLD  1536
#define SPLITS 4

// ---------------- device scratch (no allocations allowed) -------------------
__device__ float g_te[100 * 256];
__device__ int   g_perm[NROWS], g_sortpos[NROWS], g_ssteps[NROWS], g_kstart[64];

__device__ __align__(16) __nv_bfloat16 g_xh   [NROWS * EDIM],  g_xl   [NROWS * EDIM];
__device__ __align__(16) __nv_bfloat16 g_wqkvh[QKVLD * EDIM],  g_wqkvl[QKVLD * EDIM];
__device__ __align__(16) __nv_bfloat16 g_wouth[EDIM * EDIM],   g_woutl[EDIM * EDIM];
__device__ __align__(16) __nv_bfloat16 g_wmlph[EDIM * 896],    g_wmlpl[EDIM * 896];
__device__ __align__(16) __nv_bfloat16 g_qkvh [NROWS * QKVLD], g_qkvl [NROWS * QKVLD];
__device__ __align__(16) __nv_bfloat16 g_vth  [EDIM * NROWS];
__device__ __align__(16) __nv_bfloat16 g_ctxh [NROWS * EDIM],  g_ctxl [NROWS * EDIM];
__device__ __align__(16) __nv_bfloat16 g_combh[NROWS * 896],   g_combl[NROWS * 896];
__device__ float g_h[NROWS * EDIM];
__device__ float g_part[(size_t)SPLITS * NROWS * EDIM];
__device__ float g_psum[SPLITS * 8 * NROWS];

// ---------------- helpers ----------------------------------------------------
__device__ __forceinline__ void mma16816(float* c,
    uint32_t a0, uint32_t a1, uint32_t a2, uint32_t a3,
    uint32_t b0, uint32_t b1) {
    asm volatile(
        "mma.sync.aligned.m16n8k16.row.col.f32.bf16.bf16.f32 "
        "{%0,%1,%2,%3},{%4,%5,%6,%7},{%8,%9},{%0,%1,%2,%3};"
        : "+f"(c[0]), "+f"(c[1]), "+f"(c[2]), "+f"(c[3])
        : "r"(a0), "r"(a1), "r"(a2), "r"(a3), "r"(b0), "r"(b1));
}

__device__ __forceinline__ void ldsm4(uint32_t* r, uint32_t addr) {
    asm volatile("ldmatrix.sync.aligned.m8n8.x4.shared.b16 {%0,%1,%2,%3}, [%4];"
        : "=r"(r[0]), "=r"(r[1]), "=r"(r[2]), "=r"(r[3]) : "r"(addr));
}

__device__ __forceinline__ void cp16(uint32_t dst, const void* src) {
    asm volatile("cp.async.cg.shared.global [%0], [%1], 16;" :: "r"(dst), "l"(src));
}
__device__ __forceinline__ void cp4(uint32_t dst, const void* src) {
    asm volatile("cp.async.ca.shared.global [%0], [%1], 4;" :: "r"(dst), "l"(src));
}
__device__ __forceinline__ void cp_commit() { asm volatile("cp.async.commit_group;"); }
__device__ __forceinline__ void cp_wait0()  { asm volatile("cp.async.wait_group 0;"); }

__device__ __forceinline__ void split2(float v0, float v1, uint32_t& hi, uint32_t& lo) {
    __nv_bfloat162 h = __floats2bfloat162_rn(v0, v1);
    float r0 = v0 - __bfloat162float(h.x);
    float r1 = v1 - __bfloat162float(h.y);
    __nv_bfloat162 l = __floats2bfloat162_rn(r0, r1);
    hi = *reinterpret_cast<uint32_t*>(&h);
    lo = *reinterpret_cast<uint32_t*>(&l);
}

__device__ __forceinline__ uint32_t pack_bf162(float v0, float v1) {
    __nv_bfloat162 h = __floats2bfloat162_rn(v0, v1);
    return *reinterpret_cast<uint32_t*>(&h);
}

// ---------------- time table ---------------------------------------------------
__global__ void build_te_kernel() {
    int t = blockIdx.x * blockDim.x + threadIdx.x;
    if (t >= 100 * 128) return;
    int p = t >> 7;
    int k = t & 127;
    double div = exp(-((double)(2 * k)) * log(10000.0) / 256.0);
    double ang = (double)p * div;
    g_te[p * 256 + 2 * k]     = (float)sin(ang);
    g_te[p * 256 + 2 * k + 1] = (float)cos(ang);
}

// ---------------- deterministic stable sort (parallel chunked) ------------------
__global__ void sort_kernel(const int* __restrict__ steps) {
    __shared__ int s_steps[NROWS];
    __shared__ unsigned short hist[128][100];
    __shared__ int base[100];
    const int t = threadIdx.x;   // 128 threads, 32 rows each

    for (int i = t; i < NROWS; i += 128) {
        int s = steps[i];
        s_steps[i] = s < 0 ? 0 : (s > 99 ? 99 : s);
    }
    __syncthreads();

    for (int b = 0; b < 100; b++) hist[t][b] = 0;
    const int r0 = t * 32;
    for (int r = 0; r < 32; r++) hist[t][s_steps[r0 + r]]++;
    __syncthreads();

    if (t < 100) {
        int acc = 0;
        for (int c = 0; c < 128; c++) {
            int v = hist[c][t];
            hist[c][t] = (unsigned short)acc;
            acc += v;
        }
        base[t] = acc;
    }
    __syncthreads();
    if (t == 0) {
        int acc = 0;
        for (int b = 0; b < 100; b++) { int v = base[b]; base[b] = acc; acc += v; }
    }
    __syncthreads();

    for (int r = 0; r < 32; r++) {
        int i = r0 + r;
        int s = s_steps[i];
        int pos = base[s] + hist[t][s];
        hist[t][s]++;
        g_perm[pos] = i;
        g_sortpos[i] = pos;
        g_ssteps[pos] = s;
    }
    __syncthreads();

    if (t < 64) {
        int qmin = g_ssteps[t * 64];
        int ks = 0;
        while (ks < 64 && g_ssteps[ks * 64 + 63] < qmin) ks++;
        g_kstart[t] = ks;
    }
}

// ---------------- all fp32 -> bf16 hi/lo splits in ONE kernel -------------------
#define CV0 (NROWS * EDIM)            // x        2097152
#define CV1 (CV0 + QKVLD * EDIM)      // +wqkv    2883584
#define CV2 (CV1 + EDIM * EDIM)       // +wout    3145728
#define CV3 (CV2 + EDIM * 896)        // +wmlp    3604480
__global__ void cvt_all_kernel(const float* __restrict__ x,
                               const float* __restrict__ wq,
                               const float* __restrict__ wo,
                               const float* __restrict__ wm) {
    int i = (blockIdx.x * blockDim.x + threadIdx.x) * 2;
    if (i >= CV3) return;
    const float* src;
    __nv_bfloat16 *dh, *dl;
    int off;
    if (i < CV0)      { src = x;  dh = g_xh;    dl = g_xl;    off = i; }
    else if (i < CV1) { src = wq; dh = g_wqkvh; dl = g_wqkvl; off = i - CV0; }
    else if (i < CV2) { src = wo; dh = g_wouth; dl = g_woutl; off = i - CV1; }
    else              { src = wm; dh = g_wmlph; dl = g_wmlpl; off = i - CV2; }
    float2 v = *(const float2*)(src + off);
    uint32_t hw, lw;
    split2(v.x, v.y, hw, lw);
    *(uint32_t*)(dh + off) = hw;
    *(uint32_t*)(dl + off) = lw;
}

// ---------------- split-bf16 tensor GEMM, 128x64 tile, 256 thr, cp.async --------
// smem per stage (bytes): Ah 18432, Al 18432, Wh 9216, Wl 9216 = 55296; x2 stages.
template<int MODE>
__global__ __launch_bounds__(256)
void mma_gemm(const __nv_bfloat16* __restrict__ Ah, const __nv_bfloat16* __restrict__ Al,
              int lda,
              const __nv_bfloat16* __restrict__ Wh, const __nv_bfloat16* __restrict__ Wl,
              const float* __restrict__ bias, int K,
              float* __restrict__ Cf,
              __nv_bfloat16* __restrict__ Ch, __nv_bfloat16* __restrict__ Cl, int ldc) {
    extern __shared__ __align__(16) unsigned char smraw[];
    const uint32_t smb = (uint32_t)__cvta_generic_to_shared(smraw);
    const int t = threadIdx.x;
    const int w = t >> 5, lane = t & 31, g = lane >> 2, tq = lane & 3;
    const int bm = blockIdx.y * 128, bn = blockIdx.x * 64;
    const int lrow = t >> 1, lhalf = (t & 1) * 32;                 // A fill: 128 rows
    const uint32_t ldstA = (uint32_t)((lrow * 72 + lhalf) * 2);
    const int wrow = t >> 2, wq4 = (t & 3) * 16;                   // W fill: 64 rows
    const uint32_t ldstW = (uint32_t)((wrow * 72 + wq4) * 2);

    const int lr  = lane & 7;
    const int sel = lane >> 3;
    const uint32_t aoff = (uint32_t)(((16 * w + (sel & 1) * 8 + lr) * 72 + (sel >> 1) * 8) * 2);
    const uint32_t boff = (uint32_t)((((sel >> 1) * 8 + lr) * 72 + (sel & 1) * 8) * 2);

    const int nck = K >> 6;

    auto issue = [&](int c, int stg) {
        const size_t ao = (size_t)(bm + lrow) * lda + c * 64 + lhalf;
        const size_t wo = (size_t)(bn + wrow) * K   + c * 64 + wq4;
        const uint32_t b0 = smb + (uint32_t)stg * 55296;
        #pragma unroll
        for (int j = 0; j < 4; j++) {
            cp16(b0 +         ldstA + j * 16, Ah + ao + j * 8);
            cp16(b0 + 18432 + ldstA + j * 16, Al + ao + j * 8);
        }
        #pragma unroll
        for (int j = 0; j < 2; j++) {
            cp16(b0 + 36864 + ldstW + j * 16, Wh + wo + j * 8);
            cp16(b0 + 46080 + ldstW + j * 16, Wl + wo + j * 8);
        }
        cp_commit();
    };

    float c[8][4];
    #pragma unroll
    for (int i = 0; i < 8; i++)
        #pragma unroll
        for (int j = 0; j < 4; j++) c[i][j] = 0.f;

    issue(0, 0);
    for (int ck = 0; ck < nck; ck++) {
        cp_wait0();
        __syncthreads();
        if (ck + 1 < nck) issue(ck + 1, (ck + 1) & 1);
        const uint32_t b0 = smb + (uint32_t)(ck & 1) * 55296;
        #pragma unroll
        for (int kb = 0; kb < 4; kb++) {
            uint32_t ah[4], al[4];
            ldsm4(ah, b0 +         aoff + kb * 32);
            ldsm4(al, b0 + 18432 + aoff + kb * 32);
            #pragma unroll
            for (int p = 0; p < 4; p++) {
                uint32_t bh[4], bl[4];
                ldsm4(bh, b0 + 36864 + boff + p * 2304 + kb * 32);
                ldsm4(bl, b0 + 46080 + boff + p * 2304 + kb * 32);
                mma16816(c[2 * p],     ah[0], ah[1], ah[2], ah[3], bh[0], bh[1]);
                mma16816(c[2 * p],     ah[0], ah[1], ah[2], ah[3], bl[0], bl[1]);
                mma16816(c[2 * p],     al[0], al[1], al[2], al[3], bh[0], bh[1]);
                mma16816(c[2 * p + 1], ah[0], ah[1], ah[2], ah[3], bh[2], bh[3]);
                mma16816(c[2 * p + 1], ah[0], ah[1], ah[2], ah[3], bl[2], bl[3]);
                mma16816(c[2 * p + 1], al[0], al[1], al[2], al[3], bh[2], bh[3]);
            }
        }
        __syncthreads();
    }

    const int r0 = bm + 16 * w + g, r1 = r0 + 8;
    size_t gr0, gr1;
    if (MODE == 0) { gr0 = g_sortpos[r0]; gr1 = g_sortpos[r1]; }
    else           { gr0 = r0;            gr1 = r1; }
    #pragma unroll
    for (int nb = 0; nb < 8; nb++) {
        const int col = bn + 8 * nb + 2 * tq;
        float b0 = __ldg(bias + col), b1 = __ldg(bias + col + 1);
        float v0 = c[nb][0] + b0, v1 = c[nb][1] + b1;
        float v2 = c[nb][2] + b0, v3 = c[nb][3] + b1;
        if (MODE == 2) {
            *(float2*)&Cf[gr0 * ldc + col] = make_float2(v0, v1);
            *(float2*)&Cf[gr1 * ldc + col] = make_float2(v2, v3);
        } else {
            uint32_t h0, l0, h1, l1;
            split2(v0, v1, h0, l0);
            split2(v2, v3, h1, l1);
            *(uint32_t*)&Ch[gr0 * ldc + col] = h0;
            *(uint32_t*)&Cl[gr0 * ldc + col] = l0;
            *(uint32_t*)&Ch[gr1 * ldc + col] = h1;
            *(uint32_t*)&Cl[gr1 * ldc + col] = l1;
        }
    }
}

// ---------------- V transpose (hi only): sorted v -> [head][d][key] -------------
__global__ __launch_bounds__(128)
void vt_transpose_kernel() {
    __shared__ __align__(16) __nv_bfloat16 th[64 * 72];
    const int t = threadIdx.x;
    const int rb = blockIdx.x * 64, h = blockIdx.y;
    const int lrow = t >> 1, lhalf = (t & 1) * 32;
    const size_t src = (size_t)(rb + lrow) * QKVLD + 1024 + h * 64 + lhalf;
    #pragma unroll
    for (int j = 0; j < 4; j++)
        *(uint4*)&th[lrow * 72 + lhalf + j * 8] = *(const uint4*)(g_qkvh + src + j * 8);
    __syncthreads();
    const int d = t >> 1, kh = (t & 1) * 32;
    __nv_bfloat16* dh = g_vth + (size_t)(h * 64 + d) * NROWS + rb;
    #pragma unroll
    for (int j = 0; j < 16; j++) {
        int sr = kh + 2 * j;
        __nv_bfloat162 a;
        a.x = th[sr * 72 + d]; a.y = th[(sr + 1) * 72 + d];
        *(__nv_bfloat162*)(dh + sr) = a;
    }
}

// ---------------- flash attention: 128-row Q tiles, 8 warps, cp.async -----------
// smem bytes: Qh 0 (18432), Ql 18432; stage s at 36864+s*27648: Kh, +9216 Kl,
// +18432 Th; sks at 92160 + s*256. Total 92672.
__global__ __launch_bounds__(256, 2)
void attn_kernel() {
    extern __shared__ __align__(16) unsigned char smraw[];
    const uint32_t smb = (uint32_t)__cvta_generic_to_shared(smraw);
    __nv_bfloat16* Qh = (__nv_bfloat16*)smraw;
    __nv_bfloat16* Ql = Qh + 9216;
    int* sks0 = (int*)(smraw + 92160);

    const int qt = blockIdx.x, h = blockIdx.y, sp = blockIdx.z;
    const int qb = qt * 128;
    const int t = threadIdx.x, w = t >> 5, lane = t & 31, g = lane >> 2, tq = lane & 3;
    const int lrow = t >> 1, lhalf = (t & 1) * 32;

    const int lr  = lane & 7;
    const int sel = lane >> 3;
    const uint32_t aoff = (uint32_t)(((16 * w + (sel & 1) * 8 + lr) * 72 + (sel >> 1) * 8) * 2);
    const uint32_t boff = (uint32_t)((((sel >> 1) * 8 + lr) * 72 + (sel & 1) * 8) * 2);

    const int ks0 = g_kstart[2 * qt];
    const int len = (64 - ks0 + SPLITS - 1) / SPLITS;
    const int k0  = ks0 + sp * len;
    const int k1  = (k0 + len < 64) ? (k0 + len) : 64;

    const int krow = t >> 2, koff = (t & 3) * 16;
    const uint32_t kdst = (uint32_t)((krow * 72 + koff) * 2);

    auto issue = [&](int kt, int stg) {
        const int kb64 = kt * 64;
        const size_t ks = (size_t)(kb64 + krow) * QKVLD + 512 + h * 64 + koff;
        const size_t vs = (size_t)(h * 64 + krow) * NROWS + kb64 + koff;
        const uint32_t b0 = smb + 36864 + (uint32_t)stg * 27648;
        cp16(b0 +            kdst,      g_qkvh + ks);
        cp16(b0 +            kdst + 16, g_qkvh + ks + 8);
        cp16(b0 + 1 * 9216 + kdst,      g_qkvl + ks);
        cp16(b0 + 1 * 9216 + kdst + 16, g_qkvl + ks + 8);
        cp16(b0 + 2 * 9216 + kdst,      g_vth  + vs);
        cp16(b0 + 2 * 9216 + kdst + 16, g_vth  + vs + 8);
        if (t < 64) cp4(smb + 92160 + (uint32_t)stg * 256 + t * 4, g_ssteps + kb64 + t);
        cp_commit();
    };

    if (k0 < k1) issue(k0, k0 & 1);
    {
        const size_t src = (size_t)(qb + lrow) * QKVLD + h * 64 + lhalf;
        #pragma unroll
        for (int j = 0; j < 4; j++) {
            *(uint4*)&Qh[lrow * 72 + lhalf + j * 8] = *(const uint4*)(g_qkvh + src + j * 8);
            *(uint4*)&Ql[lrow * 72 + lhalf + j * 8] = *(const uint4*)(g_qkvl + src + j * 8);
        }
    }
    const int sq_a = g_ssteps[qb + 16 * w + g];
    const int sq_b = g_ssteps[qb + 16 * w + g + 8];
    __syncthreads();

    uint32_t qfh[4][4], qfl[4][4];
    #pragma unroll
    for (int kb = 0; kb < 4; kb++) {
        ldsm4(qfh[kb], smb +         aoff + kb * 32);
        ldsm4(qfl[kb], smb + 18432 + aoff + kb * 32);
    }

    float o[8][4];
    #pragma unroll
    for (int i = 0; i < 8; i++)
        #pragma unroll
        for (int j = 0; j < 4; j++) o[i][j] = 0.f;
    float ps_a = 0.f, ps_b = 0.f;

    for (int kt = k0; kt < k1; kt++) {
        const int stg = kt & 1;
        cp_wait0();
        __syncthreads();
        if (kt + 1 < k1) issue(kt + 1, (kt + 1) & 1);

        const uint32_t b0 = smb + 36864 + (uint32_t)stg * 27648;
        const int* sksS = sks0 + stg * 64;

        // S = Q K^T (3-term split)
        float s[8][4];
        #pragma unroll
        for (int i = 0; i < 8; i++)
            #pragma unroll
            for (int j = 0; j < 4; j++) s[i][j] = 0.f;
        #pragma unroll
        for (int kb = 0; kb < 4; kb++) {
            #pragma unroll
            for (int p = 0; p < 4; p++) {
                uint32_t bh[4], bl[4];
                ldsm4(bh, b0 +        boff + p * 2304 + kb * 32);
                ldsm4(bl, b0 + 9216 + boff + p * 2304 + kb * 32);
                mma16816(s[2 * p],     qfh[kb][0], qfh[kb][1], qfh[kb][2], qfh[kb][3], bh[0], bh[1]);
                mma16816(s[2 * p],     qfh[kb][0], qfh[kb][1], qfh[kb][2], qfh[kb][3], bl[0], bl[1]);
                mma16816(s[2 * p],     qfl[kb][0], qfl[kb][1], qfl[kb][2], qfl[kb][3], bh[0], bh[1]);
                mma16816(s[2 * p + 1], qfh[kb][0], qfh[kb][1], qfh[kb][2], qfh[kb][3], bh[2], bh[3]);
                mma16816(s[2 * p + 1], qfh[kb][0], qfh[kb][1], qfh[kb][2], qfh[kb][3], bl[2], bl[3]);
                mma16816(s[2 * p + 1], qfl[kb][0], qfl[kb][1], qfl[kb][2], qfl[kb][3], bh[2], bh[3]);
            }
        }

        // softmax (fixed shift) + mask; P hi-only frags; exact p in row sums
        uint32_t pah[16];
        #pragma unroll
        for (int nb = 0; nb < 8; nb++) {
            int2 kk = *(const int2*)&sksS[8 * nb + 2 * tq];
            float p0 = __expf(s[nb][0] * 0.125f); if (kk.x < sq_a) p0 = 0.f;
            float p1 = __expf(s[nb][1] * 0.125f); if (kk.y < sq_a) p1 = 0.f;
            float p2 = __expf(s[nb][2] * 0.125f); if (kk.x < sq_b) p2 = 0.f;
            float p3 = __expf(s[nb][3] * 0.125f); if (kk.y < sq_b) p3 = 0.f;
            ps_a += p0 + p1;
            ps_b += p2 + p3;
            pah[2 * nb]     = pack_bf162(p0, p1);
            pah[2 * nb + 1] = pack_bf162(p2, p3);
        }

        // O += P_hi @ V_hi
        #pragma unroll
        for (int kb = 0; kb < 4; kb++) {
            uint32_t a0 = pah[4 * kb],     a1 = pah[4 * kb + 1];
            uint32_t a2 = pah[4 * kb + 2], a3 = pah[4 * kb + 3];
            #pragma unroll
            for (int p = 0; p < 4; p++) {
                uint32_t bh[4];
                ldsm4(bh, b0 + 2 * 9216 + boff + p * 2304 + kb * 32);
                mma16816(o[2 * p],     a0, a1, a2, a3, bh[0], bh[1]);
                mma16816(o[2 * p + 1], a0, a1, a2, a3, bh[2], bh[3]);
            }
        }
        __syncthreads();
    }

    ps_a += __shfl_xor_sync(0xffffffffu, ps_a, 1);
    ps_a += __shfl_xor_sync(0xffffffffu, ps_a, 2);
    ps_b += __shfl_xor_sync(0xffffffffu, ps_b, 1);
    ps_b += __shfl_xor_sync(0xffffffffu, ps_b, 2);
    const int rl0 = 16 * w + g, rl1 = rl0 + 8;
    if (tq == 0) {
        g_psum[(sp * 8 + h) * NROWS + qb + rl0] = ps_a;
        g_psum[(sp * 8 + h) * NROWS + qb + rl1] = ps_b;
    }
    #pragma unroll
    for (int nb = 0; nb < 8; nb++) {
        const int col = h * 64 + 8 * nb + 2 * tq;
        *(float2*)&g_part[((size_t)sp * NROWS + qb + rl0) * EDIM + col] = make_float2(o[nb][0], o[nb][1]);
        *(float2*)&g_part[((size_t)sp * NROWS + qb + rl1) * EDIM + col] = make_float2(o[nb][2], o[nb][3]);
    }
}

// ---------------- fused: combine KV-splits -> ctx  AND  fill comb 512..895 ------
// 320 threads: t<128 combine (4 cols each), t>=128 fill (2 cols each, 192 thr)
__global__ void combfill_kernel(const int* __restrict__ dmask,
                                const int* __restrict__ steps,
                                const float* __restrict__ status) {
    const int r = blockIdx.x;
    const int t = threadIdx.x;
    __shared__ float inv[8];
    __shared__ int so;
    if (t == 0) so = g_perm[r];
    if (t >= 312) {                      // 8 threads compute inverse row sums
        int hh = t - 312;
        float tot = 0.f;
        #pragma unroll
        for (int s = 0; s < SPLITS; s++) tot += g_psum[(s * 8 + hh) * NROWS + r];
        inv[hh] = 1.f / tot;
    }
    __syncthreads();

    if (t < 128) {
        const int c = t * 4;
        float4 a = *(const float4*)&g_part[(size_t)r * EDIM + c];
        #pragma unroll
        for (int s = 1; s < SPLITS; s++) {
            float4 b = *(const float4*)&g_part[((size_t)s * NROWS + r) * EDIM + c];
            a.x += b.x; a.y += b.y; a.z += b.z; a.w += b.w;
        }
        float iv = inv[c >> 6];
        uint32_t h0, l0, h1, l1;
        split2(a.x * iv, a.y * iv, h0, l0);
        split2(a.z * iv, a.w * iv, h1, l1);
        *(uint32_t*)&g_ctxh[(size_t)r * EDIM + c]     = h0;
        *(uint32_t*)&g_ctxl[(size_t)r * EDIM + c]     = l0;
        *(uint32_t*)&g_ctxh[(size_t)r * EDIM + c + 2] = h1;
        *(uint32_t*)&g_ctxl[(size_t)r * EDIM + c + 2] = l1;
    } else {
        const int col = 2 * (t - 128);   // 0..382
        float v0, v1;
        if (col < 128) {
            int dm = dmask[so];
            v0 = status[dm * 128 + col];
            v1 = status[dm * 128 + col + 1];
        } else {
            int sc = steps[so];
            sc = sc < 0 ? 0 : (sc > 99 ? 99 : sc);
            v0 = g_te[sc * 256 + col - 128];
            v1 = g_te[sc * 256 + col - 127];
        }
        uint32_t hw, lw;
        split2(v0, v1, hw, lw);
        *(uint32_t*)&g_combh[(size_t)r * 896 + 512 + col] = hw;
        *(uint32_t*)&g_combl[(size_t)r * 896 + 512 + col] = lw;
    }
}

// ---------------- LayerNorm -> ReLU -> residual (un-permute) --------------------
__global__ void ln_relu_res_kernel(const float* __restrict__ x,
                                   const float* __restrict__ gamma,
                                   const float* __restrict__ beta,
                                   float* __restrict__ out) {
    const int r = blockIdx.x;
    const int t = threadIdx.x;
    __shared__ float sh[8];
    __shared__ float stat[2];
    __shared__ int so;
    if (t == 0) so = g_perm[r];

    const float* hr = g_h + (size_t)r * EDIM;
    float v0 = hr[t], v1 = hr[t + 256];

    float s = v0 + v1;
    #pragma unroll
    for (int o2 = 16; o2; o2 >>= 1) s += __shfl_xor_sync(0xffffffffu, s, o2);
    if ((t & 31) == 0) sh[t >> 5] = s;
    __syncthreads();
    if (t == 0) {
        float tot = 0.f;
        #pragma unroll
        for (int i = 0; i < 8; i++) tot += sh[i];
        stat[0] = tot * (1.f / 512.f);
    }
    __syncthreads();
    float mu = stat[0];
    float d0 = v0 - mu, d1 = v1 - mu;
    float vv = d0 * d0 + d1 * d1;
    #pragma unroll
    for (int o2 = 16; o2; o2 >>= 1) vv += __shfl_xor_sync(0xffffffffu, vv, o2);
    if ((t & 31) == 0) sh[t >> 5] = vv;
    __syncthreads();
    if (t == 0) {
        float tot = 0.f;
        #pragma unroll
        for (int i = 0; i < 8; i++) tot += sh[i];
        stat[1] = 1.f / sqrtf(tot * (1.f / 512.f) + 1e-5f);
    }
    __syncthreads();
    float inv = stat[1];

    float y0 = fmaxf(d0 * inv * gamma[t]       + beta[t],       0.f);
    float y1 = fmaxf(d1 * inv * gamma[t + 256] + beta[t + 256], 0.f);
    const size_t orow = so;
    out[orow * EDIM + t]       = x[orow * EDIM + t]       + y0;
    out[orow * EDIM + t + 256] = x[orow * EDIM + t + 256] + y1;
}

// ---------------- launch ---------------------------------------------------------
extern "C" void kernel_launch(void* const* d_in, const int* in_sizes, int n_in,
                              void* d_out, int out_size) {
    const float* x      = (const float*)d_in[0];
    const int*   dmask  = (const int*)  d_in[1];
    const int*   steps  = (const int*)  d_in[2];
    const float* status = (const float*)d_in[3];
    const float* wqkv   = (const float*)d_in[4];
    const float* bqkv   = (const float*)d_in[5];
    const float* wout   = (const float*)d_in[6];
    const float* bout   = (const float*)d_in[7];
    const float* wmlp   = (const float*)d_in[8];
    const float* bmlp   = (const float*)d_in[9];
    const float* gamma  = (const float*)d_in[10];
    const float* beta   = (const float*)d_in[11];
    float* out = (float*)d_out;

    __nv_bfloat16 *xh, *xl, *wqh, *wql, *woh, *wol, *wmh, *wml;
    __nv_bfloat16 *qkvh, *qkvl, *ctxh, *ctxl, *combh, *combl;
    float* hbuf;
    cudaGetSymbolAddress((void**)&xh,    g_xh);
    cudaGetSymbolAddress((void**)&xl,    g_xl);
    cudaGetSymbolAddress((void**)&wqh,   g_wqkvh);
    cudaGetSymbolAddress((void**)&wql,   g_wqkvl);
    cudaGetSymbolAddress((void**)&woh,   g_wouth);
    cudaGetSymbolAddress((void**)&wol,   g_woutl);
    cudaGetSymbolAddress((void**)&wmh,   g_wmlph);
    cudaGetSymbolAddress((void**)&wml,   g_wmlpl);
    cudaGetSymbolAddress((void**)&qkvh,  g_qkvh);
    cudaGetSymbolAddress((void**)&qkvl,  g_qkvl);
    cudaGetSymbolAddress((void**)&ctxh,  g_ctxh);
    cudaGetSymbolAddress((void**)&ctxl,  g_ctxl);
    cudaGetSymbolAddress((void**)&combh, g_combh);
    cudaGetSymbolAddress((void**)&combl, g_combl);
    cudaGetSymbolAddress((void**)&hbuf,  g_h);

    const int attn_smem = 92672;
    const int gemm_smem = 110592;
    cudaFuncSetAttribute(attn_kernel, cudaFuncAttributeMaxDynamicSharedMemorySize, attn_smem);
    cudaFuncSetAttribute(mma_gemm<0>,  cudaFuncAttributeMaxDynamicSharedMemorySize, gemm_smem);
    cudaFuncSetAttribute(mma_gemm<1>,  cudaFuncAttributeMaxDynamicSharedMemorySize, gemm_smem);
    cudaFuncSetAttribute(mma_gemm<2>,  cudaFuncAttributeMaxDynamicSharedMemorySize, gemm_smem);

    sort_kernel<<<1, 128>>>(steps);
    build_te_kernel<<<50, 256>>>();

    cvt_all_kernel<<<(CV3 / 2 + 255) / 256, 256>>>(x, wqkv, wout, wmlp);

    // qkv = x @ Wqkv^T + b (rows scattered into sorted order)
    mma_gemm<0><<<dim3(24, 32), 256, gemm_smem>>>(xh, xl, EDIM, wqh, wql, bqkv, EDIM,
                                                  nullptr, qkvh, qkvl, QKVLD);

    vt_transpose_kernel<<<dim3(64, 8), 128>>>();

    attn_kernel<<<dim3(32, 8, SPLITS), 256, attn_smem>>>();

    combfill_kernel<<<4096, 320>>>(dmask, steps, status);

    mma_gemm<1><<<dim3(8, 32), 256, gemm_smem>>>(ctxh, ctxl, EDIM, woh, wol, bout, EDIM,
                                                 nullptr, combh, combl, 896);

    mma_gemm<2><<<dim3(8, 32), 256, gemm_smem>>>(combh, combl, 896, wmh, wml, bmlp, 896,
                                                 hbuf, nullptr, nullptr, EDIM);

    ln_relu_res_kernel<<<4096, 256>>>(x, gamma, beta, out);
}